// round 1
// baseline (speedup 1.0000x reference)
#include <cuda_runtime.h>
#include <math.h>

#define NB 4
#define NS 2048
#define ND 2048
#define NH 16
#define NHD 128
#define ROWS (NB*NS)        /* 8192 */
#define QKV_COLS (3*ND)     /* 6144 */

// Scratch (allocation-free rule: device globals)
__device__ float g_qkv[(size_t)ROWS * QKV_COLS];   // 201 MB
__device__ float g_attn[(size_t)ROWS * ND];        // 67 MB

// ---------------------------------------------------------------------------
// C[M,N] = A[M,K] @ W[K,N] + bias[N]   (all row-major, all dims % 128 == 0,
// K % 16 == 0). 128x128 tile, BK=16, 256 threads, 8x8 per thread.
// ---------------------------------------------------------------------------
__global__ __launch_bounds__(256, 2)
void sgemm_bias(const float* __restrict__ A, const float* __restrict__ W,
                const float* __restrict__ bias, float* __restrict__ C,
                int M, int N, int K)
{
    __shared__ float As[16][132];   // A tile transposed: As[k][m]
    __shared__ float Bs[16][132];   // W tile: Bs[k][n]
    const int t  = threadIdx.x;
    const int tx = t & 15, ty = t >> 4;
    const int rowBase = blockIdx.y * 128;
    const int colBase = blockIdx.x * 128;

    float acc[8][8];
    #pragma unroll
    for (int i = 0; i < 8; i++)
        #pragma unroll
        for (int j = 0; j < 8; j++) acc[i][j] = 0.f;

    for (int k0 = 0; k0 < K; k0 += 16) {
        #pragma unroll
        for (int u = 0; u < 2; u++) {
            int idx = t + 256*u;            // 0..511
            int r = idx >> 2, c4 = idx & 3; // 128 rows x 4 float4
            float4 v = *(const float4*)&A[(size_t)(rowBase + r)*K + k0 + c4*4];
            As[c4*4+0][r] = v.x; As[c4*4+1][r] = v.y;
            As[c4*4+2][r] = v.z; As[c4*4+3][r] = v.w;
        }
        #pragma unroll
        for (int u = 0; u < 2; u++) {
            int idx = t + 256*u;
            int r = idx >> 5, c4 = idx & 31; // 16 rows x 32 float4
            *(float4*)&Bs[r][c4*4] =
                *(const float4*)&W[(size_t)(k0 + r)*N + colBase + c4*4];
        }
        __syncthreads();
        #pragma unroll
        for (int kk = 0; kk < 16; kk++) {
            float a[8], b[8];
            *(float4*)&a[0] = *(const float4*)&As[kk][ty*8];
            *(float4*)&a[4] = *(const float4*)&As[kk][ty*8+4];
            *(float4*)&b[0] = *(const float4*)&Bs[kk][tx*8];
            *(float4*)&b[4] = *(const float4*)&Bs[kk][tx*8+4];
            #pragma unroll
            for (int i = 0; i < 8; i++)
                #pragma unroll
                for (int j = 0; j < 8; j++)
                    acc[i][j] = fmaf(a[i], b[j], acc[i][j]);
        }
        __syncthreads();
    }

    float bv[8];
    #pragma unroll
    for (int j = 0; j < 8; j++) bv[j] = bias[colBase + tx*8 + j];
    #pragma unroll
    for (int i = 0; i < 8; i++) {
        size_t off = (size_t)(rowBase + ty*8 + i)*N + colBase + tx*8;
        float4 v0 = make_float4(acc[i][0]+bv[0], acc[i][1]+bv[1],
                                acc[i][2]+bv[2], acc[i][3]+bv[3]);
        float4 v1 = make_float4(acc[i][4]+bv[4], acc[i][5]+bv[5],
                                acc[i][6]+bv[6], acc[i][7]+bv[7]);
        *(float4*)&C[off]   = v0;
        *(float4*)&C[off+4] = v1;
    }
}

// ---------------------------------------------------------------------------
// Causal flash attention with ALiBi. One CTA per (b, h, 64-row q tile).
// qkv layout: [b*S + s][6144], q at h*128, k at 2048+h*128, v at 4096+h*128.
// ---------------------------------------------------------------------------
#define SMEM_FLASH ((128*68 + 128*68 + 64*128 + 64*65) * 4)  /* 119040 B */

__global__ __launch_bounds__(256, 1)
void flash_attn(const float* __restrict__ qkv, float* __restrict__ attn)
{
    extern __shared__ float sm[];
    float* QsT = sm;                 // [128][68] kd-major (transposed)
    float* KsT = QsT + 128*68;       // [128][68] kd-major
    float* Vs  = KsT + 128*68;       // [64][128]
    float* Ss  = Vs  + 64*128;       // [64][65] score tile

    const int qt   = blockIdx.x;     // 0..31
    const int h    = blockIdx.y;
    const int b    = blockIdx.z;
    const int t    = threadIdx.x;
    const int lane = t & 31, w = t >> 5;
    const int tx   = t & 15, ty = t >> 4;

    const float scale = 0.08838834764831845f;        // 1/sqrt(128)
    const float slope = exp2f(-0.5f * (float)(h + 1)); // ALiBi slope (H=16=2^4)
    const size_t rstride = QKV_COLS;

    // Load Q tile transposed: QsT[kd][row]
    const float* Qg = qkv + ((size_t)(b*NS + qt*64))*rstride + h*NHD;
    {
        int r  = t >> 2;
        int cb = (t & 3) * 32;
        #pragma unroll
        for (int u = 0; u < 8; u++) {
            float4 v = *(const float4*)&Qg[(size_t)r*rstride + cb + u*4];
            int c = cb + u*4;
            QsT[(c+0)*68 + r] = v.x;
            QsT[(c+1)*68 + r] = v.y;
            QsT[(c+2)*68 + r] = v.z;
            QsT[(c+3)*68 + r] = v.w;
        }
    }

    // Online-softmax state: warp w owns rows (w&1)*32+lane, hd chunk (w>>1)*32
    const int prow = (w & 1)*32 + lane;
    const int hd0  = (w >> 1)*32;
    float mCur = -1e30f, lsum = 0.f;
    float oacc[32];
    #pragma unroll
    for (int i = 0; i < 32; i++) oacc[i] = 0.f;

    for (int kt = 0; kt <= qt; kt++) {
        __syncthreads();   // previous iteration's readers done with KsT/Vs/Ss

        const float* Kg = qkv + ((size_t)(b*NS + kt*64))*rstride + ND + h*NHD;
        const float* Vg = Kg + ND;
        {
            int r  = t >> 2;
            int cb = (t & 3) * 32;
            #pragma unroll
            for (int u = 0; u < 8; u++) {
                float4 v = *(const float4*)&Kg[(size_t)r*rstride + cb + u*4];
                int c = cb + u*4;
                KsT[(c+0)*68 + r] = v.x;
                KsT[(c+1)*68 + r] = v.y;
                KsT[(c+2)*68 + r] = v.z;
                KsT[(c+3)*68 + r] = v.w;
            }
            #pragma unroll
            for (int u = 0; u < 8; u++) {
                int idx = t + 256*u;
                int rv = idx >> 5, c4 = idx & 31;
                *(float4*)&Vs[rv*128 + c4*4] =
                    *(const float4*)&Vg[(size_t)rv*rstride + c4*4];
            }
        }
        __syncthreads();

        // Score tile: 16x16 threads, each 4 q-rows x 4 k-cols
        {
            float sacc[4][4];
            #pragma unroll
            for (int i = 0; i < 4; i++)
                #pragma unroll
                for (int j = 0; j < 4; j++) sacc[i][j] = 0.f;

            #pragma unroll 4
            for (int kd = 0; kd < 128; kd++) {
                float4 a  = *(const float4*)&QsT[kd*68 + ty*4];
                float4 bq = *(const float4*)&KsT[kd*68 + tx*4];
                float av[4] = {a.x, a.y, a.z, a.w};
                float kv[4] = {bq.x, bq.y, bq.z, bq.w};
                #pragma unroll
                for (int i = 0; i < 4; i++)
                    #pragma unroll
                    for (int j = 0; j < 4; j++)
                        sacc[i][j] = fmaf(av[i], kv[j], sacc[i][j]);
            }
            #pragma unroll
            for (int i = 0; i < 4; i++) {
                int qpos = qt*64 + ty*4 + i;
                #pragma unroll
                for (int j = 0; j < 4; j++) {
                    int kpos = kt*64 + tx*4 + j;
                    float v = sacc[i][j]*scale + slope*(float)(kpos - (NS-1));
                    if (kpos > qpos) v = -1e30f;   // causal mask
                    Ss[(ty*4+i)*65 + tx*4 + j] = v;
                }
            }
        }
        __syncthreads();

        // Online softmax + P@V update
        {
            float mNew = mCur;
            #pragma unroll 8
            for (int j = 0; j < 64; j++) mNew = fmaxf(mNew, Ss[prow*65 + j]);
            float corr = __expf(mCur - mNew);
            lsum *= corr;
            #pragma unroll
            for (int i = 0; i < 32; i++) oacc[i] *= corr;
            #pragma unroll 2
            for (int j = 0; j < 64; j++) {
                float p = __expf(Ss[prow*65 + j] - mNew);
                lsum += p;
                #pragma unroll
                for (int i2 = 0; i2 < 32; i2 += 4) {
                    float4 v = *(const float4*)&Vs[j*128 + hd0 + i2];
                    oacc[i2+0] = fmaf(p, v.x, oacc[i2+0]);
                    oacc[i2+1] = fmaf(p, v.y, oacc[i2+1]);
                    oacc[i2+2] = fmaf(p, v.z, oacc[i2+2]);
                    oacc[i2+3] = fmaf(p, v.w, oacc[i2+3]);
                }
            }
            mCur = mNew;
        }
    }

    float inv = 1.0f / lsum;
    size_t off = ((size_t)(b*NS + qt*64 + prow))*ND + h*NHD + hd0;
    #pragma unroll
    for (int i2 = 0; i2 < 32; i2 += 4) {
        float4 v = make_float4(oacc[i2+0]*inv, oacc[i2+1]*inv,
                               oacc[i2+2]*inv, oacc[i2+3]*inv);
        *(float4*)&attn[off + i2] = v;
    }
}

// ---------------------------------------------------------------------------
extern "C" void kernel_launch(void* const* d_in, const int* in_sizes, int n_in,
                              void* d_out, int out_size)
{
    const float* x    = (const float*)d_in[0];
    const float* Wqkv = (const float*)d_in[1];
    const float* bqkv = (const float*)d_in[2];
    const float* Wout = (const float*)d_in[3];
    const float* bout = (const float*)d_in[4];
    float* out = (float*)d_out;

    float *qkv = nullptr, *attn = nullptr;
    cudaGetSymbolAddress((void**)&qkv,  g_qkv);
    cudaGetSymbolAddress((void**)&attn, g_attn);
    cudaFuncSetAttribute(flash_attn,
                         cudaFuncAttributeMaxDynamicSharedMemorySize, SMEM_FLASH);

    // qkv = x @ Wqkv + b_qkv        [8192, 6144]
    sgemm_bias<<<dim3(QKV_COLS/128, ROWS/128), 256>>>(
        x, Wqkv, bqkv, qkv, ROWS, QKV_COLS, ND);

    // attention                      [8192, 2048]
    flash_attn<<<dim3(NS/64, NH, NB), 256, SMEM_FLASH>>>(qkv, attn);

    // out = attn @ Wout + b_out      [8192, 2048]
    sgemm_bias<<<dim3(ND/128, ROWS/128), 256>>>(
        attn, Wout, bout, out, ROWS, ND, ND);
}

// round 3
// speedup vs baseline: 1.6032x; 1.6032x over previous
#include <cuda_runtime.h>
#include <cuda_bf16.h>
#include <cstdint>
#include <math.h>

#define NB 4
#define NS 2048
#define ND 2048
#define NH 16
#define NHD 128
#define ROWS (NB*NS)        /* 8192 */
#define QKV_COLS (3*ND)     /* 6144 */

// ---------------- scratch (device globals: allocation-free rule) ----------
__device__ float g_qkv[(size_t)ROWS * QKV_COLS];           // 201 MB fp32
__device__ float g_attn[(size_t)ROWS * ND];                // 67 MB fp32
__device__ __nv_bfloat16 g_xhi[(size_t)ROWS * ND];
__device__ __nv_bfloat16 g_xlo[(size_t)ROWS * ND];
__device__ __nv_bfloat16 g_ahi[(size_t)ROWS * ND];
__device__ __nv_bfloat16 g_alo[(size_t)ROWS * ND];
__device__ __nv_bfloat16 g_wqT_hi[(size_t)QKV_COLS * ND];  // Wqkv^T [6144][2048]
__device__ __nv_bfloat16 g_wqT_lo[(size_t)QKV_COLS * ND];
__device__ __nv_bfloat16 g_woT_hi[(size_t)ND * ND];        // Wout^T [2048][2048]
__device__ __nv_bfloat16 g_woT_lo[(size_t)ND * ND];

// ---------------- PTX helpers (baseline features only: sm_80+) ------------
__device__ __forceinline__ uint32_t smem_u32(const void* p) {
    uint32_t a;
    asm("{ .reg .u64 t; cvta.to.shared.u64 t, %1; cvt.u32.u64 %0, t; }"
        : "=r"(a) : "l"(p));
    return a;
}

__device__ __forceinline__ void cpa16(uint32_t s, const void* g) {
    asm volatile("cp.async.cg.shared.global [%0], [%1], 16;" :: "r"(s), "l"(g));
}
#define CP_COMMIT() asm volatile("cp.async.commit_group;" ::: "memory")
#define CP_WAIT(n)  asm volatile("cp.async.wait_group %0;" :: "n"(n) : "memory")

__device__ __forceinline__ void ldsm4(uint32_t* r, uint32_t addr) {
    asm volatile("ldmatrix.sync.aligned.m8n8.x4.shared.b16 {%0,%1,%2,%3}, [%4];"
                 : "=r"(r[0]), "=r"(r[1]), "=r"(r[2]), "=r"(r[3]) : "r"(addr));
}

__device__ __forceinline__ void mma16816(float* d, const uint32_t* a,
                                         const uint32_t* b) {
    asm volatile(
        "mma.sync.aligned.m16n8k16.row.col.f32.bf16.bf16.f32 "
        "{%0,%1,%2,%3}, {%4,%5,%6,%7}, {%8,%9}, {%0,%1,%2,%3};"
        : "+f"(d[0]), "+f"(d[1]), "+f"(d[2]), "+f"(d[3])
        : "r"(a[0]), "r"(a[1]), "r"(a[2]), "r"(a[3]), "r"(b[0]), "r"(b[1]));
}

// ---------------------------------------------------------------------------
// conversion kernels: fp32 -> (bf16 hi, bf16 lo)
// ---------------------------------------------------------------------------
__global__ void cvt_split(const float4* __restrict__ in, uint2* __restrict__ hi,
                          uint2* __restrict__ lo)
{
    int i = blockIdx.x * blockDim.x + threadIdx.x;
    float4 v = in[i];
    __nv_bfloat16 h0 = __float2bfloat16(v.x), h1 = __float2bfloat16(v.y);
    __nv_bfloat16 h2 = __float2bfloat16(v.z), h3 = __float2bfloat16(v.w);
    __nv_bfloat16 l0 = __float2bfloat16(v.x - __bfloat162float(h0));
    __nv_bfloat16 l1 = __float2bfloat16(v.y - __bfloat162float(h1));
    __nv_bfloat16 l2 = __float2bfloat16(v.z - __bfloat162float(h2));
    __nv_bfloat16 l3 = __float2bfloat16(v.w - __bfloat162float(h3));
    uint2 uh, ul;
    uh.x = ((uint32_t)__bfloat16_as_ushort(h1) << 16) | __bfloat16_as_ushort(h0);
    uh.y = ((uint32_t)__bfloat16_as_ushort(h3) << 16) | __bfloat16_as_ushort(h2);
    ul.x = ((uint32_t)__bfloat16_as_ushort(l1) << 16) | __bfloat16_as_ushort(l0);
    ul.y = ((uint32_t)__bfloat16_as_ushort(l3) << 16) | __bfloat16_as_ushort(l2);
    hi[i] = uh;
    lo[i] = ul;
}

// W [K][N] fp32  ->  T [N][K] bf16 hi/lo
__global__ void cvt_split_T(const float* __restrict__ W,
                            __nv_bfloat16* __restrict__ Thi,
                            __nv_bfloat16* __restrict__ Tlo, int K, int N)
{
    __shared__ float tile[32][33];
    int n0 = blockIdx.x * 32, k0 = blockIdx.y * 32;
    int tx = threadIdx.x, ty = threadIdx.y;  // 32 x 8
    #pragma unroll
    for (int r = 0; r < 4; r++)
        tile[ty + r*8][tx] = W[(size_t)(k0 + ty + r*8) * N + n0 + tx];
    __syncthreads();
    #pragma unroll
    for (int r = 0; r < 4; r++) {
        float v = tile[tx][ty + r*8];          // W[k0+tx][n0+ty+r*8]
        __nv_bfloat16 h = __float2bfloat16(v);
        __nv_bfloat16 l = __float2bfloat16(v - __bfloat162float(h));
        size_t o = (size_t)(n0 + ty + r*8) * K + k0 + tx;
        Thi[o] = h;
        Tlo[o] = l;
    }
}

// ---------------------------------------------------------------------------
// bf16x3 GEMM via mma.sync: C[M,N] = A[M,K] @ B[N,K]^T + bias[N]
// CTA 128x128, BK=32, 8 warps (2m x 4n), warp tile 64x32, 3-stage cp.async.
// smem tile: 128 rows x 64 B, 16B chunks XOR-swizzled by ((row>>1)&3).
// ---------------------------------------------------------------------------
#define STAGES 3
#define STAGE_BYTES 32768      /* 4 tiles x 8192 B */
#define GEMM_SMEM (STAGES * STAGE_BYTES)

#define SWZ(row, kb) ((kb) ^ ((((row) >> 1) & 3) << 4))

__device__ __forceinline__ void issue_stage(
    uint32_t sb_stage, const __nv_bfloat16* __restrict__ Ahi,
    const __nv_bfloat16* __restrict__ Alo,
    const __nv_bfloat16* __restrict__ Bhi,
    const __nv_bfloat16* __restrict__ Blo,
    int rowBase, int colBase, int k0, int K, int t)
{
    #pragma unroll
    for (int u = 0; u < 2; u++) {
        int idx = t + 256*u;           // 0..511
        int row = idx >> 2, chunk = idx & 3;
        uint32_t soff = (uint32_t)(row*64 + SWZ(row, chunk*16));
        size_t ge = (size_t)row * K + k0 + chunk*8;
        cpa16(sb_stage +         soff, Ahi + (size_t)rowBase*K + ge);
        cpa16(sb_stage +  8192 + soff, Alo + (size_t)rowBase*K + ge);
        cpa16(sb_stage + 16384 + soff, Bhi + (size_t)colBase*K + ge);
        cpa16(sb_stage + 24576 + soff, Blo + (size_t)colBase*K + ge);
    }
    CP_COMMIT();
}

__global__ __launch_bounds__(256, 1)
void gemm_mma(const __nv_bfloat16* __restrict__ Ahi,
              const __nv_bfloat16* __restrict__ Alo,
              const __nv_bfloat16* __restrict__ Bhi,
              const __nv_bfloat16* __restrict__ Blo,
              const float* __restrict__ bias, float* __restrict__ C,
              int M, int N, int K)
{
    extern __shared__ char sm[];
    const uint32_t sb = smem_u32(sm);

    const int t = threadIdx.x, lane = t & 31, w = t >> 5;
    const int warp_m = w & 1, warp_n = w >> 1;   // 2 x 4
    const int rowBase = blockIdx.y * 128;
    const int colBase = blockIdx.x * 128;
    const int ksteps  = K >> 5;

    const int mat = lane >> 3, r8 = lane & 7;

    float acc[4][4][4];
    #pragma unroll
    for (int i = 0; i < 4; i++)
        #pragma unroll
        for (int j = 0; j < 4; j++)
            #pragma unroll
            for (int q = 0; q < 4; q++) acc[i][j][q] = 0.f;

    // prologue: stages 0,1
    issue_stage(sb,               Ahi, Alo, Bhi, Blo, rowBase, colBase, 0,  K, t);
    issue_stage(sb + STAGE_BYTES, Ahi, Alo, Bhi, Blo, rowBase, colBase, 32, K, t);

    // per-thread ldmatrix row indices (fixed across loop)
    int rowA[4], rowB[2];
    #pragma unroll
    for (int fm = 0; fm < 4; fm++)
        rowA[fm] = warp_m*64 + fm*16 + (mat & 1)*8 + r8;
    #pragma unroll
    for (int fb = 0; fb < 2; fb++)
        rowB[fb] = warp_n*32 + fb*16 + (mat >> 1)*8 + r8;

    for (int i = 0; i < ksteps; i++) {
        CP_WAIT(1);
        __syncthreads();

        const uint32_t st = sb + (uint32_t)(i % STAGES) * STAGE_BYTES;

        #pragma unroll
        for (int ks = 0; ks < 2; ks++) {
            uint32_t ah[4][4], al[4][4], bh[4][2], bl[4][2];
            const int kbA = ks*32 + (mat >> 1)*16;
            const int kbB = ks*32 + (mat & 1)*16;
            #pragma unroll
            for (int fm = 0; fm < 4; fm++) {
                uint32_t off = (uint32_t)(rowA[fm]*64 + SWZ(rowA[fm], kbA));
                ldsm4(ah[fm], st +        off);
                ldsm4(al[fm], st + 8192 + off);
            }
            #pragma unroll
            for (int fb = 0; fb < 2; fb++) {
                uint32_t off = (uint32_t)(rowB[fb]*64 + SWZ(rowB[fb], kbB));
                uint32_t rh[4], rl[4];
                ldsm4(rh, st + 16384 + off);
                ldsm4(rl, st + 24576 + off);
                bh[fb*2+0][0] = rh[0]; bh[fb*2+0][1] = rh[1];
                bh[fb*2+1][0] = rh[2]; bh[fb*2+1][1] = rh[3];
                bl[fb*2+0][0] = rl[0]; bl[fb*2+0][1] = rl[1];
                bl[fb*2+1][0] = rl[2]; bl[fb*2+1][1] = rl[3];
            }
            #pragma unroll
            for (int fm = 0; fm < 4; fm++)
                #pragma unroll
                for (int fn = 0; fn < 4; fn++) {
                    mma16816(acc[fm][fn], ah[fm], bh[fn]);
                    mma16816(acc[fm][fn], ah[fm], bl[fn]);
                    mma16816(acc[fm][fn], al[fm], bh[fn]);
                }
        }
        __syncthreads();
        if (i + 2 < ksteps)
            issue_stage(sb + (uint32_t)((i + 2) % STAGES) * STAGE_BYTES,
                        Ahi, Alo, Bhi, Blo, rowBase, colBase, (i + 2)*32, K, t);
    }

    // epilogue: acc[fm][fn]: d0,d1 -> row lane/4, cols 2*(lane%4)+{0,1};
    //                         d2,d3 -> row+8
    const int qrow = lane >> 2, qcol = (lane & 3) * 2;
    #pragma unroll
    for (int fn = 0; fn < 4; fn++) {
        const int col = colBase + warp_n*32 + fn*8 + qcol;
        const float b0 = bias[col], b1 = bias[col + 1];
        #pragma unroll
        for (int fm = 0; fm < 4; fm++) {
            const int row0 = rowBase + warp_m*64 + fm*16 + qrow;
            float2 v0 = make_float2(acc[fm][fn][0] + b0, acc[fm][fn][1] + b1);
            float2 v1 = make_float2(acc[fm][fn][2] + b0, acc[fm][fn][3] + b1);
            *(float2*)&C[(size_t)row0 * N + col]       = v0;
            *(float2*)&C[(size_t)(row0 + 8) * N + col] = v1;
        }
    }
}

// ---------------------------------------------------------------------------
// Causal flash attention with ALiBi (fp32, unchanged).
// ---------------------------------------------------------------------------
#define SMEM_FLASH ((128*68 + 128*68 + 64*128 + 64*65) * 4)  /* 119040 B */

__global__ __launch_bounds__(256, 1)
void flash_attn(const float* __restrict__ qkv, float* __restrict__ attn)
{
    extern __shared__ float smf[];
    float* QsT = smf;
    float* KsT = QsT + 128*68;
    float* Vs  = KsT + 128*68;
    float* Ss  = Vs  + 64*128;

    const int qt   = blockIdx.x;
    const int h    = blockIdx.y;
    const int b    = blockIdx.z;
    const int t    = threadIdx.x;
    const int lane = t & 31, w = t >> 5;
    const int tx   = t & 15, ty = t >> 4;

    const float scale = 0.08838834764831845f;
    const float slope = exp2f(-0.5f * (float)(h + 1));
    const size_t rstride = QKV_COLS;

    const float* Qg = qkv + ((size_t)(b*NS + qt*64))*rstride + h*NHD;
    {
        int r  = t >> 2;
        int cb = (t & 3) * 32;
        #pragma unroll
        for (int u = 0; u < 8; u++) {
            float4 v = *(const float4*)&Qg[(size_t)r*rstride + cb + u*4];
            int c = cb + u*4;
            QsT[(c+0)*68 + r] = v.x;
            QsT[(c+1)*68 + r] = v.y;
            QsT[(c+2)*68 + r] = v.z;
            QsT[(c+3)*68 + r] = v.w;
        }
    }

    const int prow = (w & 1)*32 + lane;
    const int hd0  = (w >> 1)*32;
    float mCur = -1e30f, lsum = 0.f;
    float oacc[32];
    #pragma unroll
    for (int i = 0; i < 32; i++) oacc[i] = 0.f;

    for (int kt = 0; kt <= qt; kt++) {
        __syncthreads();
        const float* Kg = qkv + ((size_t)(b*NS + kt*64))*rstride + ND + h*NHD;
        const float* Vg = Kg + ND;
        {
            int r  = t >> 2;
            int cb = (t & 3) * 32;
            #pragma unroll
            for (int u = 0; u < 8; u++) {
                float4 v = *(const float4*)&Kg[(size_t)r*rstride + cb + u*4];
                int c = cb + u*4;
                KsT[(c+0)*68 + r] = v.x;
                KsT[(c+1)*68 + r] = v.y;
                KsT[(c+2)*68 + r] = v.z;
                KsT[(c+3)*68 + r] = v.w;
            }
            #pragma unroll
            for (int u = 0; u < 8; u++) {
                int idx = t + 256*u;
                int rv = idx >> 5, c4 = idx & 31;
                *(float4*)&Vs[rv*128 + c4*4] =
                    *(const float4*)&Vg[(size_t)rv*rstride + c4*4];
            }
        }
        __syncthreads();

        {
            float sacc[4][4];
            #pragma unroll
            for (int i = 0; i < 4; i++)
                #pragma unroll
                for (int j = 0; j < 4; j++) sacc[i][j] = 0.f;

            #pragma unroll 4
            for (int kd = 0; kd < 128; kd++) {
                float4 a  = *(const float4*)&QsT[kd*68 + ty*4];
                float4 bq = *(const float4*)&KsT[kd*68 + tx*4];
                float av[4] = {a.x, a.y, a.z, a.w};
                float kv[4] = {bq.x, bq.y, bq.z, bq.w};
                #pragma unroll
                for (int i = 0; i < 4; i++)
                    #pragma unroll
                    for (int j = 0; j < 4; j++)
                        sacc[i][j] = fmaf(av[i], kv[j], sacc[i][j]);
            }
            #pragma unroll
            for (int i = 0; i < 4; i++) {
                int qpos = qt*64 + ty*4 + i;
                #pragma unroll
                for (int j = 0; j < 4; j++) {
                    int kpos = kt*64 + tx*4 + j;
                    float v = sacc[i][j]*scale + slope*(float)(kpos - (NS-1));
                    if (kpos > qpos) v = -1e30f;
                    Ss[(ty*4+i)*65 + tx*4 + j] = v;
                }
            }
        }
        __syncthreads();

        {
            float mNew = mCur;
            #pragma unroll 8
            for (int j = 0; j < 64; j++) mNew = fmaxf(mNew, Ss[prow*65 + j]);
            float corr = __expf(mCur - mNew);
            lsum *= corr;
            #pragma unroll
            for (int i = 0; i < 32; i++) oacc[i] *= corr;
            #pragma unroll 2
            for (int j = 0; j < 64; j++) {
                float p = __expf(Ss[prow*65 + j] - mNew);
                lsum += p;
                #pragma unroll
                for (int i2 = 0; i2 < 32; i2 += 4) {
                    float4 v = *(const float4*)&Vs[j*128 + hd0 + i2];
                    oacc[i2+0] = fmaf(p, v.x, oacc[i2+0]);
                    oacc[i2+1] = fmaf(p, v.y, oacc[i2+1]);
                    oacc[i2+2] = fmaf(p, v.z, oacc[i2+2]);
                    oacc[i2+3] = fmaf(p, v.w, oacc[i2+3]);
                }
            }
            mCur = mNew;
        }
    }

    float inv = 1.0f / lsum;
    size_t off = ((size_t)(b*NS + qt*64 + prow))*ND + h*NHD + hd0;
    #pragma unroll
    for (int i2 = 0; i2 < 32; i2 += 4) {
        float4 v = make_float4(oacc[i2+0]*inv, oacc[i2+1]*inv,
                               oacc[i2+2]*inv, oacc[i2+3]*inv);
        *(float4*)&attn[off + i2] = v;
    }
}

// ---------------------------------------------------------------------------
extern "C" void kernel_launch(void* const* d_in, const int* in_sizes, int n_in,
                              void* d_out, int out_size)
{
    const float* x    = (const float*)d_in[0];
    const float* Wqkv = (const float*)d_in[1];
    const float* bqkv = (const float*)d_in[2];
    const float* Wout = (const float*)d_in[3];
    const float* bout = (const float*)d_in[4];
    float* out = (float*)d_out;

    float *qkv = nullptr, *attn = nullptr;
    __nv_bfloat16 *xhi, *xlo, *ahi, *alo, *wqh, *wql, *woh, *wol;
    cudaGetSymbolAddress((void**)&qkv,  g_qkv);
    cudaGetSymbolAddress((void**)&attn, g_attn);
    cudaGetSymbolAddress((void**)&xhi,  g_xhi);
    cudaGetSymbolAddress((void**)&xlo,  g_xlo);
    cudaGetSymbolAddress((void**)&ahi,  g_ahi);
    cudaGetSymbolAddress((void**)&alo,  g_alo);
    cudaGetSymbolAddress((void**)&wqh,  g_wqT_hi);
    cudaGetSymbolAddress((void**)&wql,  g_wqT_lo);
    cudaGetSymbolAddress((void**)&woh,  g_woT_hi);
    cudaGetSymbolAddress((void**)&wol,  g_woT_lo);

    cudaFuncSetAttribute(flash_attn,
                         cudaFuncAttributeMaxDynamicSharedMemorySize, SMEM_FLASH);
    cudaFuncSetAttribute(gemm_mma,
                         cudaFuncAttributeMaxDynamicSharedMemorySize, GEMM_SMEM);

    // operand conversions
    cvt_split<<<(ROWS*(size_t)ND/4 + 255)/256, 256>>>(
        (const float4*)x, (uint2*)xhi, (uint2*)xlo);
    cvt_split_T<<<dim3(QKV_COLS/32, ND/32), dim3(32, 8)>>>(Wqkv, wqh, wql, ND, QKV_COLS);
    cvt_split_T<<<dim3(ND/32, ND/32), dim3(32, 8)>>>(Wout, woh, wol, ND, ND);

    // qkv = x @ Wqkv + b_qkv   [8192, 6144]
    gemm_mma<<<dim3(QKV_COLS/128, ROWS/128), 256, GEMM_SMEM>>>(
        xhi, xlo, wqh, wql, bqkv, qkv, ROWS, QKV_COLS, ND);

    // attention                [8192, 2048]
    flash_attn<<<dim3(NS/64, NH, NB), 256, SMEM_FLASH>>>(qkv, attn);

    // out = attn @ Wout + b_out
    cvt_split<<<(ROWS*(size_t)ND/4 + 255)/256, 256>>>(
        (const float4*)attn, (uint2*)ahi, (uint2*)alo);
    gemm_mma<<<dim3(ND/128, ROWS/128), 256, GEMM_SMEM>>>(
        ahi, alo, woh, wol, bout, out, ROWS, ND, ND);
}

// round 4
// speedup vs baseline: 2.8269x; 1.7633x over previous
#include <cuda_runtime.h>
#include <cuda_bf16.h>
#include <cstdint>
#include <math.h>

#define NB 4
#define NS 2048
#define ND 2048
#define NH 16
#define NHD 128
#define ROWS (NB*NS)        /* 8192 */
#define QKV_COLS (3*ND)     /* 6144 */

// ---------------- scratch (device globals: allocation-free rule) ----------
__device__ float g_qkv[(size_t)ROWS * QKV_COLS];           // 201 MB fp32
__device__ __nv_bfloat16 g_xhi[(size_t)ROWS * ND];
__device__ __nv_bfloat16 g_xlo[(size_t)ROWS * ND];
__device__ __nv_bfloat16 g_ahi[(size_t)ROWS * ND];         // attn out hi
__device__ __nv_bfloat16 g_alo[(size_t)ROWS * ND];         // attn out lo
__device__ __nv_bfloat16 g_wqT_hi[(size_t)QKV_COLS * ND];  // Wqkv^T [6144][2048]
__device__ __nv_bfloat16 g_wqT_lo[(size_t)QKV_COLS * ND];
__device__ __nv_bfloat16 g_woT_hi[(size_t)ND * ND];        // Wout^T [2048][2048]
__device__ __nv_bfloat16 g_woT_lo[(size_t)ND * ND];
// per-head split QKV: [B*H][S][HD]
__device__ __nv_bfloat16 g_qh[(size_t)ROWS * ND];
__device__ __nv_bfloat16 g_ql[(size_t)ROWS * ND];
__device__ __nv_bfloat16 g_kh[(size_t)ROWS * ND];
__device__ __nv_bfloat16 g_kl[(size_t)ROWS * ND];
__device__ __nv_bfloat16 g_vh[(size_t)ROWS * ND];
__device__ __nv_bfloat16 g_vl[(size_t)ROWS * ND];

// ---------------- PTX helpers (baseline features only: sm_80+) ------------
__device__ __forceinline__ uint32_t smem_u32(const void* p) {
    uint32_t a;
    asm("{ .reg .u64 t; cvta.to.shared.u64 t, %1; cvt.u32.u64 %0, t; }"
        : "=r"(a) : "l"(p));
    return a;
}

__device__ __forceinline__ void cpa16(uint32_t s, const void* g) {
    asm volatile("cp.async.cg.shared.global [%0], [%1], 16;" :: "r"(s), "l"(g));
}
#define CP_COMMIT() asm volatile("cp.async.commit_group;" ::: "memory")
#define CP_WAIT(n)  asm volatile("cp.async.wait_group %0;" :: "n"(n) : "memory")

__device__ __forceinline__ void ldsm4(uint32_t* r, uint32_t addr) {
    asm volatile("ldmatrix.sync.aligned.m8n8.x4.shared.b16 {%0,%1,%2,%3}, [%4];"
                 : "=r"(r[0]), "=r"(r[1]), "=r"(r[2]), "=r"(r[3]) : "r"(addr));
}
__device__ __forceinline__ void ldsm4t(uint32_t* r, uint32_t addr) {
    asm volatile("ldmatrix.sync.aligned.m8n8.x4.trans.shared.b16 {%0,%1,%2,%3}, [%4];"
                 : "=r"(r[0]), "=r"(r[1]), "=r"(r[2]), "=r"(r[3]) : "r"(addr));
}

__device__ __forceinline__ void mma16816(float* d, const uint32_t* a,
                                         const uint32_t* b) {
    asm volatile(
        "mma.sync.aligned.m16n8k16.row.col.f32.bf16.bf16.f32 "
        "{%0,%1,%2,%3}, {%4,%5,%6,%7}, {%8,%9}, {%0,%1,%2,%3};"
        : "+f"(d[0]), "+f"(d[1]), "+f"(d[2]), "+f"(d[3])
        : "r"(a[0]), "r"(a[1]), "r"(a[2]), "r"(a[3]), "r"(b[0]), "r"(b[1]));
}

#define PACK2(lo16, hi16) (((uint32_t)(hi16) << 16) | (uint32_t)(lo16))
#define BFU(x) __bfloat16_as_ushort(x)

// ---------------------------------------------------------------------------
// conversion kernels
// ---------------------------------------------------------------------------
__global__ void cvt_split(const float4* __restrict__ in, uint2* __restrict__ hi,
                          uint2* __restrict__ lo)
{
    int i = blockIdx.x * blockDim.x + threadIdx.x;
    float4 v = in[i];
    __nv_bfloat16 h0 = __float2bfloat16(v.x), h1 = __float2bfloat16(v.y);
    __nv_bfloat16 h2 = __float2bfloat16(v.z), h3 = __float2bfloat16(v.w);
    __nv_bfloat16 l0 = __float2bfloat16(v.x - __bfloat162float(h0));
    __nv_bfloat16 l1 = __float2bfloat16(v.y - __bfloat162float(h1));
    __nv_bfloat16 l2 = __float2bfloat16(v.z - __bfloat162float(h2));
    __nv_bfloat16 l3 = __float2bfloat16(v.w - __bfloat162float(h3));
    uint2 uh, ul;
    uh.x = PACK2(BFU(h0), BFU(h1));  uh.y = PACK2(BFU(h2), BFU(h3));
    ul.x = PACK2(BFU(l0), BFU(l1));  ul.y = PACK2(BFU(l2), BFU(l3));
    hi[i] = uh;
    lo[i] = ul;
}

// W [K][N] fp32  ->  T [N][K] bf16 hi/lo
__global__ void cvt_split_T(const float* __restrict__ W,
                            __nv_bfloat16* __restrict__ Thi,
                            __nv_bfloat16* __restrict__ Tlo, int K, int N)
{
    __shared__ float tile[32][33];
    int n0 = blockIdx.x * 32, k0 = blockIdx.y * 32;
    int tx = threadIdx.x, ty = threadIdx.y;  // 32 x 8
    #pragma unroll
    for (int r = 0; r < 4; r++)
        tile[ty + r*8][tx] = W[(size_t)(k0 + ty + r*8) * N + n0 + tx];
    __syncthreads();
    #pragma unroll
    for (int r = 0; r < 4; r++) {
        float v = tile[tx][ty + r*8];
        __nv_bfloat16 h = __float2bfloat16(v);
        __nv_bfloat16 l = __float2bfloat16(v - __bfloat162float(h));
        size_t o = (size_t)(n0 + ty + r*8) * K + k0 + tx;
        Thi[o] = h;
        Tlo[o] = l;
    }
}

// g_qkv [8192][6144] fp32 -> per-head [B*H][S][HD] bf16 hi/lo for q,k,v
__global__ void cvt_qkv(const float* __restrict__ qkv,
                        uint2* __restrict__ qh, uint2* __restrict__ ql,
                        uint2* __restrict__ kh, uint2* __restrict__ kl,
                        uint2* __restrict__ vh, uint2* __restrict__ vl)
{
    const int row = blockIdx.x;            // b*NS + s
    const int b = row >> 11, s = row & 2047;
    const int t = threadIdx.x;
    #pragma unroll
    for (int it = 0; it < 6; it++) {
        int idx  = it*256 + t;             // 0..1535
        int col4 = idx * 4;
        int sel  = col4 >> 11;
        int h    = (col4 >> 7) & 15;
        int hd   = col4 & 127;
        float4 v = *(const float4*)&qkv[(size_t)row * QKV_COLS + col4];
        __nv_bfloat16 h0 = __float2bfloat16(v.x), h1 = __float2bfloat16(v.y);
        __nv_bfloat16 h2 = __float2bfloat16(v.z), h3 = __float2bfloat16(v.w);
        __nv_bfloat16 l0 = __float2bfloat16(v.x - __bfloat162float(h0));
        __nv_bfloat16 l1 = __float2bfloat16(v.y - __bfloat162float(h1));
        __nv_bfloat16 l2 = __float2bfloat16(v.z - __bfloat162float(h2));
        __nv_bfloat16 l3 = __float2bfloat16(v.w - __bfloat162float(h3));
        uint2 uh, ul;
        uh.x = PACK2(BFU(h0), BFU(h1));  uh.y = PACK2(BFU(h2), BFU(h3));
        ul.x = PACK2(BFU(l0), BFU(l1));  ul.y = PACK2(BFU(l2), BFU(l3));
        size_t o = (((size_t)(b*NH + h) * NS + s) * NHD + hd) >> 2;
        uint2* dh = (sel == 0) ? qh : (sel == 1) ? kh : vh;
        uint2* dl = (sel == 0) ? ql : (sel == 1) ? kl : vl;
        dh[o] = uh;
        dl[o] = ul;
    }
}

// ---------------------------------------------------------------------------
// bf16x3 GEMM via mma.sync (unchanged from R3)
// ---------------------------------------------------------------------------
#define STAGES 3
#define STAGE_BYTES 32768
#define GEMM_SMEM (STAGES * STAGE_BYTES)
#define SWZ(row, kb) ((kb) ^ ((((row) >> 1) & 3) << 4))

__device__ __forceinline__ void issue_stage(
    uint32_t sb_stage, const __nv_bfloat16* __restrict__ Ahi,
    const __nv_bfloat16* __restrict__ Alo,
    const __nv_bfloat16* __restrict__ Bhi,
    const __nv_bfloat16* __restrict__ Blo,
    int rowBase, int colBase, int k0, int K, int t)
{
    #pragma unroll
    for (int u = 0; u < 2; u++) {
        int idx = t + 256*u;
        int row = idx >> 2, chunk = idx & 3;
        uint32_t soff = (uint32_t)(row*64 + SWZ(row, chunk*16));
        size_t ge = (size_t)row * K + k0 + chunk*8;
        cpa16(sb_stage +         soff, Ahi + (size_t)rowBase*K + ge);
        cpa16(sb_stage +  8192 + soff, Alo + (size_t)rowBase*K + ge);
        cpa16(sb_stage + 16384 + soff, Bhi + (size_t)colBase*K + ge);
        cpa16(sb_stage + 24576 + soff, Blo + (size_t)colBase*K + ge);
    }
    CP_COMMIT();
}

__global__ __launch_bounds__(256, 1)
void gemm_mma(const __nv_bfloat16* __restrict__ Ahi,
              const __nv_bfloat16* __restrict__ Alo,
              const __nv_bfloat16* __restrict__ Bhi,
              const __nv_bfloat16* __restrict__ Blo,
              const float* __restrict__ bias, float* __restrict__ C,
              int M, int N, int K)
{
    extern __shared__ char sm[];
    const uint32_t sb = smem_u32(sm);

    const int t = threadIdx.x, lane = t & 31, w = t >> 5;
    const int warp_m = w & 1, warp_n = w >> 1;
    const int rowBase = blockIdx.y * 128;
    const int colBase = blockIdx.x * 128;
    const int ksteps  = K >> 5;
    const int mat = lane >> 3, r8 = lane & 7;

    float acc[4][4][4];
    #pragma unroll
    for (int i = 0; i < 4; i++)
        #pragma unroll
        for (int j = 0; j < 4; j++)
            #pragma unroll
            for (int q = 0; q < 4; q++) acc[i][j][q] = 0.f;

    issue_stage(sb,               Ahi, Alo, Bhi, Blo, rowBase, colBase, 0,  K, t);
    issue_stage(sb + STAGE_BYTES, Ahi, Alo, Bhi, Blo, rowBase, colBase, 32, K, t);

    int rowA[4], rowB[2];
    #pragma unroll
    for (int fm = 0; fm < 4; fm++)
        rowA[fm] = warp_m*64 + fm*16 + (mat & 1)*8 + r8;
    #pragma unroll
    for (int fb = 0; fb < 2; fb++)
        rowB[fb] = warp_n*32 + fb*16 + (mat >> 1)*8 + r8;

    for (int i = 0; i < ksteps; i++) {
        CP_WAIT(1);
        __syncthreads();
        const uint32_t st = sb + (uint32_t)(i % STAGES) * STAGE_BYTES;

        #pragma unroll
        for (int ks = 0; ks < 2; ks++) {
            uint32_t ah[4][4], al[4][4], bh[4][2], bl[4][2];
            const int kbA = ks*32 + (mat >> 1)*16;
            const int kbB = ks*32 + (mat & 1)*16;
            #pragma unroll
            for (int fm = 0; fm < 4; fm++) {
                uint32_t off = (uint32_t)(rowA[fm]*64 + SWZ(rowA[fm], kbA));
                ldsm4(ah[fm], st +        off);
                ldsm4(al[fm], st + 8192 + off);
            }
            #pragma unroll
            for (int fb = 0; fb < 2; fb++) {
                uint32_t off = (uint32_t)(rowB[fb]*64 + SWZ(rowB[fb], kbB));
                uint32_t rh[4], rl[4];
                ldsm4(rh, st + 16384 + off);
                ldsm4(rl, st + 24576 + off);
                bh[fb*2+0][0] = rh[0]; bh[fb*2+0][1] = rh[1];
                bh[fb*2+1][0] = rh[2]; bh[fb*2+1][1] = rh[3];
                bl[fb*2+0][0] = rl[0]; bl[fb*2+0][1] = rl[1];
                bl[fb*2+1][0] = rl[2]; bl[fb*2+1][1] = rl[3];
            }
            #pragma unroll
            for (int fm = 0; fm < 4; fm++)
                #pragma unroll
                for (int fn = 0; fn < 4; fn++) {
                    mma16816(acc[fm][fn], ah[fm], bh[fn]);
                    mma16816(acc[fm][fn], ah[fm], bl[fn]);
                    mma16816(acc[fm][fn], al[fm], bh[fn]);
                }
        }
        __syncthreads();
        if (i + 2 < ksteps)
            issue_stage(sb + (uint32_t)((i + 2) % STAGES) * STAGE_BYTES,
                        Ahi, Alo, Bhi, Blo, rowBase, colBase, (i + 2)*32, K, t);
    }

    const int qrow = lane >> 2, qcol = (lane & 3) * 2;
    #pragma unroll
    for (int fn = 0; fn < 4; fn++) {
        const int col = colBase + warp_n*32 + fn*8 + qcol;
        const float b0 = bias[col], b1 = bias[col + 1];
        #pragma unroll
        for (int fm = 0; fm < 4; fm++) {
            const int row0 = rowBase + warp_m*64 + fm*16 + qrow;
            float2 v0 = make_float2(acc[fm][fn][0] + b0, acc[fm][fn][1] + b1);
            float2 v1 = make_float2(acc[fm][fn][2] + b0, acc[fm][fn][3] + b1);
            *(float2*)&C[(size_t)row0 * N + col]       = v0;
            *(float2*)&C[(size_t)(row0 + 8) * N + col] = v1;
        }
    }
}

// ---------------------------------------------------------------------------
// Flash attention via mma.sync, bf16x3 emulation, ALiBi + causal.
// CTA: 128 q rows x (h, b). 8 warps x 16 rows. K-tiles of 64 keys.
// smem: Q(hi|lo) 64KB @0, stages of K(hi|lo)+V(hi|lo) 64KB @65536 + s*65536.
// Row layout: 128 hd * 2B = 256B = 16 chunks of 16B, chunk ^= (row&7).
// ---------------------------------------------------------------------------
#define FLASH_SMEM (65536 + 2*65536)   /* 196608 */
#define SWZF(row, chunk) (((chunk) ^ ((row) & 7)) << 4)

__device__ __forceinline__ void flash_load_kv(
    uint32_t st, const __nv_bfloat16* __restrict__ kh,
    const __nv_bfloat16* __restrict__ kl,
    const __nv_bfloat16* __restrict__ vh,
    const __nv_bfloat16* __restrict__ vl,
    size_t hb, int kt, int t)
{
    #pragma unroll
    for (int u = 0; u < 4; u++) {
        int idx = t + 256*u;                 // 0..1023
        int row = idx >> 4, chunk = idx & 15;
        uint32_t soff = (uint32_t)(row*256 + SWZF(row, chunk));
        size_t g = hb + (size_t)(kt*64 + row)*NHD + chunk*8;
        cpa16(st +         soff, kh + g);
        cpa16(st + 16384 + soff, kl + g);
        cpa16(st + 32768 + soff, vh + g);
        cpa16(st + 49152 + soff, vl + g);
    }
}

__global__ __launch_bounds__(256, 1)
void flash_mma(const __nv_bfloat16* __restrict__ qh,
               const __nv_bfloat16* __restrict__ ql,
               const __nv_bfloat16* __restrict__ kh,
               const __nv_bfloat16* __restrict__ kl,
               const __nv_bfloat16* __restrict__ vh,
               const __nv_bfloat16* __restrict__ vl,
               __nv_bfloat16* __restrict__ ahi,
               __nv_bfloat16* __restrict__ alo)
{
    extern __shared__ char sm[];
    const uint32_t sb = smem_u32(sm);

    const int qt = blockIdx.x, h = blockIdx.y, b = blockIdx.z;
    const int t = threadIdx.x, lane = t & 31, w = t >> 5;
    const size_t hb = (size_t)(b*NH + h) * NS * NHD;

    const float scale = 0.08838834764831845f;          // 1/sqrt(128)
    const float slope = exp2f(-0.5f * (float)(h + 1)); // ALiBi, H=16
    const int r8 = lane & 7, m01 = (lane >> 3) & 1, m2 = lane >> 4;
    const int qr = lane >> 2, qc = (lane & 3) * 2;
    const int rg0 = qt*128 + w*16 + qr;                // global q row (c0/c1)

    // load Q tile (rows qt*128 .. +127)
    #pragma unroll
    for (int u = 0; u < 8; u++) {
        int idx = t + 256*u;                 // 0..2047
        int row = idx >> 4, chunk = idx & 15;
        uint32_t soff = (uint32_t)(row*256 + SWZF(row, chunk));
        size_t g = hb + (size_t)(qt*128 + row)*NHD + chunk*8;
        cpa16(sb +         soff, qh + g);
        cpa16(sb + 32768 + soff, ql + g);
    }
    flash_load_kv(sb + 65536, kh, kl, vh, vl, hb, 0, t);
    CP_COMMIT();                                       // group: Q + stage0
    flash_load_kv(sb + 65536 + 65536, kh, kl, vh, vl, hb, 1, t);
    CP_COMMIT();                                       // group: stage1

    float m0 = -1e30f, m1 = -1e30f, l0 = 0.f, l1 = 0.f;
    float acc_o[16][4];
    #pragma unroll
    for (int i = 0; i < 16; i++)
        #pragma unroll
        for (int j = 0; j < 4; j++) acc_o[i][j] = 0.f;

    const int nkt = 2*qt + 2;
    for (int kt = 0; kt < nkt; kt++) {
        if (kt == nkt - 1) { CP_WAIT(0); } else { CP_WAIT(1); }
        __syncthreads();
        const uint32_t st = sb + 65536 + (uint32_t)(kt & 1)*65536;

        // ---- S = Q K^T (3-term) ----
        float s_[8][4];
        #pragma unroll
        for (int i = 0; i < 8; i++)
            #pragma unroll
            for (int j = 0; j < 4; j++) s_[i][j] = 0.f;

        #pragma unroll
        for (int kc = 0; kc < 8; kc++) {
            uint32_t ah[4], al[4];
            int qrow = w*16 + m01*8 + r8;
            int qchk = kc*2 + m2;
            uint32_t qa = sb + (uint32_t)(qrow*256 + SWZF(qrow, qchk));
            ldsm4(ah, qa);
            ldsm4(al, qa + 32768);
            #pragma unroll
            for (int ng = 0; ng < 4; ng++) {
                int krow = ng*16 + m2*8 + r8;
                int kchk = kc*2 + m01;
                uint32_t ka = st + (uint32_t)(krow*256 + SWZF(krow, kchk));
                uint32_t rh[4], rl[4];
                ldsm4(rh, ka);
                ldsm4(rl, ka + 16384);
                mma16816(s_[ng*2+0], ah, rh);
                mma16816(s_[ng*2+0], ah, rl);
                mma16816(s_[ng*2+0], al, rh);
                mma16816(s_[ng*2+1], ah, rh+2);
                mma16816(s_[ng*2+1], ah, rl+2);
                mma16816(s_[ng*2+1], al, rh+2);
            }
        }

        // ---- scale + alibi + causal mask, row max ----
        const bool diag = (kt >= 2*qt);
        float tm0 = -1e30f, tm1 = -1e30f;
        #pragma unroll
        for (int nt = 0; nt < 8; nt++) {
            #pragma unroll
            for (int jj = 0; jj < 2; jj++) {
                int col = kt*64 + nt*8 + qc + jj;
                float ab = slope * (float)(col - (NS - 1));
                float v0 = fmaf(s_[nt][jj],     scale, ab);
                float v1 = fmaf(s_[nt][2 + jj], scale, ab);
                if (diag) {
                    if (col > rg0)     v0 = -1e30f;
                    if (col > rg0 + 8) v1 = -1e30f;
                }
                s_[nt][jj]     = v0;
                s_[nt][2 + jj] = v1;
                tm0 = fmaxf(tm0, v0);
                tm1 = fmaxf(tm1, v1);
            }
        }
        tm0 = fmaxf(tm0, __shfl_xor_sync(0xffffffffu, tm0, 1));
        tm0 = fmaxf(tm0, __shfl_xor_sync(0xffffffffu, tm0, 2));
        tm1 = fmaxf(tm1, __shfl_xor_sync(0xffffffffu, tm1, 1));
        tm1 = fmaxf(tm1, __shfl_xor_sync(0xffffffffu, tm1, 2));

        float mn0 = fmaxf(m0, tm0), mn1 = fmaxf(m1, tm1);
        float c0 = __expf(m0 - mn0), c1 = __expf(m1 - mn1);
        m0 = mn0; m1 = mn1;
        l0 *= c0; l1 *= c1;
        #pragma unroll
        for (int i = 0; i < 16; i++) {
            acc_o[i][0] *= c0; acc_o[i][1] *= c0;
            acc_o[i][2] *= c1; acc_o[i][3] *= c1;
        }
        #pragma unroll
        for (int nt = 0; nt < 8; nt++) {
            float p0 = __expf(s_[nt][0] - m0);
            float p1 = __expf(s_[nt][1] - m0);
            float p2 = __expf(s_[nt][2] - m1);
            float p3 = __expf(s_[nt][3] - m1);
            l0 += p0 + p1;
            l1 += p2 + p3;
            s_[nt][0] = p0; s_[nt][1] = p1; s_[nt][2] = p2; s_[nt][3] = p3;
        }

        // ---- O += P V (3-term) ----
        #pragma unroll
        for (int kc = 0; kc < 4; kc++) {
            uint32_t ph[4], pl[4];
            {
                const float* pa = s_[2*kc];
                const float* pb = s_[2*kc + 1];
                __nv_bfloat16 h0 = __float2bfloat16(pa[0]);
                __nv_bfloat16 h1 = __float2bfloat16(pa[1]);
                __nv_bfloat16 h2 = __float2bfloat16(pa[2]);
                __nv_bfloat16 h3 = __float2bfloat16(pa[3]);
                __nv_bfloat16 h4 = __float2bfloat16(pb[0]);
                __nv_bfloat16 h5 = __float2bfloat16(pb[1]);
                __nv_bfloat16 h6 = __float2bfloat16(pb[2]);
                __nv_bfloat16 h7 = __float2bfloat16(pb[3]);
                ph[0] = PACK2(BFU(h0), BFU(h1));
                ph[1] = PACK2(BFU(h2), BFU(h3));
                ph[2] = PACK2(BFU(h4), BFU(h5));
                ph[3] = PACK2(BFU(h6), BFU(h7));
                __nv_bfloat16 e0 = __float2bfloat16(pa[0] - __bfloat162float(h0));
                __nv_bfloat16 e1 = __float2bfloat16(pa[1] - __bfloat162float(h1));
                __nv_bfloat16 e2 = __float2bfloat16(pa[2] - __bfloat162float(h2));
                __nv_bfloat16 e3 = __float2bfloat16(pa[3] - __bfloat162float(h3));
                __nv_bfloat16 e4 = __float2bfloat16(pb[0] - __bfloat162float(h4));
                __nv_bfloat16 e5 = __float2bfloat16(pb[1] - __bfloat162float(h5));
                __nv_bfloat16 e6 = __float2bfloat16(pb[2] - __bfloat162float(h6));
                __nv_bfloat16 e7 = __float2bfloat16(pb[3] - __bfloat162float(h7));
                pl[0] = PACK2(BFU(e0), BFU(e1));
                pl[1] = PACK2(BFU(e2), BFU(e3));
                pl[2] = PACK2(BFU(e4), BFU(e5));
                pl[3] = PACK2(BFU(e6), BFU(e7));
            }
            #pragma unroll
            for (int ng = 0; ng < 8; ng++) {
                int vrow = kc*16 + m01*8 + r8;
                int vchk = ng*2 + m2;
                uint32_t va = st + 32768 + (uint32_t)(vrow*256 + SWZF(vrow, vchk));
                uint32_t wh[4], wl[4];
                ldsm4t(wh, va);
                ldsm4t(wl, va + 16384);
                mma16816(acc_o[ng*2+0], ph, wh);
                mma16816(acc_o[ng*2+0], ph, wl);
                mma16816(acc_o[ng*2+0], pl, wh);
                mma16816(acc_o[ng*2+1], ph, wh+2);
                mma16816(acc_o[ng*2+1], ph, wl+2);
                mma16816(acc_o[ng*2+1], pl, wh+2);
            }
        }

        __syncthreads();
        if (kt + 2 < nkt) {
            flash_load_kv(sb + 65536 + (uint32_t)(kt & 1)*65536,
                          kh, kl, vh, vl, hb, kt + 2, t);
            CP_COMMIT();
        }
    }

    // ---- finalize ----
    l0 += __shfl_xor_sync(0xffffffffu, l0, 1);
    l0 += __shfl_xor_sync(0xffffffffu, l0, 2);
    l1 += __shfl_xor_sync(0xffffffffu, l1, 1);
    l1 += __shfl_xor_sync(0xffffffffu, l1, 2);
    const float inv0 = 1.f / l0, inv1 = 1.f / l1;

    const size_t row0 = (size_t)(b*NS) + qt*128 + w*16 + qr;
    #pragma unroll
    for (int nt = 0; nt < 16; nt++) {
        int col = h*NHD + nt*8 + qc;
        float v0 = acc_o[nt][0] * inv0, v1 = acc_o[nt][1] * inv0;
        float v2 = acc_o[nt][2] * inv1, v3 = acc_o[nt][3] * inv1;
        __nv_bfloat16 h0 = __float2bfloat16(v0), h1 = __float2bfloat16(v1);
        __nv_bfloat16 h2 = __float2bfloat16(v2), h3 = __float2bfloat16(v3);
        __nv_bfloat16 e0 = __float2bfloat16(v0 - __bfloat162float(h0));
        __nv_bfloat16 e1 = __float2bfloat16(v1 - __bfloat162float(h1));
        __nv_bfloat16 e2 = __float2bfloat16(v2 - __bfloat162float(h2));
        __nv_bfloat16 e3 = __float2bfloat16(v3 - __bfloat162float(h3));
        *(uint32_t*)&ahi[row0 * ND + col]       = PACK2(BFU(h0), BFU(h1));
        *(uint32_t*)&alo[row0 * ND + col]       = PACK2(BFU(e0), BFU(e1));
        *(uint32_t*)&ahi[(row0 + 8) * ND + col] = PACK2(BFU(h2), BFU(h3));
        *(uint32_t*)&alo[(row0 + 8) * ND + col] = PACK2(BFU(e2), BFU(e3));
    }
}

// ---------------------------------------------------------------------------
extern "C" void kernel_launch(void* const* d_in, const int* in_sizes, int n_in,
                              void* d_out, int out_size)
{
    const float* x    = (const float*)d_in[0];
    const float* Wqkv = (const float*)d_in[1];
    const float* bqkv = (const float*)d_in[2];
    const float* Wout = (const float*)d_in[3];
    const float* bout = (const float*)d_in[4];
    float* out = (float*)d_out;

    float* qkv = nullptr;
    __nv_bfloat16 *xhi, *xlo, *ahi, *alo, *wqh, *wql, *woh, *wol;
    __nv_bfloat16 *qh, *ql, *kh, *kl, *vh, *vl;
    cudaGetSymbolAddress((void**)&qkv,  g_qkv);
    cudaGetSymbolAddress((void**)&xhi,  g_xhi);
    cudaGetSymbolAddress((void**)&xlo,  g_xlo);
    cudaGetSymbolAddress((void**)&ahi,  g_ahi);
    cudaGetSymbolAddress((void**)&alo,  g_alo);
    cudaGetSymbolAddress((void**)&wqh,  g_wqT_hi);
    cudaGetSymbolAddress((void**)&wql,  g_wqT_lo);
    cudaGetSymbolAddress((void**)&woh,  g_woT_hi);
    cudaGetSymbolAddress((void**)&wol,  g_woT_lo);
    cudaGetSymbolAddress((void**)&qh,   g_qh);
    cudaGetSymbolAddress((void**)&ql,   g_ql);
    cudaGetSymbolAddress((void**)&kh,   g_kh);
    cudaGetSymbolAddress((void**)&kl,   g_kl);
    cudaGetSymbolAddress((void**)&vh,   g_vh);
    cudaGetSymbolAddress((void**)&vl,   g_vl);

    cudaFuncSetAttribute(gemm_mma,
                         cudaFuncAttributeMaxDynamicSharedMemorySize, GEMM_SMEM);
    cudaFuncSetAttribute(flash_mma,
                         cudaFuncAttributeMaxDynamicSharedMemorySize, FLASH_SMEM);

    // operand conversions
    cvt_split<<<(ROWS*(size_t)ND/4 + 255)/256, 256>>>(
        (const float4*)x, (uint2*)xhi, (uint2*)xlo);
    cvt_split_T<<<dim3(QKV_COLS/32, ND/32), dim3(32, 8)>>>(Wqkv, wqh, wql, ND, QKV_COLS);
    cvt_split_T<<<dim3(ND/32, ND/32), dim3(32, 8)>>>(Wout, woh, wol, ND, ND);

    // qkv = x @ Wqkv + b_qkv   [8192, 6144]
    gemm_mma<<<dim3(QKV_COLS/128, ROWS/128), 256, GEMM_SMEM>>>(
        xhi, xlo, wqh, wql, bqkv, qkv, ROWS, QKV_COLS, ND);

    // split into per-head bf16 hi/lo
    cvt_qkv<<<ROWS, 256>>>(qkv, (uint2*)qh, (uint2*)ql, (uint2*)kh,
                           (uint2*)kl, (uint2*)vh, (uint2*)vl);

    // attention -> writes proj A-operand (hi/lo) directly
    flash_mma<<<dim3(NS/128, NH, NB), 256, FLASH_SMEM>>>(
        qh, ql, kh, kl, vh, vl, ahi, alo);

    // out = attn @ Wout + b_out
    gemm_mma<<<dim3(ND/128, ROWS/128), 256, GEMM_SMEM>>>(
        ahi, alo, woh, wol, bout, out, ROWS, ND, ND);
}

// round 5
// speedup vs baseline: 2.9905x; 1.0579x over previous
#include <cuda_runtime.h>
#include <cuda_bf16.h>
#include <cstdint>
#include <math.h>

#define NB 4
#define NS 2048
#define ND 2048
#define NH 16
#define NHD 128
#define ROWS (NB*NS)        /* 8192 */
#define QKV_COLS (3*ND)     /* 6144 */

// ---------------- scratch (device globals: allocation-free rule) ----------
__device__ __nv_bfloat16 g_xhi[(size_t)ROWS * ND];
__device__ __nv_bfloat16 g_xlo[(size_t)ROWS * ND];
__device__ __nv_bfloat16 g_ahi[(size_t)ROWS * ND];         // attn out hi
__device__ __nv_bfloat16 g_alo[(size_t)ROWS * ND];         // attn out lo
__device__ __nv_bfloat16 g_wqT_hi[(size_t)QKV_COLS * ND];  // Wqkv^T [6144][2048]
__device__ __nv_bfloat16 g_wqT_lo[(size_t)QKV_COLS * ND];
__device__ __nv_bfloat16 g_woT_hi[(size_t)ND * ND];        // Wout^T [2048][2048]
__device__ __nv_bfloat16 g_woT_lo[(size_t)ND * ND];
// per-head split QKV: [B*H][S][HD]
__device__ __nv_bfloat16 g_qh[(size_t)ROWS * ND];
__device__ __nv_bfloat16 g_ql[(size_t)ROWS * ND];
__device__ __nv_bfloat16 g_kh[(size_t)ROWS * ND];
__device__ __nv_bfloat16 g_kl[(size_t)ROWS * ND];
__device__ __nv_bfloat16 g_vh[(size_t)ROWS * ND];
__device__ __nv_bfloat16 g_vl[(size_t)ROWS * ND];

// ---------------- PTX helpers (baseline features only: sm_80+) ------------
__device__ __forceinline__ uint32_t smem_u32(const void* p) {
    uint32_t a;
    asm("{ .reg .u64 t; cvta.to.shared.u64 t, %1; cvt.u32.u64 %0, t; }"
        : "=r"(a) : "l"(p));
    return a;
}

__device__ __forceinline__ void cpa16(uint32_t s, const void* g) {
    asm volatile("cp.async.cg.shared.global [%0], [%1], 16;" :: "r"(s), "l"(g));
}
#define CP_COMMIT() asm volatile("cp.async.commit_group;" ::: "memory")
#define CP_WAIT(n)  asm volatile("cp.async.wait_group %0;" :: "n"(n) : "memory")

__device__ __forceinline__ void ldsm4(uint32_t* r, uint32_t addr) {
    asm volatile("ldmatrix.sync.aligned.m8n8.x4.shared.b16 {%0,%1,%2,%3}, [%4];"
                 : "=r"(r[0]), "=r"(r[1]), "=r"(r[2]), "=r"(r[3]) : "r"(addr));
}
__device__ __forceinline__ void ldsm4t(uint32_t* r, uint32_t addr) {
    asm volatile("ldmatrix.sync.aligned.m8n8.x4.trans.shared.b16 {%0,%1,%2,%3}, [%4];"
                 : "=r"(r[0]), "=r"(r[1]), "=r"(r[2]), "=r"(r[3]) : "r"(addr));
}

__device__ __forceinline__ void mma16816(float* d, const uint32_t* a,
                                         const uint32_t* b) {
    asm volatile(
        "mma.sync.aligned.m16n8k16.row.col.f32.bf16.bf16.f32 "
        "{%0,%1,%2,%3}, {%4,%5,%6,%7}, {%8,%9}, {%0,%1,%2,%3};"
        : "+f"(d[0]), "+f"(d[1]), "+f"(d[2]), "+f"(d[3])
        : "r"(a[0]), "r"(a[1]), "r"(a[2]), "r"(a[3]), "r"(b[0]), "r"(b[1]));
}

#define PACK2(lo16, hi16) (((uint32_t)(hi16) << 16) | (uint32_t)(lo16))
#define BFU(x) __bfloat16_as_ushort(x)

__device__ __forceinline__ uint32_t split_pair(float a, float b, uint32_t& lo) {
    __nv_bfloat16 h0 = __float2bfloat16(a), h1 = __float2bfloat16(b);
    __nv_bfloat16 e0 = __float2bfloat16(a - __bfloat162float(h0));
    __nv_bfloat16 e1 = __float2bfloat16(b - __bfloat162float(h1));
    lo = PACK2(BFU(e0), BFU(e1));
    return PACK2(BFU(h0), BFU(h1));
}

// ---------------------------------------------------------------------------
// conversion kernels
// ---------------------------------------------------------------------------
__global__ void cvt_split(const float4* __restrict__ in, uint2* __restrict__ hi,
                          uint2* __restrict__ lo)
{
    int i = blockIdx.x * blockDim.x + threadIdx.x;
    float4 v = in[i];
    uint2 uh, ul;
    uh.x = split_pair(v.x, v.y, ul.x);
    uh.y = split_pair(v.z, v.w, ul.y);
    hi[i] = uh;
    lo[i] = ul;
}

// W [K][N] fp32  ->  T [N][K] bf16 hi/lo
__global__ void cvt_split_T(const float* __restrict__ W,
                            __nv_bfloat16* __restrict__ Thi,
                            __nv_bfloat16* __restrict__ Tlo, int K, int N)
{
    __shared__ float tile[32][33];
    int n0 = blockIdx.x * 32, k0 = blockIdx.y * 32;
    int tx = threadIdx.x, ty = threadIdx.y;  // 32 x 8
    #pragma unroll
    for (int r = 0; r < 4; r++)
        tile[ty + r*8][tx] = W[(size_t)(k0 + ty + r*8) * N + n0 + tx];
    __syncthreads();
    #pragma unroll
    for (int r = 0; r < 4; r++) {
        float v = tile[tx][ty + r*8];
        __nv_bfloat16 h = __float2bfloat16(v);
        __nv_bfloat16 l = __float2bfloat16(v - __bfloat162float(h));
        size_t o = (size_t)(n0 + ty + r*8) * K + k0 + tx;
        Thi[o] = h;
        Tlo[o] = l;
    }
}

// ---------------------------------------------------------------------------
// bf16x3 GEMM via mma.sync. EPI=0: fp32 C + bias. EPI=1: split per-head QKV.
// CTA 128x128, BK=32, 8 warps (2m x 4n), 4-stage cp.async, 1 sync per step.
// ---------------------------------------------------------------------------
#define STAGES 4
#define STAGE_BYTES 32768
#define GEMM_SMEM (STAGES * STAGE_BYTES)
#define SWZ(row, kb) ((kb) ^ ((((row) >> 1) & 3) << 4))

__device__ __forceinline__ void issue_stage(
    uint32_t sb_stage, const __nv_bfloat16* __restrict__ Ahi,
    const __nv_bfloat16* __restrict__ Alo,
    const __nv_bfloat16* __restrict__ Bhi,
    const __nv_bfloat16* __restrict__ Blo,
    int rowBase, int colBase, int k0, int K, int t)
{
    #pragma unroll
    for (int u = 0; u < 2; u++) {
        int idx = t + 256*u;
        int row = idx >> 2, chunk = idx & 3;
        uint32_t soff = (uint32_t)(row*64 + SWZ(row, chunk*16));
        size_t ge = (size_t)row * K + k0 + chunk*8;
        cpa16(sb_stage +         soff, Ahi + (size_t)rowBase*K + ge);
        cpa16(sb_stage +  8192 + soff, Alo + (size_t)rowBase*K + ge);
        cpa16(sb_stage + 16384 + soff, Bhi + (size_t)colBase*K + ge);
        cpa16(sb_stage + 24576 + soff, Blo + (size_t)colBase*K + ge);
    }
    CP_COMMIT();
}

template<int EPI>
__global__ __launch_bounds__(256, 1)
void gemm_mma(const __nv_bfloat16* __restrict__ Ahi,
              const __nv_bfloat16* __restrict__ Alo,
              const __nv_bfloat16* __restrict__ Bhi,
              const __nv_bfloat16* __restrict__ Blo,
              const float* __restrict__ bias, float* __restrict__ C,
              __nv_bfloat16* __restrict__ q_h, __nv_bfloat16* __restrict__ q_l,
              __nv_bfloat16* __restrict__ k_h, __nv_bfloat16* __restrict__ k_l,
              __nv_bfloat16* __restrict__ v_h, __nv_bfloat16* __restrict__ v_l,
              int M, int N, int K)
{
    extern __shared__ char sm[];
    const uint32_t sb = smem_u32(sm);

    const int t = threadIdx.x, lane = t & 31, w = t >> 5;
    const int warp_m = w & 1, warp_n = w >> 1;
    const int rowBase = blockIdx.y * 128;
    const int colBase = blockIdx.x * 128;
    const int ksteps  = K >> 5;
    const int mat = lane >> 3, r8 = lane & 7;

    float acc[4][4][4];
    #pragma unroll
    for (int i = 0; i < 4; i++)
        #pragma unroll
        for (int j = 0; j < 4; j++)
            #pragma unroll
            for (int q = 0; q < 4; q++) acc[i][j][q] = 0.f;

    issue_stage(sb,                 Ahi, Alo, Bhi, Blo, rowBase, colBase, 0,  K, t);
    issue_stage(sb +   STAGE_BYTES, Ahi, Alo, Bhi, Blo, rowBase, colBase, 32, K, t);
    issue_stage(sb + 2*STAGE_BYTES, Ahi, Alo, Bhi, Blo, rowBase, colBase, 64, K, t);

    int rowA[4], rowB[2];
    #pragma unroll
    for (int fm = 0; fm < 4; fm++)
        rowA[fm] = warp_m*64 + fm*16 + (mat & 1)*8 + r8;
    #pragma unroll
    for (int fb = 0; fb < 2; fb++)
        rowB[fb] = warp_n*32 + fb*16 + (mat >> 1)*8 + r8;

    for (int i = 0; i < ksteps; i++) {
        CP_WAIT(2);
        __syncthreads();
        // issue next stage early: slot (i+3)%4 was fully read in iter i-1,
        // and the barrier above proves all warps passed that point.
        if (i + 3 < ksteps)
            issue_stage(sb + (uint32_t)((i + 3) & 3) * STAGE_BYTES,
                        Ahi, Alo, Bhi, Blo, rowBase, colBase, (i + 3)*32, K, t);
        else
            CP_COMMIT();   // empty group keeps per-thread accounting uniform

        const uint32_t st = sb + (uint32_t)(i & 3) * STAGE_BYTES;

        #pragma unroll
        for (int ks = 0; ks < 2; ks++) {
            uint32_t ah[4][4], al[4][4], bh[4][2], bl[4][2];
            const int kbA = ks*32 + (mat >> 1)*16;
            const int kbB = ks*32 + (mat & 1)*16;
            #pragma unroll
            for (int fm = 0; fm < 4; fm++) {
                uint32_t off = (uint32_t)(rowA[fm]*64 + SWZ(rowA[fm], kbA));
                ldsm4(ah[fm], st +        off);
                ldsm4(al[fm], st + 8192 + off);
            }
            #pragma unroll
            for (int fb = 0; fb < 2; fb++) {
                uint32_t off = (uint32_t)(rowB[fb]*64 + SWZ(rowB[fb], kbB));
                uint32_t rh[4], rl[4];
                ldsm4(rh, st + 16384 + off);
                ldsm4(rl, st + 24576 + off);
                bh[fb*2+0][0] = rh[0]; bh[fb*2+0][1] = rh[1];
                bh[fb*2+1][0] = rh[2]; bh[fb*2+1][1] = rh[3];
                bl[fb*2+0][0] = rl[0]; bl[fb*2+0][1] = rl[1];
                bl[fb*2+1][0] = rl[2]; bl[fb*2+1][1] = rl[3];
            }
            #pragma unroll
            for (int fm = 0; fm < 4; fm++)
                #pragma unroll
                for (int fn = 0; fn < 4; fn++) {
                    mma16816(acc[fm][fn], ah[fm], bh[fn]);
                    mma16816(acc[fm][fn], ah[fm], bl[fn]);
                    mma16816(acc[fm][fn], al[fm], bh[fn]);
                }
        }
        __syncthreads();
    }

    const int qrow = lane >> 2, qcol = (lane & 3) * 2;
    #pragma unroll
    for (int fn = 0; fn < 4; fn++) {
        const int col = colBase + warp_n*32 + fn*8 + qcol;
        const float b0 = bias[col], b1 = bias[col + 1];
        if (EPI == 0) {
            #pragma unroll
            for (int fm = 0; fm < 4; fm++) {
                const int row0 = rowBase + warp_m*64 + fm*16 + qrow;
                float2 v0 = make_float2(acc[fm][fn][0] + b0, acc[fm][fn][1] + b1);
                float2 v1 = make_float2(acc[fm][fn][2] + b0, acc[fm][fn][3] + b1);
                *(float2*)&C[(size_t)row0 * N + col]       = v0;
                *(float2*)&C[(size_t)(row0 + 8) * N + col] = v1;
            }
        } else {
            const int sel = col >> 11, hh = (col >> 7) & 15, hd = col & 127;
            __nv_bfloat16* dh = (sel == 0) ? q_h : (sel == 1) ? k_h : v_h;
            __nv_bfloat16* dl = (sel == 0) ? q_l : (sel == 1) ? k_l : v_l;
            #pragma unroll
            for (int fm = 0; fm < 4; fm++) {
                const int r0 = rowBase + warp_m*64 + fm*16 + qrow;
                #pragma unroll
                for (int rr = 0; rr < 2; rr++) {
                    const int r = r0 + rr*8;
                    float va = acc[fm][fn][rr*2+0] + b0;
                    float vb = acc[fm][fn][rr*2+1] + b1;
                    uint32_t lo, hi = split_pair(va, vb, lo);
                    size_t o = (((size_t)((r >> 11)*NH + hh) * NS +
                                 (r & 2047)) * NHD + hd);
                    *(uint32_t*)&dh[o] = hi;
                    *(uint32_t*)&dl[o] = lo;
                }
            }
        }
    }
}

// ---------------------------------------------------------------------------
// Flash attention via mma.sync, bf16x3 emulation, ALiBi + causal.
// CTA: 128 q rows x (h, b). 8 warps x 16 rows. K-tiles of 64 keys.
// Q held in registers; 3 KV stages of 64KB (K hi|K lo|V hi|V lo), Q staged
// initially in slot 2. Single __syncthreads per k-tile.
// ---------------------------------------------------------------------------
#define FLASH_SMEM (3*65536)   /* 196608 */
#define SWZF(row, chunk) (((chunk) ^ ((row) & 7)) << 4)

__device__ __forceinline__ void flash_load_kv(
    uint32_t st, const __nv_bfloat16* __restrict__ kh,
    const __nv_bfloat16* __restrict__ kl,
    const __nv_bfloat16* __restrict__ vh,
    const __nv_bfloat16* __restrict__ vl,
    size_t hb, int kt, int t)
{
    #pragma unroll
    for (int u = 0; u < 4; u++) {
        int idx = t + 256*u;                 // 0..1023
        int row = idx >> 4, chunk = idx & 15;
        uint32_t soff = (uint32_t)(row*256 + SWZF(row, chunk));
        size_t g = hb + (size_t)(kt*64 + row)*NHD + chunk*8;
        cpa16(st +         soff, kh + g);
        cpa16(st + 16384 + soff, kl + g);
        cpa16(st + 32768 + soff, vh + g);
        cpa16(st + 49152 + soff, vl + g);
    }
    CP_COMMIT();
}

__global__ __launch_bounds__(256, 1)
void flash_mma(const __nv_bfloat16* __restrict__ qh,
               const __nv_bfloat16* __restrict__ ql,
               const __nv_bfloat16* __restrict__ kh,
               const __nv_bfloat16* __restrict__ kl,
               const __nv_bfloat16* __restrict__ vh,
               const __nv_bfloat16* __restrict__ vl,
               __nv_bfloat16* __restrict__ ahi,
               __nv_bfloat16* __restrict__ alo)
{
    extern __shared__ char sm[];
    const uint32_t sb = smem_u32(sm);
    const uint32_t qst = sb + 2*65536;       // Q staging = slot 2

    const int qt = blockIdx.x, h = blockIdx.y, b = blockIdx.z;
    const int t = threadIdx.x, lane = t & 31, w = t >> 5;
    const size_t hb = (size_t)(b*NH + h) * NS * NHD;

    const float scale = 0.08838834764831845f;          // 1/sqrt(128)
    const float slope = exp2f(-0.5f * (float)(h + 1)); // ALiBi, H=16
    const int r8 = lane & 7, m01 = (lane >> 3) & 1, m2 = lane >> 4;
    const int qr = lane >> 2, qc = (lane & 3) * 2;
    const int rg0 = qt*128 + w*16 + qr;                // global q row (c0/c1)

    // stage Q into slot 2
    #pragma unroll
    for (int u = 0; u < 8; u++) {
        int idx = t + 256*u;                 // 0..2047
        int row = idx >> 4, chunk = idx & 15;
        uint32_t soff = (uint32_t)(row*256 + SWZF(row, chunk));
        size_t g = hb + (size_t)(qt*128 + row)*NHD + chunk*8;
        cpa16(qst +         soff, qh + g);
        cpa16(qst + 32768 + soff, ql + g);
    }
    CP_COMMIT();                             // group: Q
    flash_load_kv(sb,         kh, kl, vh, vl, hb, 0, t);   // group: KV0
    flash_load_kv(sb + 65536, kh, kl, vh, vl, hb, 1, t);   // group: KV1

    CP_WAIT(2);                              // Q complete
    __syncthreads();

    // Q fragments -> registers (per warp: its own 16 rows, all 128 hd)
    uint32_t fqh[8][4], fql[8][4];
    {
        const int qrow = w*16 + m01*8 + r8;
        #pragma unroll
        for (int kc = 0; kc < 8; kc++) {
            uint32_t qa = qst + (uint32_t)(qrow*256 + SWZF(qrow, kc*2 + m2));
            ldsm4(fqh[kc], qa);
            ldsm4(fql[kc], qa + 32768);
        }
    }

    float m0 = -1e30f, m1 = -1e30f, l0 = 0.f, l1 = 0.f;
    float acc_o[16][4];
    #pragma unroll
    for (int i = 0; i < 16; i++)
        #pragma unroll
        for (int j = 0; j < 4; j++) acc_o[i][j] = 0.f;

    const int nkt = 2*qt + 2;
    for (int kt = 0; kt < nkt; kt++) {
        CP_WAIT(1);
        __syncthreads();
        // slot (kt+2)%3 was fully read in iter kt-1 (or was the Q staging,
        // whose reads precede the first barrier) — safe to refill now.
        if (kt + 2 < nkt)
            flash_load_kv(sb + (uint32_t)((kt + 2) % 3)*65536,
                          kh, kl, vh, vl, hb, kt + 2, t);
        else
            CP_COMMIT();

        const uint32_t st = sb + (uint32_t)(kt % 3)*65536;

        // ---- S = Q K^T (3-term) ----
        float s_[8][4];
        #pragma unroll
        for (int i = 0; i < 8; i++)
            #pragma unroll
            for (int j = 0; j < 4; j++) s_[i][j] = 0.f;

        #pragma unroll
        for (int kc = 0; kc < 8; kc++) {
            #pragma unroll
            for (int ng = 0; ng < 4; ng++) {
                int krow = ng*16 + m2*8 + r8;
                int kchk = kc*2 + m01;
                uint32_t ka = st + (uint32_t)(krow*256 + SWZF(krow, kchk));
                uint32_t rh[4], rl[4];
                ldsm4(rh, ka);
                ldsm4(rl, ka + 16384);
                mma16816(s_[ng*2+0], fqh[kc], rh);
                mma16816(s_[ng*2+0], fqh[kc], rl);
                mma16816(s_[ng*2+0], fql[kc], rh);
                mma16816(s_[ng*2+1], fqh[kc], rh+2);
                mma16816(s_[ng*2+1], fqh[kc], rl+2);
                mma16816(s_[ng*2+1], fql[kc], rh+2);
            }
        }

        // ---- scale + alibi + causal mask, row max ----
        const bool diag = (kt >= 2*qt);
        float tm0 = -1e30f, tm1 = -1e30f;
        #pragma unroll
        for (int nt = 0; nt < 8; nt++) {
            #pragma unroll
            for (int jj = 0; jj < 2; jj++) {
                int col = kt*64 + nt*8 + qc + jj;
                float ab = slope * (float)(col - (NS - 1));
                float v0 = fmaf(s_[nt][jj],     scale, ab);
                float v1 = fmaf(s_[nt][2 + jj], scale, ab);
                if (diag) {
                    if (col > rg0)     v0 = -1e30f;
                    if (col > rg0 + 8) v1 = -1e30f;
                }
                s_[nt][jj]     = v0;
                s_[nt][2 + jj] = v1;
                tm0 = fmaxf(tm0, v0);
                tm1 = fmaxf(tm1, v1);
            }
        }
        tm0 = fmaxf(tm0, __shfl_xor_sync(0xffffffffu, tm0, 1));
        tm0 = fmaxf(tm0, __shfl_xor_sync(0xffffffffu, tm0, 2));
        tm1 = fmaxf(tm1, __shfl_xor_sync(0xffffffffu, tm1, 1));
        tm1 = fmaxf(tm1, __shfl_xor_sync(0xffffffffu, tm1, 2));

        float mn0 = fmaxf(m0, tm0), mn1 = fmaxf(m1, tm1);
        float c0 = __expf(m0 - mn0), c1 = __expf(m1 - mn1);
        m0 = mn0; m1 = mn1;
        l0 *= c0; l1 *= c1;
        #pragma unroll
        for (int i = 0; i < 16; i++) {
            acc_o[i][0] *= c0; acc_o[i][1] *= c0;
            acc_o[i][2] *= c1; acc_o[i][3] *= c1;
        }
        #pragma unroll
        for (int nt = 0; nt < 8; nt++) {
            float p0 = __expf(s_[nt][0] - m0);
            float p1 = __expf(s_[nt][1] - m0);
            float p2 = __expf(s_[nt][2] - m1);
            float p3 = __expf(s_[nt][3] - m1);
            l0 += p0 + p1;
            l1 += p2 + p3;
            s_[nt][0] = p0; s_[nt][1] = p1; s_[nt][2] = p2; s_[nt][3] = p3;
        }

        // ---- O += P V (3-term) ----
        #pragma unroll
        for (int kc = 0; kc < 4; kc++) {
            uint32_t ph[4], pl[4];
            {
                const float* pa = s_[2*kc];
                const float* pb = s_[2*kc + 1];
                ph[0] = split_pair(pa[0], pa[1], pl[0]);
                ph[1] = split_pair(pa[2], pa[3], pl[1]);
                ph[2] = split_pair(pb[0], pb[1], pl[2]);
                ph[3] = split_pair(pb[2], pb[3], pl[3]);
            }
            #pragma unroll
            for (int ng = 0; ng < 8; ng++) {
                int vrow = kc*16 + m01*8 + r8;
                int vchk = ng*2 + m2;
                uint32_t va = st + 32768 + (uint32_t)(vrow*256 + SWZF(vrow, vchk));
                uint32_t wh[4], wl[4];
                ldsm4t(wh, va);
                ldsm4t(wl, va + 16384);
                mma16816(acc_o[ng*2+0], ph, wh);
                mma16816(acc_o[ng*2+0], ph, wl);
                mma16816(acc_o[ng*2+0], pl, wh);
                mma16816(acc_o[ng*2+1], ph, wh+2);
                mma16816(acc_o[ng*2+1], ph, wl+2);
                mma16816(acc_o[ng*2+1], pl, wh+2);
            }
        }
    }

    // ---- finalize ----
    l0 += __shfl_xor_sync(0xffffffffu, l0, 1);
    l0 += __shfl_xor_sync(0xffffffffu, l0, 2);
    l1 += __shfl_xor_sync(0xffffffffu, l1, 1);
    l1 += __shfl_xor_sync(0xffffffffu, l1, 2);
    const float inv0 = 1.f / l0, inv1 = 1.f / l1;

    const size_t row0 = (size_t)(b*NS) + qt*128 + w*16 + qr;
    #pragma unroll
    for (int nt = 0; nt < 16; nt++) {
        int col = h*NHD + nt*8 + qc;
        uint32_t lo0, lo1;
        uint32_t hi0 = split_pair(acc_o[nt][0]*inv0, acc_o[nt][1]*inv0, lo0);
        uint32_t hi1 = split_pair(acc_o[nt][2]*inv1, acc_o[nt][3]*inv1, lo1);
        *(uint32_t*)&ahi[row0 * ND + col]       = hi0;
        *(uint32_t*)&alo[row0 * ND + col]       = lo0;
        *(uint32_t*)&ahi[(row0 + 8) * ND + col] = hi1;
        *(uint32_t*)&alo[(row0 + 8) * ND + col] = lo1;
    }
}

// ---------------------------------------------------------------------------
extern "C" void kernel_launch(void* const* d_in, const int* in_sizes, int n_in,
                              void* d_out, int out_size)
{
    const float* x    = (const float*)d_in[0];
    const float* Wqkv = (const float*)d_in[1];
    const float* bqkv = (const float*)d_in[2];
    const float* Wout = (const float*)d_in[3];
    const float* bout = (const float*)d_in[4];
    float* out = (float*)d_out;

    __nv_bfloat16 *xhi, *xlo, *ahi, *alo, *wqh, *wql, *woh, *wol;
    __nv_bfloat16 *qh, *ql, *kh, *kl, *vh, *vl;
    cudaGetSymbolAddress((void**)&xhi,  g_xhi);
    cudaGetSymbolAddress((void**)&xlo,  g_xlo);
    cudaGetSymbolAddress((void**)&ahi,  g_ahi);
    cudaGetSymbolAddress((void**)&alo,  g_alo);
    cudaGetSymbolAddress((void**)&wqh,  g_wqT_hi);
    cudaGetSymbolAddress((void**)&wql,  g_wqT_lo);
    cudaGetSymbolAddress((void**)&woh,  g_woT_hi);
    cudaGetSymbolAddress((void**)&wol,  g_woT_lo);
    cudaGetSymbolAddress((void**)&qh,   g_qh);
    cudaGetSymbolAddress((void**)&ql,   g_ql);
    cudaGetSymbolAddress((void**)&kh,   g_kh);
    cudaGetSymbolAddress((void**)&kl,   g_kl);
    cudaGetSymbolAddress((void**)&vh,   g_vh);
    cudaGetSymbolAddress((void**)&vl,   g_vl);

    cudaFuncSetAttribute(gemm_mma<0>,
                         cudaFuncAttributeMaxDynamicSharedMemorySize, GEMM_SMEM);
    cudaFuncSetAttribute(gemm_mma<1>,
                         cudaFuncAttributeMaxDynamicSharedMemorySize, GEMM_SMEM);
    cudaFuncSetAttribute(flash_mma,
                         cudaFuncAttributeMaxDynamicSharedMemorySize, FLASH_SMEM);

    // operand conversions
    cvt_split<<<(ROWS*(size_t)ND/4 + 255)/256, 256>>>(
        (const float4*)x, (uint2*)xhi, (uint2*)xlo);
    cvt_split_T<<<dim3(QKV_COLS/32, ND/32), dim3(32, 8)>>>(Wqkv, wqh, wql, ND, QKV_COLS);
    cvt_split_T<<<dim3(ND/32, ND/32), dim3(32, 8)>>>(Wout, woh, wol, ND, ND);

    // qkv = x @ Wqkv + b_qkv, written directly as split per-head q/k/v
    gemm_mma<1><<<dim3(QKV_COLS/128, ROWS/128), 256, GEMM_SMEM>>>(
        xhi, xlo, wqh, wql, bqkv, nullptr,
        qh, ql, kh, kl, vh, vl, ROWS, QKV_COLS, ND);

    // attention -> writes proj A-operand (hi/lo) directly
    flash_mma<<<dim3(NS/128, NH, NB), 256, FLASH_SMEM>>>(
        qh, ql, kh, kl, vh, vl, ahi, alo);

    // out = attn @ Wout + b_out
    gemm_mma<0><<<dim3(ND/128, ROWS/128), 256, GEMM_SMEM>>>(
        ahi, alo, woh, wol, bout, out,
        nullptr, nullptr, nullptr, nullptr, nullptr, nullptr, ROWS, ND, ND);
}

// round 6
// speedup vs baseline: 3.0419x; 1.0172x over previous
#include <cuda_runtime.h>
#include <cuda_bf16.h>
#include <cstdint>
#include <math.h>

#define NB 4
#define NS 2048
#define ND 2048
#define NH 16
#define NHD 128
#define ROWS (NB*NS)        /* 8192 */
#define QKV_COLS (3*ND)     /* 6144 */

// ---------------- scratch (device globals: allocation-free rule) ----------
__device__ __nv_bfloat16 g_xhi[(size_t)ROWS * ND];
__device__ __nv_bfloat16 g_xlo[(size_t)ROWS * ND];
__device__ __nv_bfloat16 g_ahi[(size_t)ROWS * ND];         // attn out hi
__device__ __nv_bfloat16 g_alo[(size_t)ROWS * ND];         // attn out lo
__device__ __nv_bfloat16 g_wqT_hi[(size_t)QKV_COLS * ND];  // Wqkv^T [6144][2048]
__device__ __nv_bfloat16 g_wqT_lo[(size_t)QKV_COLS * ND];
__device__ __nv_bfloat16 g_woT_hi[(size_t)ND * ND];        // Wout^T [2048][2048]
__device__ __nv_bfloat16 g_woT_lo[(size_t)ND * ND];
// per-head split QKV: [B*H][S][HD]
__device__ __nv_bfloat16 g_qh[(size_t)ROWS * ND];
__device__ __nv_bfloat16 g_ql[(size_t)ROWS * ND];
__device__ __nv_bfloat16 g_kh[(size_t)ROWS * ND];
__device__ __nv_bfloat16 g_kl[(size_t)ROWS * ND];
__device__ __nv_bfloat16 g_vh[(size_t)ROWS * ND];
__device__ __nv_bfloat16 g_vl[(size_t)ROWS * ND];

// ---------------- PTX helpers (baseline features only: sm_80+) ------------
__device__ __forceinline__ uint32_t smem_u32(const void* p) {
    uint32_t a;
    asm("{ .reg .u64 t; cvta.to.shared.u64 t, %1; cvt.u32.u64 %0, t; }"
        : "=r"(a) : "l"(p));
    return a;
}

__device__ __forceinline__ void cpa16(uint32_t s, const void* g) {
    asm volatile("cp.async.cg.shared.global [%0], [%1], 16;" :: "r"(s), "l"(g));
}
#define CP_COMMIT() asm volatile("cp.async.commit_group;" ::: "memory")
#define CP_WAIT(n)  asm volatile("cp.async.wait_group %0;" :: "n"(n) : "memory")

__device__ __forceinline__ void ldsm4(uint32_t* r, uint32_t addr) {
    asm volatile("ldmatrix.sync.aligned.m8n8.x4.shared.b16 {%0,%1,%2,%3}, [%4];"
                 : "=r"(r[0]), "=r"(r[1]), "=r"(r[2]), "=r"(r[3]) : "r"(addr));
}
__device__ __forceinline__ void ldsm4t(uint32_t* r, uint32_t addr) {
    asm volatile("ldmatrix.sync.aligned.m8n8.x4.trans.shared.b16 {%0,%1,%2,%3}, [%4];"
                 : "=r"(r[0]), "=r"(r[1]), "=r"(r[2]), "=r"(r[3]) : "r"(addr));
}

__device__ __forceinline__ void mma16816(float* d, const uint32_t* a,
                                         const uint32_t* b) {
    asm volatile(
        "mma.sync.aligned.m16n8k16.row.col.f32.bf16.bf16.f32 "
        "{%0,%1,%2,%3}, {%4,%5,%6,%7}, {%8,%9}, {%0,%1,%2,%3};"
        : "+f"(d[0]), "+f"(d[1]), "+f"(d[2]), "+f"(d[3])
        : "r"(a[0]), "r"(a[1]), "r"(a[2]), "r"(a[3]), "r"(b[0]), "r"(b[1]));
}

#define PACK2(lo16, hi16) (((uint32_t)(hi16) << 16) | (uint32_t)(lo16))
#define BFU(x) __bfloat16_as_ushort(x)

__device__ __forceinline__ uint32_t split_pair(float a, float b, uint32_t& lo) {
    __nv_bfloat16 h0 = __float2bfloat16(a), h1 = __float2bfloat16(b);
    __nv_bfloat16 e0 = __float2bfloat16(a - __bfloat162float(h0));
    __nv_bfloat16 e1 = __float2bfloat16(b - __bfloat162float(h1));
    lo = PACK2(BFU(e0), BFU(e1));
    return PACK2(BFU(h0), BFU(h1));
}

// ---------------------------------------------------------------------------
// conversion kernels
// ---------------------------------------------------------------------------
__global__ void cvt_split(const float4* __restrict__ in, uint2* __restrict__ hi,
                          uint2* __restrict__ lo)
{
    int i = blockIdx.x * blockDim.x + threadIdx.x;
    float4 v = in[i];
    uint2 uh, ul;
    uh.x = split_pair(v.x, v.y, ul.x);
    uh.y = split_pair(v.z, v.w, ul.y);
    hi[i] = uh;
    lo[i] = ul;
}

// W [K][N] fp32  ->  T [N][K] bf16 hi/lo
__global__ void cvt_split_T(const float* __restrict__ W,
                            __nv_bfloat16* __restrict__ Thi,
                            __nv_bfloat16* __restrict__ Tlo, int K, int N)
{
    __shared__ float tile[32][33];
    int n0 = blockIdx.x * 32, k0 = blockIdx.y * 32;
    int tx = threadIdx.x, ty = threadIdx.y;  // 32 x 8
    #pragma unroll
    for (int r = 0; r < 4; r++)
        tile[ty + r*8][tx] = W[(size_t)(k0 + ty + r*8) * N + n0 + tx];
    __syncthreads();
    #pragma unroll
    for (int r = 0; r < 4; r++) {
        float v = tile[tx][ty + r*8];
        __nv_bfloat16 h = __float2bfloat16(v);
        __nv_bfloat16 l = __float2bfloat16(v - __bfloat162float(h));
        size_t o = (size_t)(n0 + ty + r*8) * K + k0 + tx;
        Thi[o] = h;
        Tlo[o] = l;
    }
}

// ---------------------------------------------------------------------------
// bf16x3 GEMM via mma.sync. EPI=0: fp32 C + bias. EPI=1: split per-head QKV.
// CTA 128x256, BK=32, 8 warps (2m x 4n), warp tile 64x64, 4-stage cp.async.
// Stage: Ahi 8KB | Alo 8KB | Bhi 16KB | Blo 16KB = 48KB.
// ---------------------------------------------------------------------------
#define STAGES 4
#define STAGE_BYTES 49152
#define GEMM_SMEM (STAGES * STAGE_BYTES)   /* 192 KB */
#define SWZ(row, kb) ((kb) ^ ((((row) >> 1) & 3) << 4))

__device__ __forceinline__ void issue_stage(
    uint32_t sb_stage, const __nv_bfloat16* __restrict__ Ahi,
    const __nv_bfloat16* __restrict__ Alo,
    const __nv_bfloat16* __restrict__ Bhi,
    const __nv_bfloat16* __restrict__ Blo,
    int rowBase, int colBase, int k0, int K, int t)
{
    // A: 128 rows x 64 B (hi + lo)
    #pragma unroll
    for (int u = 0; u < 2; u++) {
        int idx = t + 256*u;
        int row = idx >> 2, chunk = idx & 3;
        uint32_t soff = (uint32_t)(row*64 + SWZ(row, chunk*16));
        size_t ge = (size_t)(rowBase + row) * K + k0 + chunk*8;
        cpa16(sb_stage +        soff, Ahi + ge);
        cpa16(sb_stage + 8192 + soff, Alo + ge);
    }
    // B: 256 rows x 64 B (hi + lo)
    #pragma unroll
    for (int u = 0; u < 4; u++) {
        int idx = t + 256*u;
        int row = idx >> 2, chunk = idx & 3;
        uint32_t soff = (uint32_t)(row*64 + SWZ(row, chunk*16));
        size_t ge = (size_t)(colBase + row) * K + k0 + chunk*8;
        cpa16(sb_stage + 16384 + soff, Bhi + ge);
        cpa16(sb_stage + 32768 + soff, Blo + ge);
    }
    CP_COMMIT();
}

template<int EPI>
__global__ __launch_bounds__(256, 1)
void gemm_mma(const __nv_bfloat16* __restrict__ Ahi,
              const __nv_bfloat16* __restrict__ Alo,
              const __nv_bfloat16* __restrict__ Bhi,
              const __nv_bfloat16* __restrict__ Blo,
              const float* __restrict__ bias, float* __restrict__ C,
              __nv_bfloat16* __restrict__ q_h, __nv_bfloat16* __restrict__ q_l,
              __nv_bfloat16* __restrict__ k_h, __nv_bfloat16* __restrict__ k_l,
              __nv_bfloat16* __restrict__ v_h, __nv_bfloat16* __restrict__ v_l,
              int M, int N, int K)
{
    extern __shared__ char sm[];
    const uint32_t sb = smem_u32(sm);

    const int t = threadIdx.x, lane = t & 31, w = t >> 5;
    const int warp_m = w & 1, warp_n = w >> 1;   // 2 x 4
    const int rowBase = blockIdx.y * 128;
    const int colBase = blockIdx.x * 256;
    const int ksteps  = K >> 5;
    const int mat = lane >> 3, r8 = lane & 7;

    float acc[4][8][4];
    #pragma unroll
    for (int i = 0; i < 4; i++)
        #pragma unroll
        for (int j = 0; j < 8; j++)
            #pragma unroll
            for (int q = 0; q < 4; q++) acc[i][j][q] = 0.f;

    issue_stage(sb,                 Ahi, Alo, Bhi, Blo, rowBase, colBase, 0,  K, t);
    issue_stage(sb +   STAGE_BYTES, Ahi, Alo, Bhi, Blo, rowBase, colBase, 32, K, t);
    issue_stage(sb + 2*STAGE_BYTES, Ahi, Alo, Bhi, Blo, rowBase, colBase, 64, K, t);

    int rowA[4], rowB[4];
    #pragma unroll
    for (int fm = 0; fm < 4; fm++)
        rowA[fm] = warp_m*64 + fm*16 + (mat & 1)*8 + r8;
    #pragma unroll
    for (int fb = 0; fb < 4; fb++)
        rowB[fb] = warp_n*64 + fb*16 + (mat >> 1)*8 + r8;

    for (int i = 0; i < ksteps; i++) {
        CP_WAIT(2);
        __syncthreads();
        // issue next stage early: slot (i+3)%4 was fully read in iter i-1,
        // and the barrier above proves all warps passed that point.
        if (i + 3 < ksteps)
            issue_stage(sb + (uint32_t)((i + 3) & 3) * STAGE_BYTES,
                        Ahi, Alo, Bhi, Blo, rowBase, colBase, (i + 3)*32, K, t);
        else
            CP_COMMIT();   // empty group keeps per-thread accounting uniform

        const uint32_t st = sb + (uint32_t)(i & 3) * STAGE_BYTES;

        #pragma unroll
        for (int ks = 0; ks < 2; ks++) {
            uint32_t ah[4][4], al[4][4];
            const int kbA = ks*32 + (mat >> 1)*16;
            const int kbB = ks*32 + (mat & 1)*16;
            #pragma unroll
            for (int fm = 0; fm < 4; fm++) {
                uint32_t off = (uint32_t)(rowA[fm]*64 + SWZ(rowA[fm], kbA));
                ldsm4(ah[fm], st +        off);
                ldsm4(al[fm], st + 8192 + off);
            }
            #pragma unroll
            for (int fb = 0; fb < 4; fb++) {
                uint32_t off = (uint32_t)(rowB[fb]*64 + SWZ(rowB[fb], kbB));
                uint32_t rh[4], rl[4];
                ldsm4(rh, st + 16384 + off);
                ldsm4(rl, st + 32768 + off);
                #pragma unroll
                for (int fm = 0; fm < 4; fm++) {
                    mma16816(acc[fm][2*fb+0], ah[fm], rh);
                    mma16816(acc[fm][2*fb+0], ah[fm], rl);
                    mma16816(acc[fm][2*fb+0], al[fm], rh);
                    mma16816(acc[fm][2*fb+1], ah[fm], rh+2);
                    mma16816(acc[fm][2*fb+1], ah[fm], rl+2);
                    mma16816(acc[fm][2*fb+1], al[fm], rh+2);
                }
            }
        }
        __syncthreads();
    }

    const int qrow = lane >> 2, qcol = (lane & 3) * 2;
    #pragma unroll
    for (int fn = 0; fn < 8; fn++) {
        const int col = colBase + warp_n*64 + fn*8 + qcol;
        const float b0 = bias[col], b1 = bias[col + 1];
        if (EPI == 0) {
            #pragma unroll
            for (int fm = 0; fm < 4; fm++) {
                const int row0 = rowBase + warp_m*64 + fm*16 + qrow;
                float2 v0 = make_float2(acc[fm][fn][0] + b0, acc[fm][fn][1] + b1);
                float2 v1 = make_float2(acc[fm][fn][2] + b0, acc[fm][fn][3] + b1);
                *(float2*)&C[(size_t)row0 * N + col]       = v0;
                *(float2*)&C[(size_t)(row0 + 8) * N + col] = v1;
            }
        } else {
            const int sel = col >> 11, hh = (col >> 7) & 15, hd = col & 127;
            __nv_bfloat16* dh = (sel == 0) ? q_h : (sel == 1) ? k_h : v_h;
            __nv_bfloat16* dl = (sel == 0) ? q_l : (sel == 1) ? k_l : v_l;
            #pragma unroll
            for (int fm = 0; fm < 4; fm++) {
                const int r0 = rowBase + warp_m*64 + fm*16 + qrow;
                #pragma unroll
                for (int rr = 0; rr < 2; rr++) {
                    const int r = r0 + rr*8;
                    float va = acc[fm][fn][rr*2+0] + b0;
                    float vb = acc[fm][fn][rr*2+1] + b1;
                    uint32_t lo, hi = split_pair(va, vb, lo);
                    size_t o = (((size_t)((r >> 11)*NH + hh) * NS +
                                 (r & 2047)) * NHD + hd);
                    *(uint32_t*)&dh[o] = hi;
                    *(uint32_t*)&dl[o] = lo;
                }
            }
        }
    }
}

// ---------------------------------------------------------------------------
// Flash attention via mma.sync, bf16x3 emulation, ALiBi + causal.
// (unchanged from R5: Q register-resident, 3 KV stages, 1 sync per k-tile)
// ---------------------------------------------------------------------------
#define FLASH_SMEM (3*65536)   /* 196608 */
#define SWZF(row, chunk) (((chunk) ^ ((row) & 7)) << 4)

__device__ __forceinline__ void flash_load_kv(
    uint32_t st, const __nv_bfloat16* __restrict__ kh,
    const __nv_bfloat16* __restrict__ kl,
    const __nv_bfloat16* __restrict__ vh,
    const __nv_bfloat16* __restrict__ vl,
    size_t hb, int kt, int t)
{
    #pragma unroll
    for (int u = 0; u < 4; u++) {
        int idx = t + 256*u;                 // 0..1023
        int row = idx >> 4, chunk = idx & 15;
        uint32_t soff = (uint32_t)(row*256 + SWZF(row, chunk));
        size_t g = hb + (size_t)(kt*64 + row)*NHD + chunk*8;
        cpa16(st +         soff, kh + g);
        cpa16(st + 16384 + soff, kl + g);
        cpa16(st + 32768 + soff, vh + g);
        cpa16(st + 49152 + soff, vl + g);
    }
    CP_COMMIT();
}

__global__ __launch_bounds__(256, 1)
void flash_mma(const __nv_bfloat16* __restrict__ qh,
               const __nv_bfloat16* __restrict__ ql,
               const __nv_bfloat16* __restrict__ kh,
               const __nv_bfloat16* __restrict__ kl,
               const __nv_bfloat16* __restrict__ vh,
               const __nv_bfloat16* __restrict__ vl,
               __nv_bfloat16* __restrict__ ahi,
               __nv_bfloat16* __restrict__ alo)
{
    extern __shared__ char sm[];
    const uint32_t sb = smem_u32(sm);
    const uint32_t qst = sb + 2*65536;       // Q staging = slot 2

    const int qt = blockIdx.x, h = blockIdx.y, b = blockIdx.z;
    const int t = threadIdx.x, lane = t & 31, w = t >> 5;
    const size_t hb = (size_t)(b*NH + h) * NS * NHD;

    const float scale = 0.08838834764831845f;          // 1/sqrt(128)
    const float slope = exp2f(-0.5f * (float)(h + 1)); // ALiBi, H=16
    const int r8 = lane & 7, m01 = (lane >> 3) & 1, m2 = lane >> 4;
    const int qr = lane >> 2, qc = (lane & 3) * 2;
    const int rg0 = qt*128 + w*16 + qr;                // global q row (c0/c1)

    // stage Q into slot 2
    #pragma unroll
    for (int u = 0; u < 8; u++) {
        int idx = t + 256*u;                 // 0..2047
        int row = idx >> 4, chunk = idx & 15;
        uint32_t soff = (uint32_t)(row*256 + SWZF(row, chunk));
        size_t g = hb + (size_t)(qt*128 + row)*NHD + chunk*8;
        cpa16(qst +         soff, qh + g);
        cpa16(qst + 32768 + soff, ql + g);
    }
    CP_COMMIT();                             // group: Q
    flash_load_kv(sb,         kh, kl, vh, vl, hb, 0, t);   // group: KV0
    flash_load_kv(sb + 65536, kh, kl, vh, vl, hb, 1, t);   // group: KV1

    CP_WAIT(2);                              // Q complete
    __syncthreads();

    // Q fragments -> registers (per warp: its own 16 rows, all 128 hd)
    uint32_t fqh[8][4], fql[8][4];
    {
        const int qrow = w*16 + m01*8 + r8;
        #pragma unroll
        for (int kc = 0; kc < 8; kc++) {
            uint32_t qa = qst + (uint32_t)(qrow*256 + SWZF(qrow, kc*2 + m2));
            ldsm4(fqh[kc], qa);
            ldsm4(fql[kc], qa + 32768);
        }
    }

    float m0 = -1e30f, m1 = -1e30f, l0 = 0.f, l1 = 0.f;
    float acc_o[16][4];
    #pragma unroll
    for (int i = 0; i < 16; i++)
        #pragma unroll
        for (int j = 0; j < 4; j++) acc_o[i][j] = 0.f;

    const int nkt = 2*qt + 2;
    for (int kt = 0; kt < nkt; kt++) {
        CP_WAIT(1);
        __syncthreads();
        // slot (kt+2)%3 was fully read in iter kt-1 (or was the Q staging,
        // whose reads precede the first barrier) — safe to refill now.
        if (kt + 2 < nkt)
            flash_load_kv(sb + (uint32_t)((kt + 2) % 3)*65536,
                          kh, kl, vh, vl, hb, kt + 2, t);
        else
            CP_COMMIT();

        const uint32_t st = sb + (uint32_t)(kt % 3)*65536;

        // ---- S = Q K^T (3-term) ----
        float s_[8][4];
        #pragma unroll
        for (int i = 0; i < 8; i++)
            #pragma unroll
            for (int j = 0; j < 4; j++) s_[i][j] = 0.f;

        #pragma unroll
        for (int kc = 0; kc < 8; kc++) {
            #pragma unroll
            for (int ng = 0; ng < 4; ng++) {
                int krow = ng*16 + m2*8 + r8;
                int kchk = kc*2 + m01;
                uint32_t ka = st + (uint32_t)(krow*256 + SWZF(krow, kchk));
                uint32_t rh[4], rl[4];
                ldsm4(rh, ka);
                ldsm4(rl, ka + 16384);
                mma16816(s_[ng*2+0], fqh[kc], rh);
                mma16816(s_[ng*2+0], fqh[kc], rl);
                mma16816(s_[ng*2+0], fql[kc], rh);
                mma16816(s_[ng*2+1], fqh[kc], rh+2);
                mma16816(s_[ng*2+1], fqh[kc], rl+2);
                mma16816(s_[ng*2+1], fql[kc], rh+2);
            }
        }

        // ---- scale + alibi + causal mask, row max ----
        const bool diag = (kt >= 2*qt);
        float tm0 = -1e30f, tm1 = -1e30f;
        #pragma unroll
        for (int nt = 0; nt < 8; nt++) {
            #pragma unroll
            for (int jj = 0; jj < 2; jj++) {
                int col = kt*64 + nt*8 + qc + jj;
                float ab = slope * (float)(col - (NS - 1));
                float v0 = fmaf(s_[nt][jj],     scale, ab);
                float v1 = fmaf(s_[nt][2 + jj], scale, ab);
                if (diag) {
                    if (col > rg0)     v0 = -1e30f;
                    if (col > rg0 + 8) v1 = -1e30f;
                }
                s_[nt][jj]     = v0;
                s_[nt][2 + jj] = v1;
                tm0 = fmaxf(tm0, v0);
                tm1 = fmaxf(tm1, v1);
            }
        }
        tm0 = fmaxf(tm0, __shfl_xor_sync(0xffffffffu, tm0, 1));
        tm0 = fmaxf(tm0, __shfl_xor_sync(0xffffffffu, tm0, 2));
        tm1 = fmaxf(tm1, __shfl_xor_sync(0xffffffffu, tm1, 1));
        tm1 = fmaxf(tm1, __shfl_xor_sync(0xffffffffu, tm1, 2));

        float mn0 = fmaxf(m0, tm0), mn1 = fmaxf(m1, tm1);
        float c0 = __expf(m0 - mn0), c1 = __expf(m1 - mn1);
        m0 = mn0; m1 = mn1;
        l0 *= c0; l1 *= c1;
        #pragma unroll
        for (int i = 0; i < 16; i++) {
            acc_o[i][0] *= c0; acc_o[i][1] *= c0;
            acc_o[i][2] *= c1; acc_o[i][3] *= c1;
        }
        #pragma unroll
        for (int nt = 0; nt < 8; nt++) {
            float p0 = __expf(s_[nt][0] - m0);
            float p1 = __expf(s_[nt][1] - m0);
            float p2 = __expf(s_[nt][2] - m1);
            float p3 = __expf(s_[nt][3] - m1);
            l0 += p0 + p1;
            l1 += p2 + p3;
            s_[nt][0] = p0; s_[nt][1] = p1; s_[nt][2] = p2; s_[nt][3] = p3;
        }

        // ---- O += P V (3-term) ----
        #pragma unroll
        for (int kc = 0; kc < 4; kc++) {
            uint32_t ph[4], pl[4];
            {
                const float* pa = s_[2*kc];
                const float* pb = s_[2*kc + 1];
                ph[0] = split_pair(pa[0], pa[1], pl[0]);
                ph[1] = split_pair(pa[2], pa[3], pl[1]);
                ph[2] = split_pair(pb[0], pb[1], pl[2]);
                ph[3] = split_pair(pb[2], pb[3], pl[3]);
            }
            #pragma unroll
            for (int ng = 0; ng < 8; ng++) {
                int vrow = kc*16 + m01*8 + r8;
                int vchk = ng*2 + m2;
                uint32_t va = st + 32768 + (uint32_t)(vrow*256 + SWZF(vrow, vchk));
                uint32_t wh[4], wl[4];
                ldsm4t(wh, va);
                ldsm4t(wl, va + 16384);
                mma16816(acc_o[ng*2+0], ph, wh);
                mma16816(acc_o[ng*2+0], ph, wl);
                mma16816(acc_o[ng*2+0], pl, wh);
                mma16816(acc_o[ng*2+1], ph, wh+2);
                mma16816(acc_o[ng*2+1], ph, wl+2);
                mma16816(acc_o[ng*2+1], pl, wh+2);
            }
        }
    }

    // ---- finalize ----
    l0 += __shfl_xor_sync(0xffffffffu, l0, 1);
    l0 += __shfl_xor_sync(0xffffffffu, l0, 2);
    l1 += __shfl_xor_sync(0xffffffffu, l1, 1);
    l1 += __shfl_xor_sync(0xffffffffu, l1, 2);
    const float inv0 = 1.f / l0, inv1 = 1.f / l1;

    const size_t row0 = (size_t)(b*NS) + qt*128 + w*16 + qr;
    #pragma unroll
    for (int nt = 0; nt < 16; nt++) {
        int col = h*NHD + nt*8 + qc;
        uint32_t lo0, lo1;
        uint32_t hi0 = split_pair(acc_o[nt][0]*inv0, acc_o[nt][1]*inv0, lo0);
        uint32_t hi1 = split_pair(acc_o[nt][2]*inv1, acc_o[nt][3]*inv1, lo1);
        *(uint32_t*)&ahi[row0 * ND + col]       = hi0;
        *(uint32_t*)&alo[row0 * ND + col]       = lo0;
        *(uint32_t*)&ahi[(row0 + 8) * ND + col] = hi1;
        *(uint32_t*)&alo[(row0 + 8) * ND + col] = lo1;
    }
}

// ---------------------------------------------------------------------------
extern "C" void kernel_launch(void* const* d_in, const int* in_sizes, int n_in,
                              void* d_out, int out_size)
{
    const float* x    = (const float*)d_in[0];
    const float* Wqkv = (const float*)d_in[1];
    const float* bqkv = (const float*)d_in[2];
    const float* Wout = (const float*)d_in[3];
    const float* bout = (const float*)d_in[4];
    float* out = (float*)d_out;

    __nv_bfloat16 *xhi, *xlo, *ahi, *alo, *wqh, *wql, *woh, *wol;
    __nv_bfloat16 *qh, *ql, *kh, *kl, *vh, *vl;
    cudaGetSymbolAddress((void**)&xhi,  g_xhi);
    cudaGetSymbolAddress((void**)&xlo,  g_xlo);
    cudaGetSymbolAddress((void**)&ahi,  g_ahi);
    cudaGetSymbolAddress((void**)&alo,  g_alo);
    cudaGetSymbolAddress((void**)&wqh,  g_wqT_hi);
    cudaGetSymbolAddress((void**)&wql,  g_wqT_lo);
    cudaGetSymbolAddress((void**)&woh,  g_woT_hi);
    cudaGetSymbolAddress((void**)&wol,  g_woT_lo);
    cudaGetSymbolAddress((void**)&qh,   g_qh);
    cudaGetSymbolAddress((void**)&ql,   g_ql);
    cudaGetSymbolAddress((void**)&kh,   g_kh);
    cudaGetSymbolAddress((void**)&kl,   g_kl);
    cudaGetSymbolAddress((void**)&vh,   g_vh);
    cudaGetSymbolAddress((void**)&vl,   g_vl);

    cudaFuncSetAttribute(gemm_mma<0>,
                         cudaFuncAttributeMaxDynamicSharedMemorySize, GEMM_SMEM);
    cudaFuncSetAttribute(gemm_mma<1>,
                         cudaFuncAttributeMaxDynamicSharedMemorySize, GEMM_SMEM);
    cudaFuncSetAttribute(flash_mma,
                         cudaFuncAttributeMaxDynamicSharedMemorySize, FLASH_SMEM);

    // operand conversions
    cvt_split<<<(ROWS*(size_t)ND/4 + 255)/256, 256>>>(
        (const float4*)x, (uint2*)xhi, (uint2*)xlo);
    cvt_split_T<<<dim3(QKV_COLS/32, ND/32), dim3(32, 8)>>>(Wqkv, wqh, wql, ND, QKV_COLS);
    cvt_split_T<<<dim3(ND/32, ND/32), dim3(32, 8)>>>(Wout, woh, wol, ND, ND);

    // qkv = x @ Wqkv + b_qkv, written directly as split per-head q/k/v
    gemm_mma<1><<<dim3(QKV_COLS/256, ROWS/128), 256, GEMM_SMEM>>>(
        xhi, xlo, wqh, wql, bqkv, nullptr,
        qh, ql, kh, kl, vh, vl, ROWS, QKV_COLS, ND);

    // attention -> writes proj A-operand (hi/lo) directly
    flash_mma<<<dim3(NS/128, NH, NB), 256, FLASH_SMEM>>>(
        qh, ql, kh, kl, vh, vl, ahi, alo);

    // out = attn @ Wout + b_out
    gemm_mma<0><<<dim3(ND/256, ROWS/128), 256, GEMM_SMEM>>>(
        ahi, alo, woh, wol, bout, out,
        nullptr, nullptr, nullptr, nullptr, nullptr, nullptr, ROWS, ND, ND);
}

// round 7
// speedup vs baseline: 3.3785x; 1.1107x over previous
#include <cuda_runtime.h>
#include <cuda_bf16.h>
#include <cstdint>
#include <math.h>

#define NB 4
#define NS 2048
#define ND 2048
#define NH 16
#define NHD 128
#define ROWS (NB*NS)        /* 8192 */
#define QKV_COLS (3*ND)     /* 6144 */

// ---------------- scratch (device globals: allocation-free rule) ----------
__device__ __nv_bfloat16 g_xhi[(size_t)ROWS * ND];
__device__ __nv_bfloat16 g_xlo[(size_t)ROWS * ND];
__device__ __nv_bfloat16 g_ahi[(size_t)ROWS * ND];         // attn out hi
__device__ __nv_bfloat16 g_alo[(size_t)ROWS * ND];         // attn out lo
__device__ __nv_bfloat16 g_wqT_hi[(size_t)QKV_COLS * ND];  // Wqkv^T [6144][2048]
__device__ __nv_bfloat16 g_wqT_lo[(size_t)QKV_COLS * ND];
__device__ __nv_bfloat16 g_woT_hi[(size_t)ND * ND];        // Wout^T [2048][2048]
__device__ __nv_bfloat16 g_woT_lo[(size_t)ND * ND];
// per-head split QKV: [B*H][S][HD]
__device__ __nv_bfloat16 g_qh[(size_t)ROWS * ND];
__device__ __nv_bfloat16 g_ql[(size_t)ROWS * ND];
__device__ __nv_bfloat16 g_kh[(size_t)ROWS * ND];
__device__ __nv_bfloat16 g_kl[(size_t)ROWS * ND];
__device__ __nv_bfloat16 g_vh[(size_t)ROWS * ND];
__device__ __nv_bfloat16 g_vl[(size_t)ROWS * ND];

// ---------------- PTX helpers (baseline features only: sm_80+) ------------
__device__ __forceinline__ uint32_t smem_u32(const void* p) {
    uint32_t a;
    asm("{ .reg .u64 t; cvta.to.shared.u64 t, %1; cvt.u32.u64 %0, t; }"
        : "=r"(a) : "l"(p));
    return a;
}

__device__ __forceinline__ void cpa16(uint32_t s, const void* g) {
    asm volatile("cp.async.cg.shared.global [%0], [%1], 16;" :: "r"(s), "l"(g));
}
#define CP_COMMIT() asm volatile("cp.async.commit_group;" ::: "memory")
#define CP_WAIT(n)  asm volatile("cp.async.wait_group %0;" :: "n"(n) : "memory")

__device__ __forceinline__ void ldsm4(uint32_t* r, uint32_t addr) {
    asm volatile("ldmatrix.sync.aligned.m8n8.x4.shared.b16 {%0,%1,%2,%3}, [%4];"
                 : "=r"(r[0]), "=r"(r[1]), "=r"(r[2]), "=r"(r[3]) : "r"(addr));
}
__device__ __forceinline__ void ldsm4t(uint32_t* r, uint32_t addr) {
    asm volatile("ldmatrix.sync.aligned.m8n8.x4.trans.shared.b16 {%0,%1,%2,%3}, [%4];"
                 : "=r"(r[0]), "=r"(r[1]), "=r"(r[2]), "=r"(r[3]) : "r"(addr));
}

__device__ __forceinline__ void mma16816(float* d, const uint32_t* a,
                                         const uint32_t* b) {
    asm volatile(
        "mma.sync.aligned.m16n8k16.row.col.f32.bf16.bf16.f32 "
        "{%0,%1,%2,%3}, {%4,%5,%6,%7}, {%8,%9}, {%0,%1,%2,%3};"
        : "+f"(d[0]), "+f"(d[1]), "+f"(d[2]), "+f"(d[3])
        : "r"(a[0]), "r"(a[1]), "r"(a[2]), "r"(a[3]), "r"(b[0]), "r"(b[1]));
}

__device__ __forceinline__ float ex2f(float x) {
    float y;
    asm("ex2.approx.f32 %0, %1;" : "=f"(y) : "f"(x));
    return y;
}

#define PACK2(lo16, hi16) (((uint32_t)(hi16) << 16) | (uint32_t)(lo16))
#define BFU(x) __bfloat16_as_ushort(x)

__device__ __forceinline__ uint32_t split_pair(float a, float b, uint32_t& lo) {
    __nv_bfloat16 h0 = __float2bfloat16(a), h1 = __float2bfloat16(b);
    __nv_bfloat16 e0 = __float2bfloat16(a - __bfloat162float(h0));
    __nv_bfloat16 e1 = __float2bfloat16(b - __bfloat162float(h1));
    lo = PACK2(BFU(e0), BFU(e1));
    return PACK2(BFU(h0), BFU(h1));
}

// ---------------------------------------------------------------------------
// conversion kernels
// ---------------------------------------------------------------------------
__global__ void cvt_split(const float4* __restrict__ in, uint2* __restrict__ hi,
                          uint2* __restrict__ lo)
{
    int i = blockIdx.x * blockDim.x + threadIdx.x;
    float4 v = in[i];
    uint2 uh, ul;
    uh.x = split_pair(v.x, v.y, ul.x);
    uh.y = split_pair(v.z, v.w, ul.y);
    hi[i] = uh;
    lo[i] = ul;
}

// W [K][N] fp32  ->  T [N][K] bf16 hi/lo
__global__ void cvt_split_T(const float* __restrict__ W,
                            __nv_bfloat16* __restrict__ Thi,
                            __nv_bfloat16* __restrict__ Tlo, int K, int N)
{
    __shared__ float tile[32][33];
    int n0 = blockIdx.x * 32, k0 = blockIdx.y * 32;
    int tx = threadIdx.x, ty = threadIdx.y;  // 32 x 8
    #pragma unroll
    for (int r = 0; r < 4; r++)
        tile[ty + r*8][tx] = W[(size_t)(k0 + ty + r*8) * N + n0 + tx];
    __syncthreads();
    #pragma unroll
    for (int r = 0; r < 4; r++) {
        float v = tile[tx][ty + r*8];
        __nv_bfloat16 h = __float2bfloat16(v);
        __nv_bfloat16 l = __float2bfloat16(v - __bfloat162float(h));
        size_t o = (size_t)(n0 + ty + r*8) * K + k0 + tx;
        Thi[o] = h;
        Tlo[o] = l;
    }
}

// ---------------------------------------------------------------------------
// bf16x3 GEMM via mma.sync. EPI=0: fp32 C + bias. EPI=1: split per-head QKV.
// CTA 128x128, BK=32, 8 warps (2m x 4n), warp tile 64x32, 3-stage cp.async,
// 96KB smem -> 2 CTAs/SM via __launch_bounds__(256, 2).
// ---------------------------------------------------------------------------
#define STAGES 3
#define STAGE_BYTES 32768      /* Ahi 8K | Alo 8K | Bhi 8K | Blo 8K */
#define GEMM_SMEM (STAGES * STAGE_BYTES)   /* 96 KB */
#define SWZ(row, kb) ((kb) ^ ((((row) >> 1) & 3) << 4))

__device__ __forceinline__ void issue_stage(
    uint32_t sb_stage, const __nv_bfloat16* __restrict__ Ahi,
    const __nv_bfloat16* __restrict__ Alo,
    const __nv_bfloat16* __restrict__ Bhi,
    const __nv_bfloat16* __restrict__ Blo,
    int rowBase, int colBase, int k0, int K, int t)
{
    #pragma unroll
    for (int u = 0; u < 2; u++) {
        int idx = t + 256*u;
        int row = idx >> 2, chunk = idx & 3;
        uint32_t soff = (uint32_t)(row*64 + SWZ(row, chunk*16));
        size_t geA = (size_t)(rowBase + row) * K + k0 + chunk*8;
        size_t geB = (size_t)(colBase + row) * K + k0 + chunk*8;
        cpa16(sb_stage +         soff, Ahi + geA);
        cpa16(sb_stage +  8192 + soff, Alo + geA);
        cpa16(sb_stage + 16384 + soff, Bhi + geB);
        cpa16(sb_stage + 24576 + soff, Blo + geB);
    }
    CP_COMMIT();
}

template<int EPI>
__global__ __launch_bounds__(256, 2)
void gemm_mma(const __nv_bfloat16* __restrict__ Ahi,
              const __nv_bfloat16* __restrict__ Alo,
              const __nv_bfloat16* __restrict__ Bhi,
              const __nv_bfloat16* __restrict__ Blo,
              const float* __restrict__ bias, float* __restrict__ C,
              __nv_bfloat16* __restrict__ q_h, __nv_bfloat16* __restrict__ q_l,
              __nv_bfloat16* __restrict__ k_h, __nv_bfloat16* __restrict__ k_l,
              __nv_bfloat16* __restrict__ v_h, __nv_bfloat16* __restrict__ v_l,
              int M, int N, int K)
{
    extern __shared__ char sm[];
    const uint32_t sb = smem_u32(sm);

    const int t = threadIdx.x, lane = t & 31, w = t >> 5;
    const int warp_m = w & 1, warp_n = w >> 1;   // 2 x 4
    const int rowBase = blockIdx.y * 128;
    const int colBase = blockIdx.x * 128;
    const int ksteps  = K >> 5;
    const int mat = lane >> 3, r8 = lane & 7;

    float acc[4][4][4];
    #pragma unroll
    for (int i = 0; i < 4; i++)
        #pragma unroll
        for (int j = 0; j < 4; j++)
            #pragma unroll
            for (int q = 0; q < 4; q++) acc[i][j][q] = 0.f;

    issue_stage(sb,               Ahi, Alo, Bhi, Blo, rowBase, colBase, 0,  K, t);
    issue_stage(sb + STAGE_BYTES, Ahi, Alo, Bhi, Blo, rowBase, colBase, 32, K, t);

    int rowA[4], rowB[2];
    #pragma unroll
    for (int fm = 0; fm < 4; fm++)
        rowA[fm] = warp_m*64 + fm*16 + (mat & 1)*8 + r8;
    #pragma unroll
    for (int fb = 0; fb < 2; fb++)
        rowB[fb] = warp_n*32 + fb*16 + (mat >> 1)*8 + r8;

    for (int i = 0; i < ksteps; i++) {
        CP_WAIT(1);
        __syncthreads();
        // issue into slot (i+2)%3 == (i-1)%3: fully read in iter i-1,
        // and the barrier above proves all warps passed that point.
        if (i + 2 < ksteps)
            issue_stage(sb + (uint32_t)((i + 2) % 3) * STAGE_BYTES,
                        Ahi, Alo, Bhi, Blo, rowBase, colBase, (i + 2)*32, K, t);
        else
            CP_COMMIT();   // empty group keeps per-thread accounting uniform

        const uint32_t st = sb + (uint32_t)(i % 3) * STAGE_BYTES;

        #pragma unroll
        for (int ks = 0; ks < 2; ks++) {
            uint32_t ah[4][4], al[4][4];
            const int kbA = ks*32 + (mat >> 1)*16;
            const int kbB = ks*32 + (mat & 1)*16;
            #pragma unroll
            for (int fm = 0; fm < 4; fm++) {
                uint32_t off = (uint32_t)(rowA[fm]*64 + SWZ(rowA[fm], kbA));
                ldsm4(ah[fm], st +        off);
                ldsm4(al[fm], st + 8192 + off);
            }
            #pragma unroll
            for (int fb = 0; fb < 2; fb++) {
                uint32_t off = (uint32_t)(rowB[fb]*64 + SWZ(rowB[fb], kbB));
                uint32_t rh[4], rl[4];
                ldsm4(rh, st + 16384 + off);
                ldsm4(rl, st + 24576 + off);
                #pragma unroll
                for (int fm = 0; fm < 4; fm++) {
                    mma16816(acc[fm][2*fb+0], ah[fm], rh);
                    mma16816(acc[fm][2*fb+0], ah[fm], rl);
                    mma16816(acc[fm][2*fb+0], al[fm], rh);
                    mma16816(acc[fm][2*fb+1], ah[fm], rh+2);
                    mma16816(acc[fm][2*fb+1], ah[fm], rl+2);
                    mma16816(acc[fm][2*fb+1], al[fm], rh+2);
                }
            }
        }
        __syncthreads();
    }

    const int qrow = lane >> 2, qcol = (lane & 3) * 2;
    #pragma unroll
    for (int fn = 0; fn < 4; fn++) {
        const int col = colBase + warp_n*32 + fn*8 + qcol;
        const float b0 = bias[col], b1 = bias[col + 1];
        if (EPI == 0) {
            #pragma unroll
            for (int fm = 0; fm < 4; fm++) {
                const int row0 = rowBase + warp_m*64 + fm*16 + qrow;
                float2 v0 = make_float2(acc[fm][fn][0] + b0, acc[fm][fn][1] + b1);
                float2 v1 = make_float2(acc[fm][fn][2] + b0, acc[fm][fn][3] + b1);
                *(float2*)&C[(size_t)row0 * N + col]       = v0;
                *(float2*)&C[(size_t)(row0 + 8) * N + col] = v1;
            }
        } else {
            const int sel = col >> 11, hh = (col >> 7) & 15, hd = col & 127;
            __nv_bfloat16* dh = (sel == 0) ? q_h : (sel == 1) ? k_h : v_h;
            __nv_bfloat16* dl = (sel == 0) ? q_l : (sel == 1) ? k_l : v_l;
            #pragma unroll
            for (int fm = 0; fm < 4; fm++) {
                const int r0 = rowBase + warp_m*64 + fm*16 + qrow;
                #pragma unroll
                for (int rr = 0; rr < 2; rr++) {
                    const int r = r0 + rr*8;
                    float va = acc[fm][fn][rr*2+0] + b0;
                    float vb = acc[fm][fn][rr*2+1] + b1;
                    uint32_t lo, hi = split_pair(va, vb, lo);
                    size_t o = (((size_t)((r >> 11)*NH + hh) * NS +
                                 (r & 2047)) * NHD + hd);
                    *(uint32_t*)&dh[o] = hi;
                    *(uint32_t*)&dl[o] = lo;
                }
            }
        }
    }
}

// ---------------------------------------------------------------------------
// Flash attention via mma.sync, bf16x3 emulation, ALiBi + causal.
// Static-max softmax: M_est(r) = slope*(r-2047) + 8 is a provable upper bound
// on the row max (|qk*scale| << 8, ALiBi bias peaks at col=r). So
// p = ex2(qk*c1 + sl2*(col-r) - 8*log2e) directly; no running max, no
// rescaling; division by l at the end cancels the offset exactly.
// ---------------------------------------------------------------------------
#define FLASH_SMEM (3*65536)   /* 196608 */
#define SWZF(row, chunk) (((chunk) ^ ((row) & 7)) << 4)

__device__ __forceinline__ void flash_load_kv(
    uint32_t st, const __nv_bfloat16* __restrict__ kh,
    const __nv_bfloat16* __restrict__ kl,
    const __nv_bfloat16* __restrict__ vh,
    const __nv_bfloat16* __restrict__ vl,
    size_t hb, int kt, int t)
{
    #pragma unroll
    for (int u = 0; u < 4; u++) {
        int idx = t + 256*u;                 // 0..1023
        int row = idx >> 4, chunk = idx & 15;
        uint32_t soff = (uint32_t)(row*256 + SWZF(row, chunk));
        size_t g = hb + (size_t)(kt*64 + row)*NHD + chunk*8;
        cpa16(st +         soff, kh + g);
        cpa16(st + 16384 + soff, kl + g);
        cpa16(st + 32768 + soff, vh + g);
        cpa16(st + 49152 + soff, vl + g);
    }
    CP_COMMIT();
}

__global__ __launch_bounds__(256, 1)
void flash_mma(const __nv_bfloat16* __restrict__ qh,
               const __nv_bfloat16* __restrict__ ql,
               const __nv_bfloat16* __restrict__ kh,
               const __nv_bfloat16* __restrict__ kl,
               const __nv_bfloat16* __restrict__ vh,
               const __nv_bfloat16* __restrict__ vl,
               __nv_bfloat16* __restrict__ ahi,
               __nv_bfloat16* __restrict__ alo)
{
    extern __shared__ char sm[];
    const uint32_t sb = smem_u32(sm);
    const uint32_t qst = sb + 2*65536;       // Q staging = slot 2

    const int qt = blockIdx.x, h = blockIdx.y, b = blockIdx.z;
    const int t = threadIdx.x, lane = t & 31, w = t >> 5;
    const size_t hb = (size_t)(b*NH + h) * NS * NHD;

    const float L2E   = 1.4426950408889634f;
    const float scale = 0.08838834764831845f;          // 1/sqrt(128)
    const float slope = exp2f(-0.5f * (float)(h + 1)); // ALiBi, H=16
    const float c1  = scale * L2E;
    const float sl2 = slope * L2E;
    const float mc8 = -8.0f * L2E;
    const int r8 = lane & 7, m01 = (lane >> 3) & 1, m2 = lane >> 4;
    const int qr = lane >> 2, qc = (lane & 3) * 2;
    const int rg0 = qt*128 + w*16 + qr;                // global q row (c0/c1)

    // stage Q into slot 2
    #pragma unroll
    for (int u = 0; u < 8; u++) {
        int idx = t + 256*u;                 // 0..2047
        int row = idx >> 4, chunk = idx & 15;
        uint32_t soff = (uint32_t)(row*256 + SWZF(row, chunk));
        size_t g = hb + (size_t)(qt*128 + row)*NHD + chunk*8;
        cpa16(qst +         soff, qh + g);
        cpa16(qst + 32768 + soff, ql + g);
    }
    CP_COMMIT();                             // group: Q
    flash_load_kv(sb,         kh, kl, vh, vl, hb, 0, t);   // group: KV0
    flash_load_kv(sb + 65536, kh, kl, vh, vl, hb, 1, t);   // group: KV1

    CP_WAIT(2);                              // Q complete
    __syncthreads();

    // Q fragments -> registers (per warp: its own 16 rows, all 128 hd)
    uint32_t fqh[8][4], fql[8][4];
    {
        const int qrow = w*16 + m01*8 + r8;
        #pragma unroll
        for (int kc = 0; kc < 8; kc++) {
            uint32_t qa = qst + (uint32_t)(qrow*256 + SWZF(qrow, kc*2 + m2));
            ldsm4(fqh[kc], qa);
            ldsm4(fql[kc], qa + 32768);
        }
    }

    float l0 = 0.f, l1 = 0.f;
    float acc_o[16][4];
    #pragma unroll
    for (int i = 0; i < 16; i++)
        #pragma unroll
        for (int j = 0; j < 4; j++) acc_o[i][j] = 0.f;

    const int nkt = 2*qt + 2;
    for (int kt = 0; kt < nkt; kt++) {
        CP_WAIT(1);
        __syncthreads();
        // slot (kt+2)%3 was fully read in iter kt-1 (or was the Q staging,
        // whose reads precede the first barrier) — safe to refill now.
        if (kt + 2 < nkt)
            flash_load_kv(sb + (uint32_t)((kt + 2) % 3)*65536,
                          kh, kl, vh, vl, hb, kt + 2, t);
        else
            CP_COMMIT();

        const uint32_t st = sb + (uint32_t)(kt % 3)*65536;

        // ---- S = Q K^T (3-term) ----
        float s_[8][4];
        #pragma unroll
        for (int i = 0; i < 8; i++)
            #pragma unroll
            for (int j = 0; j < 4; j++) s_[i][j] = 0.f;

        #pragma unroll
        for (int kc = 0; kc < 8; kc++) {
            #pragma unroll
            for (int ng = 0; ng < 4; ng++) {
                int krow = ng*16 + m2*8 + r8;
                int kchk = kc*2 + m01;
                uint32_t ka = st + (uint32_t)(krow*256 + SWZF(krow, kchk));
                uint32_t rh[4], rl[4];
                ldsm4(rh, ka);
                ldsm4(rl, ka + 16384);
                mma16816(s_[ng*2+0], fqh[kc], rh);
                mma16816(s_[ng*2+0], fqh[kc], rl);
                mma16816(s_[ng*2+0], fql[kc], rh);
                mma16816(s_[ng*2+1], fqh[kc], rh+2);
                mma16816(s_[ng*2+1], fqh[kc], rl+2);
                mma16816(s_[ng*2+1], fql[kc], rh+2);
            }
        }

        // ---- static-max softmax: p = ex2(s*c1 + sl2*(col - r) - 8*L2E) ----
        const bool diag = (kt >= 2*qt);
        const float baseA = fmaf((float)(kt*64 + qc - rg0), sl2, mc8);
        const float baseB = baseA - 8.0f*sl2;   // rows rg0+8
        if (diag) {
            #pragma unroll
            for (int nt = 0; nt < 8; nt++) {
                #pragma unroll
                for (int jj = 0; jj < 2; jj++) {
                    const float cf = (float)(nt*8 + jj);
                    float a0 = fmaf(s_[nt][jj],     c1, fmaf(cf, sl2, baseA));
                    float a1 = fmaf(s_[nt][2 + jj], c1, fmaf(cf, sl2, baseB));
                    int col = kt*64 + nt*8 + qc + jj;
                    if (col > rg0)     a0 = -10000.f;
                    if (col > rg0 + 8) a1 = -10000.f;
                    float p0 = ex2f(a0), p1 = ex2f(a1);
                    l0 += p0; l1 += p1;
                    s_[nt][jj] = p0; s_[nt][2 + jj] = p1;
                }
            }
        } else {
            #pragma unroll
            for (int nt = 0; nt < 8; nt++) {
                #pragma unroll
                for (int jj = 0; jj < 2; jj++) {
                    const float cf = (float)(nt*8 + jj);
                    float a0 = fmaf(s_[nt][jj],     c1, fmaf(cf, sl2, baseA));
                    float a1 = fmaf(s_[nt][2 + jj], c1, fmaf(cf, sl2, baseB));
                    float p0 = ex2f(a0), p1 = ex2f(a1);
                    l0 += p0; l1 += p1;
                    s_[nt][jj] = p0; s_[nt][2 + jj] = p1;
                }
            }
        }

        // ---- O += P V (3-term) ----
        #pragma unroll
        for (int kc = 0; kc < 4; kc++) {
            uint32_t ph[4], pl[4];
            {
                const float* pa = s_[2*kc];
                const float* pb = s_[2*kc + 1];
                ph[0] = split_pair(pa[0], pa[1], pl[0]);
                ph[1] = split_pair(pa[2], pa[3], pl[1]);
                ph[2] = split_pair(pb[0], pb[1], pl[2]);
                ph[3] = split_pair(pb[2], pb[3], pl[3]);
            }
            #pragma unroll
            for (int ng = 0; ng < 8; ng++) {
                int vrow = kc*16 + m01*8 + r8;
                int vchk = ng*2 + m2;
                uint32_t va = st + 32768 + (uint32_t)(vrow*256 + SWZF(vrow, vchk));
                uint32_t wh[4], wl[4];
                ldsm4t(wh, va);
                ldsm4t(wl, va + 16384);
                mma16816(acc_o[ng*2+0], ph, wh);
                mma16816(acc_o[ng*2+0], ph, wl);
                mma16816(acc_o[ng*2+0], pl, wh);
                mma16816(acc_o[ng*2+1], ph, wh+2);
                mma16816(acc_o[ng*2+1], ph, wl+2);
                mma16816(acc_o[ng*2+1], pl, wh+2);
            }
        }
    }

    // ---- finalize ----
    l0 += __shfl_xor_sync(0xffffffffu, l0, 1);
    l0 += __shfl_xor_sync(0xffffffffu, l0, 2);
    l1 += __shfl_xor_sync(0xffffffffu, l1, 1);
    l1 += __shfl_xor_sync(0xffffffffu, l1, 2);
    const float inv0 = 1.f / l0, inv1 = 1.f / l1;

    const size_t row0 = (size_t)(b*NS) + qt*128 + w*16 + qr;
    #pragma unroll
    for (int nt = 0; nt < 16; nt++) {
        int col = h*NHD + nt*8 + qc;
        uint32_t lo0, lo1;
        uint32_t hi0 = split_pair(acc_o[nt][0]*inv0, acc_o[nt][1]*inv0, lo0);
        uint32_t hi1 = split_pair(acc_o[nt][2]*inv1, acc_o[nt][3]*inv1, lo1);
        *(uint32_t*)&ahi[row0 * ND + col]       = hi0;
        *(uint32_t*)&alo[row0 * ND + col]       = lo0;
        *(uint32_t*)&ahi[(row0 + 8) * ND + col] = hi1;
        *(uint32_t*)&alo[(row0 + 8) * ND + col] = lo1;
    }
}

// ---------------------------------------------------------------------------
extern "C" void kernel_launch(void* const* d_in, const int* in_sizes, int n_in,
                              void* d_out, int out_size)
{
    const float* x    = (const float*)d_in[0];
    const float* Wqkv = (const float*)d_in[1];
    const float* bqkv = (const float*)d_in[2];
    const float* Wout = (const float*)d_in[3];
    const float* bout = (const float*)d_in[4];
    float* out = (float*)d_out;

    __nv_bfloat16 *xhi, *xlo, *ahi, *alo, *wqh, *wql, *woh, *wol;
    __nv_bfloat16 *qh, *ql, *kh, *kl, *vh, *vl;
    cudaGetSymbolAddress((void**)&xhi,  g_xhi);
    cudaGetSymbolAddress((void**)&xlo,  g_xlo);
    cudaGetSymbolAddress((void**)&ahi,  g_ahi);
    cudaGetSymbolAddress((void**)&alo,  g_alo);
    cudaGetSymbolAddress((void**)&wqh,  g_wqT_hi);
    cudaGetSymbolAddress((void**)&wql,  g_wqT_lo);
    cudaGetSymbolAddress((void**)&woh,  g_woT_hi);
    cudaGetSymbolAddress((void**)&wol,  g_woT_lo);
    cudaGetSymbolAddress((void**)&qh,   g_qh);
    cudaGetSymbolAddress((void**)&ql,   g_ql);
    cudaGetSymbolAddress((void**)&kh,   g_kh);
    cudaGetSymbolAddress((void**)&kl,   g_kl);
    cudaGetSymbolAddress((void**)&vh,   g_vh);
    cudaGetSymbolAddress((void**)&vl,   g_vl);

    cudaFuncSetAttribute(gemm_mma<0>,
                         cudaFuncAttributeMaxDynamicSharedMemorySize, GEMM_SMEM);
    cudaFuncSetAttribute(gemm_mma<1>,
                         cudaFuncAttributeMaxDynamicSharedMemorySize, GEMM_SMEM);
    cudaFuncSetAttribute(flash_mma,
                         cudaFuncAttributeMaxDynamicSharedMemorySize, FLASH_SMEM);

    // operand conversions
    cvt_split<<<(ROWS*(size_t)ND/4 + 255)/256, 256>>>(
        (const float4*)x, (uint2*)xhi, (uint2*)xlo);
    cvt_split_T<<<dim3(QKV_COLS/32, ND/32), dim3(32, 8)>>>(Wqkv, wqh, wql, ND, QKV_COLS);
    cvt_split_T<<<dim3(ND/32, ND/32), dim3(32, 8)>>>(Wout, woh, wol, ND, ND);

    // qkv = x @ Wqkv + b_qkv, written directly as split per-head q/k/v
    gemm_mma<1><<<dim3(QKV_COLS/128, ROWS/128), 256, GEMM_SMEM>>>(
        xhi, xlo, wqh, wql, bqkv, nullptr,
        qh, ql, kh, kl, vh, vl, ROWS, QKV_COLS, ND);

    // attention -> writes proj A-operand (hi/lo) directly
    flash_mma<<<dim3(NS/128, NH, NB), 256, FLASH_SMEM>>>(
        qh, ql, kh, kl, vh, vl, ahi, alo);

    // out = attn @ Wout + b_out
    gemm_mma<0><<<dim3(ND/128, ROWS/128), 256, GEMM_SMEM>>>(
        ahi, alo, woh, wol, bout, out,
        nullptr, nullptr, nullptr, nullptr, nullptr, nullptr, ROWS, ND, ND);
}

// round 8
// speedup vs baseline: 3.3934x; 1.0044x over previous
#include <cuda_runtime.h>
#include <cuda_bf16.h>
#include <cstdint>
#include <math.h>

#define NB 4
#define NS 2048
#define ND 2048
#define NH 16
#define NHD 128
#define ROWS (NB*NS)        /* 8192 */
#define QKV_COLS (3*ND)     /* 6144 */

// ---------------- scratch (device globals: allocation-free rule) ----------
__device__ __nv_bfloat16 g_xhi[(size_t)ROWS * ND];
__device__ __nv_bfloat16 g_xlo[(size_t)ROWS * ND];
__device__ __nv_bfloat16 g_ahi[(size_t)ROWS * ND];         // attn out hi
__device__ __nv_bfloat16 g_alo[(size_t)ROWS * ND];         // attn out lo
__device__ __nv_bfloat16 g_wqT_hi[(size_t)QKV_COLS * ND];  // Wqkv^T [6144][2048]
__device__ __nv_bfloat16 g_wqT_lo[(size_t)QKV_COLS * ND];
__device__ __nv_bfloat16 g_woT_hi[(size_t)ND * ND];        // Wout^T [2048][2048]
__device__ __nv_bfloat16 g_woT_lo[(size_t)ND * ND];
// per-head split QKV: [B*H][S][HD]
__device__ __nv_bfloat16 g_qh[(size_t)ROWS * ND];
__device__ __nv_bfloat16 g_ql[(size_t)ROWS * ND];
__device__ __nv_bfloat16 g_kh[(size_t)ROWS * ND];
__device__ __nv_bfloat16 g_kl[(size_t)ROWS * ND];
__device__ __nv_bfloat16 g_vh[(size_t)ROWS * ND];
__device__ __nv_bfloat16 g_vl[(size_t)ROWS * ND];

// ---------------- PTX helpers (baseline features only: sm_80+) ------------
__device__ __forceinline__ uint32_t smem_u32(const void* p) {
    uint32_t a;
    asm("{ .reg .u64 t; cvta.to.shared.u64 t, %1; cvt.u32.u64 %0, t; }"
        : "=r"(a) : "l"(p));
    return a;
}

__device__ __forceinline__ void cpa16(uint32_t s, const void* g) {
    asm volatile("cp.async.cg.shared.global [%0], [%1], 16;" :: "r"(s), "l"(g));
}
#define CP_COMMIT() asm volatile("cp.async.commit_group;" ::: "memory")
#define CP_WAIT(n)  asm volatile("cp.async.wait_group %0;" :: "n"(n) : "memory")

__device__ __forceinline__ void ldsm4(uint32_t* r, uint32_t addr) {
    asm volatile("ldmatrix.sync.aligned.m8n8.x4.shared.b16 {%0,%1,%2,%3}, [%4];"
                 : "=r"(r[0]), "=r"(r[1]), "=r"(r[2]), "=r"(r[3]) : "r"(addr));
}
__device__ __forceinline__ void ldsm4t(uint32_t* r, uint32_t addr) {
    asm volatile("ldmatrix.sync.aligned.m8n8.x4.trans.shared.b16 {%0,%1,%2,%3}, [%4];"
                 : "=r"(r[0]), "=r"(r[1]), "=r"(r[2]), "=r"(r[3]) : "r"(addr));
}

__device__ __forceinline__ void mma16816(float* d, const uint32_t* a,
                                         const uint32_t* b) {
    asm volatile(
        "mma.sync.aligned.m16n8k16.row.col.f32.bf16.bf16.f32 "
        "{%0,%1,%2,%3}, {%4,%5,%6,%7}, {%8,%9}, {%0,%1,%2,%3};"
        : "+f"(d[0]), "+f"(d[1]), "+f"(d[2]), "+f"(d[3])
        : "r"(a[0]), "r"(a[1]), "r"(a[2]), "r"(a[3]), "r"(b[0]), "r"(b[1]));
}

__device__ __forceinline__ float ex2f(float x) {
    float y;
    asm("ex2.approx.f32 %0, %1;" : "=f"(y) : "f"(x));
    return y;
}

#define PACK2(lo16, hi16) (((uint32_t)(hi16) << 16) | (uint32_t)(lo16))
#define BFU(x) __bfloat16_as_ushort(x)

__device__ __forceinline__ uint32_t split_pair(float a, float b, uint32_t& lo) {
    __nv_bfloat16 h0 = __float2bfloat16(a), h1 = __float2bfloat16(b);
    __nv_bfloat16 e0 = __float2bfloat16(a - __bfloat162float(h0));
    __nv_bfloat16 e1 = __float2bfloat16(b - __bfloat162float(h1));
    lo = PACK2(BFU(e0), BFU(e1));
    return PACK2(BFU(h0), BFU(h1));
}

// ---------------------------------------------------------------------------
// conversion kernels
// ---------------------------------------------------------------------------
__global__ void cvt_split(const float4* __restrict__ in, uint2* __restrict__ hi,
                          uint2* __restrict__ lo)
{
    int i = blockIdx.x * blockDim.x + threadIdx.x;
    float4 v = in[i];
    uint2 uh, ul;
    uh.x = split_pair(v.x, v.y, ul.x);
    uh.y = split_pair(v.z, v.w, ul.y);
    hi[i] = uh;
    lo[i] = ul;
}

// W [K][N] fp32  ->  T [N][K] bf16 hi/lo
__global__ void cvt_split_T(const float* __restrict__ W,
                            __nv_bfloat16* __restrict__ Thi,
                            __nv_bfloat16* __restrict__ Tlo, int K, int N)
{
    __shared__ float tile[32][33];
    int n0 = blockIdx.x * 32, k0 = blockIdx.y * 32;
    int tx = threadIdx.x, ty = threadIdx.y;  // 32 x 8
    #pragma unroll
    for (int r = 0; r < 4; r++)
        tile[ty + r*8][tx] = W[(size_t)(k0 + ty + r*8) * N + n0 + tx];
    __syncthreads();
    #pragma unroll
    for (int r = 0; r < 4; r++) {
        float v = tile[tx][ty + r*8];
        __nv_bfloat16 h = __float2bfloat16(v);
        __nv_bfloat16 l = __float2bfloat16(v - __bfloat162float(h));
        size_t o = (size_t)(n0 + ty + r*8) * K + k0 + tx;
        Thi[o] = h;
        Tlo[o] = l;
    }
}

// ---------------------------------------------------------------------------
// bf16x3 GEMM via mma.sync. EPI=0: fp32 C + bias. EPI=1: split per-head QKV.
// CTA 128x128, BK=32, 8 warps (2m x 4n), warp tile 64x32, 3-stage cp.async,
// 96KB smem -> 2 CTAs/SM. ONE barrier per k-step: iteration i refills slot
// (i+2)%3 == (i-1)%3, whose reads all completed before this iteration's
// top barrier.
// ---------------------------------------------------------------------------
#define STAGES 3
#define STAGE_BYTES 32768      /* Ahi 8K | Alo 8K | Bhi 8K | Blo 8K */
#define GEMM_SMEM (STAGES * STAGE_BYTES)   /* 96 KB */
#define SWZ(row, kb) ((kb) ^ ((((row) >> 1) & 3) << 4))

__device__ __forceinline__ void issue_stage(
    uint32_t sb_stage, const __nv_bfloat16* __restrict__ Ahi,
    const __nv_bfloat16* __restrict__ Alo,
    const __nv_bfloat16* __restrict__ Bhi,
    const __nv_bfloat16* __restrict__ Blo,
    int rowBase, int colBase, int k0, int K, int t)
{
    #pragma unroll
    for (int u = 0; u < 2; u++) {
        int idx = t + 256*u;
        int row = idx >> 2, chunk = idx & 3;
        uint32_t soff = (uint32_t)(row*64 + SWZ(row, chunk*16));
        size_t geA = (size_t)(rowBase + row) * K + k0 + chunk*8;
        size_t geB = (size_t)(colBase + row) * K + k0 + chunk*8;
        cpa16(sb_stage +         soff, Ahi + geA);
        cpa16(sb_stage +  8192 + soff, Alo + geA);
        cpa16(sb_stage + 16384 + soff, Bhi + geB);
        cpa16(sb_stage + 24576 + soff, Blo + geB);
    }
    CP_COMMIT();
}

template<int EPI>
__global__ __launch_bounds__(256, 2)
void gemm_mma(const __nv_bfloat16* __restrict__ Ahi,
              const __nv_bfloat16* __restrict__ Alo,
              const __nv_bfloat16* __restrict__ Bhi,
              const __nv_bfloat16* __restrict__ Blo,
              const float* __restrict__ bias, float* __restrict__ C,
              __nv_bfloat16* __restrict__ q_h, __nv_bfloat16* __restrict__ q_l,
              __nv_bfloat16* __restrict__ k_h, __nv_bfloat16* __restrict__ k_l,
              __nv_bfloat16* __restrict__ v_h, __nv_bfloat16* __restrict__ v_l,
              int M, int N, int K)
{
    extern __shared__ char sm[];
    const uint32_t sb = smem_u32(sm);

    const int t = threadIdx.x, lane = t & 31, w = t >> 5;
    const int warp_m = w & 1, warp_n = w >> 1;   // 2 x 4
    const int rowBase = blockIdx.y * 128;
    const int colBase = blockIdx.x * 128;
    const int ksteps  = K >> 5;
    const int mat = lane >> 3, r8 = lane & 7;

    float acc[4][4][4];
    #pragma unroll
    for (int i = 0; i < 4; i++)
        #pragma unroll
        for (int j = 0; j < 4; j++)
            #pragma unroll
            for (int q = 0; q < 4; q++) acc[i][j][q] = 0.f;

    issue_stage(sb,               Ahi, Alo, Bhi, Blo, rowBase, colBase, 0,  K, t);
    issue_stage(sb + STAGE_BYTES, Ahi, Alo, Bhi, Blo, rowBase, colBase, 32, K, t);

    int rowA[4], rowB[2];
    #pragma unroll
    for (int fm = 0; fm < 4; fm++)
        rowA[fm] = warp_m*64 + fm*16 + (mat & 1)*8 + r8;
    #pragma unroll
    for (int fb = 0; fb < 2; fb++)
        rowB[fb] = warp_n*32 + fb*16 + (mat >> 1)*8 + r8;

    for (int i = 0; i < ksteps; i++) {
        CP_WAIT(1);
        __syncthreads();
        // refill slot (i+2)%3 == (i-1)%3: its reads (iter i-1) all completed
        // before every warp arrived at the barrier above.
        if (i + 2 < ksteps)
            issue_stage(sb + (uint32_t)((i + 2) % 3) * STAGE_BYTES,
                        Ahi, Alo, Bhi, Blo, rowBase, colBase, (i + 2)*32, K, t);
        else
            CP_COMMIT();   // empty group keeps per-thread accounting uniform

        const uint32_t st = sb + (uint32_t)(i % 3) * STAGE_BYTES;

        #pragma unroll
        for (int ks = 0; ks < 2; ks++) {
            uint32_t ah[4][4], al[4][4];
            const int kbA = ks*32 + (mat >> 1)*16;
            const int kbB = ks*32 + (mat & 1)*16;
            #pragma unroll
            for (int fm = 0; fm < 4; fm++) {
                uint32_t off = (uint32_t)(rowA[fm]*64 + SWZ(rowA[fm], kbA));
                ldsm4(ah[fm], st +        off);
                ldsm4(al[fm], st + 8192 + off);
            }
            #pragma unroll
            for (int fb = 0; fb < 2; fb++) {
                uint32_t off = (uint32_t)(rowB[fb]*64 + SWZ(rowB[fb], kbB));
                uint32_t rh[4], rl[4];
                ldsm4(rh, st + 16384 + off);
                ldsm4(rl, st + 24576 + off);
                #pragma unroll
                for (int fm = 0; fm < 4; fm++) {
                    mma16816(acc[fm][2*fb+0], ah[fm], rh);
                    mma16816(acc[fm][2*fb+0], ah[fm], rl);
                    mma16816(acc[fm][2*fb+0], al[fm], rh);
                    mma16816(acc[fm][2*fb+1], ah[fm], rh+2);
                    mma16816(acc[fm][2*fb+1], ah[fm], rl+2);
                    mma16816(acc[fm][2*fb+1], al[fm], rh+2);
                }
            }
        }
        // no bottom barrier: next iteration's top barrier provides the
        // read-before-overwrite guarantee.
    }

    const int qrow = lane >> 2, qcol = (lane & 3) * 2;
    #pragma unroll
    for (int fn = 0; fn < 4; fn++) {
        const int col = colBase + warp_n*32 + fn*8 + qcol;
        const float b0 = bias[col], b1 = bias[col + 1];
        if (EPI == 0) {
            #pragma unroll
            for (int fm = 0; fm < 4; fm++) {
                const int row0 = rowBase + warp_m*64 + fm*16 + qrow;
                float2 v0 = make_float2(acc[fm][fn][0] + b0, acc[fm][fn][1] + b1);
                float2 v1 = make_float2(acc[fm][fn][2] + b0, acc[fm][fn][3] + b1);
                *(float2*)&C[(size_t)row0 * N + col]       = v0;
                *(float2*)&C[(size_t)(row0 + 8) * N + col] = v1;
            }
        } else {
            const int sel = col >> 11, hh = (col >> 7) & 15, hd = col & 127;
            __nv_bfloat16* dh = (sel == 0) ? q_h : (sel == 1) ? k_h : v_h;
            __nv_bfloat16* dl = (sel == 0) ? q_l : (sel == 1) ? k_l : v_l;
            #pragma unroll
            for (int fm = 0; fm < 4; fm++) {
                const int r0 = rowBase + warp_m*64 + fm*16 + qrow;
                #pragma unroll
                for (int rr = 0; rr < 2; rr++) {
                    const int r = r0 + rr*8;
                    float va = acc[fm][fn][rr*2+0] + b0;
                    float vb = acc[fm][fn][rr*2+1] + b1;
                    uint32_t lo, hi = split_pair(va, vb, lo);
                    size_t o = (((size_t)((r >> 11)*NH + hh) * NS +
                                 (r & 2047)) * NHD + hd);
                    *(uint32_t*)&dh[o] = hi;
                    *(uint32_t*)&dl[o] = lo;
                }
            }
        }
    }
}

// ---------------------------------------------------------------------------
// Flash attention via mma.sync, bf16x3 emulation, ALiBi + causal.
// Static-max softmax (see R7). Heaviest q-tiles launch first
// (qt = 15 - blockIdx.x) to shrink the causal tail wave.
// ---------------------------------------------------------------------------
#define FLASH_SMEM (3*65536)   /* 196608 */
#define SWZF(row, chunk) (((chunk) ^ ((row) & 7)) << 4)

__device__ __forceinline__ void flash_load_kv(
    uint32_t st, const __nv_bfloat16* __restrict__ kh,
    const __nv_bfloat16* __restrict__ kl,
    const __nv_bfloat16* __restrict__ vh,
    const __nv_bfloat16* __restrict__ vl,
    size_t hb, int kt, int t)
{
    #pragma unroll
    for (int u = 0; u < 4; u++) {
        int idx = t + 256*u;                 // 0..1023
        int row = idx >> 4, chunk = idx & 15;
        uint32_t soff = (uint32_t)(row*256 + SWZF(row, chunk));
        size_t g = hb + (size_t)(kt*64 + row)*NHD + chunk*8;
        cpa16(st +         soff, kh + g);
        cpa16(st + 16384 + soff, kl + g);
        cpa16(st + 32768 + soff, vh + g);
        cpa16(st + 49152 + soff, vl + g);
    }
    CP_COMMIT();
}

__global__ __launch_bounds__(256, 1)
void flash_mma(const __nv_bfloat16* __restrict__ qh,
               const __nv_bfloat16* __restrict__ ql,
               const __nv_bfloat16* __restrict__ kh,
               const __nv_bfloat16* __restrict__ kl,
               const __nv_bfloat16* __restrict__ vh,
               const __nv_bfloat16* __restrict__ vl,
               __nv_bfloat16* __restrict__ ahi,
               __nv_bfloat16* __restrict__ alo)
{
    extern __shared__ char sm[];
    const uint32_t sb = smem_u32(sm);
    const uint32_t qst = sb + 2*65536;       // Q staging = slot 2

    const int qt = (NS/128 - 1) - blockIdx.x;   // heavy tiles first
    const int h = blockIdx.y, b = blockIdx.z;
    const int t = threadIdx.x, lane = t & 31, w = t >> 5;
    const size_t hb = (size_t)(b*NH + h) * NS * NHD;

    const float L2E   = 1.4426950408889634f;
    const float scale = 0.08838834764831845f;          // 1/sqrt(128)
    const float slope = exp2f(-0.5f * (float)(h + 1)); // ALiBi, H=16
    const float c1  = scale * L2E;
    const float sl2 = slope * L2E;
    const float mc8 = -8.0f * L2E;
    const int r8 = lane & 7, m01 = (lane >> 3) & 1, m2 = lane >> 4;
    const int qr = lane >> 2, qc = (lane & 3) * 2;
    const int rg0 = qt*128 + w*16 + qr;                // global q row (c0/c1)

    // stage Q into slot 2
    #pragma unroll
    for (int u = 0; u < 8; u++) {
        int idx = t + 256*u;                 // 0..2047
        int row = idx >> 4, chunk = idx & 15;
        uint32_t soff = (uint32_t)(row*256 + SWZF(row, chunk));
        size_t g = hb + (size_t)(qt*128 + row)*NHD + chunk*8;
        cpa16(qst +         soff, qh + g);
        cpa16(qst + 32768 + soff, ql + g);
    }
    CP_COMMIT();                             // group: Q
    flash_load_kv(sb,         kh, kl, vh, vl, hb, 0, t);   // group: KV0
    flash_load_kv(sb + 65536, kh, kl, vh, vl, hb, 1, t);   // group: KV1

    CP_WAIT(2);                              // Q complete
    __syncthreads();

    // Q fragments -> registers (per warp: its own 16 rows, all 128 hd)
    uint32_t fqh[8][4], fql[8][4];
    {
        const int qrow = w*16 + m01*8 + r8;
        #pragma unroll
        for (int kc = 0; kc < 8; kc++) {
            uint32_t qa = qst + (uint32_t)(qrow*256 + SWZF(qrow, kc*2 + m2));
            ldsm4(fqh[kc], qa);
            ldsm4(fql[kc], qa + 32768);
        }
    }

    float l0 = 0.f, l1 = 0.f;
    float acc_o[16][4];
    #pragma unroll
    for (int i = 0; i < 16; i++)
        #pragma unroll
        for (int j = 0; j < 4; j++) acc_o[i][j] = 0.f;

    const int nkt = 2*qt + 2;
    for (int kt = 0; kt < nkt; kt++) {
        CP_WAIT(1);
        __syncthreads();
        // slot (kt+2)%3 was fully read in iter kt-1 (or was the Q staging,
        // whose reads precede the first barrier) — safe to refill now.
        if (kt + 2 < nkt)
            flash_load_kv(sb + (uint32_t)((kt + 2) % 3)*65536,
                          kh, kl, vh, vl, hb, kt + 2, t);
        else
            CP_COMMIT();

        const uint32_t st = sb + (uint32_t)(kt % 3)*65536;

        // ---- S = Q K^T (3-term) ----
        float s_[8][4];
        #pragma unroll
        for (int i = 0; i < 8; i++)
            #pragma unroll
            for (int j = 0; j < 4; j++) s_[i][j] = 0.f;

        #pragma unroll
        for (int kc = 0; kc < 8; kc++) {
            #pragma unroll
            for (int ng = 0; ng < 4; ng++) {
                int krow = ng*16 + m2*8 + r8;
                int kchk = kc*2 + m01;
                uint32_t ka = st + (uint32_t)(krow*256 + SWZF(krow, kchk));
                uint32_t rh[4], rl[4];
                ldsm4(rh, ka);
                ldsm4(rl, ka + 16384);
                mma16816(s_[ng*2+0], fqh[kc], rh);
                mma16816(s_[ng*2+0], fqh[kc], rl);
                mma16816(s_[ng*2+0], fql[kc], rh);
                mma16816(s_[ng*2+1], fqh[kc], rh+2);
                mma16816(s_[ng*2+1], fqh[kc], rl+2);
                mma16816(s_[ng*2+1], fql[kc], rh+2);
            }
        }

        // ---- static-max softmax: p = ex2(s*c1 + sl2*(col - r) - 8*L2E) ----
        const bool diag = (kt >= 2*qt);
        const float baseA = fmaf((float)(kt*64 + qc - rg0), sl2, mc8);
        const float baseB = baseA - 8.0f*sl2;   // rows rg0+8
        if (diag) {
            #pragma unroll
            for (int nt = 0; nt < 8; nt++) {
                #pragma unroll
                for (int jj = 0; jj < 2; jj++) {
                    const float cf = (float)(nt*8 + jj);
                    float a0 = fmaf(s_[nt][jj],     c1, fmaf(cf, sl2, baseA));
                    float a1 = fmaf(s_[nt][2 + jj], c1, fmaf(cf, sl2, baseB));
                    int col = kt*64 + nt*8 + qc + jj;
                    if (col > rg0)     a0 = -10000.f;
                    if (col > rg0 + 8) a1 = -10000.f;
                    float p0 = ex2f(a0), p1 = ex2f(a1);
                    l0 += p0; l1 += p1;
                    s_[nt][jj] = p0; s_[nt][2 + jj] = p1;
                }
            }
        } else {
            #pragma unroll
            for (int nt = 0; nt < 8; nt++) {
                #pragma unroll
                for (int jj = 0; jj < 2; jj++) {
                    const float cf = (float)(nt*8 + jj);
                    float a0 = fmaf(s_[nt][jj],     c1, fmaf(cf, sl2, baseA));
                    float a1 = fmaf(s_[nt][2 + jj], c1, fmaf(cf, sl2, baseB));
                    float p0 = ex2f(a0), p1 = ex2f(a1);
                    l0 += p0; l1 += p1;
                    s_[nt][jj] = p0; s_[nt][2 + jj] = p1;
                }
            }
        }

        // ---- O += P V (3-term) ----
        #pragma unroll
        for (int kc = 0; kc < 4; kc++) {
            uint32_t ph[4], pl[4];
            {
                const float* pa = s_[2*kc];
                const float* pb = s_[2*kc + 1];
                ph[0] = split_pair(pa[0], pa[1], pl[0]);
                ph[1] = split_pair(pa[2], pa[3], pl[1]);
                ph[2] = split_pair(pb[0], pb[1], pl[2]);
                ph[3] = split_pair(pb[2], pb[3], pl[3]);
            }
            #pragma unroll
            for (int ng = 0; ng < 8; ng++) {
                int vrow = kc*16 + m01*8 + r8;
                int vchk = ng*2 + m2;
                uint32_t va = st + 32768 + (uint32_t)(vrow*256 + SWZF(vrow, vchk));
                uint32_t wh[4], wl[4];
                ldsm4t(wh, va);
                ldsm4t(wl, va + 16384);
                mma16816(acc_o[ng*2+0], ph, wh);
                mma16816(acc_o[ng*2+0], ph, wl);
                mma16816(acc_o[ng*2+0], pl, wh);
                mma16816(acc_o[ng*2+1], ph, wh+2);
                mma16816(acc_o[ng*2+1], ph, wl+2);
                mma16816(acc_o[ng*2+1], pl, wh+2);
            }
        }
    }

    // ---- finalize ----
    l0 += __shfl_xor_sync(0xffffffffu, l0, 1);
    l0 += __shfl_xor_sync(0xffffffffu, l0, 2);
    l1 += __shfl_xor_sync(0xffffffffu, l1, 1);
    l1 += __shfl_xor_sync(0xffffffffu, l1, 2);
    const float inv0 = 1.f / l0, inv1 = 1.f / l1;

    const size_t row0 = (size_t)(b*NS) + qt*128 + w*16 + qr;
    #pragma unroll
    for (int nt = 0; nt < 16; nt++) {
        int col = h*NHD + nt*8 + qc;
        uint32_t lo0, lo1;
        uint32_t hi0 = split_pair(acc_o[nt][0]*inv0, acc_o[nt][1]*inv0, lo0);
        uint32_t hi1 = split_pair(acc_o[nt][2]*inv1, acc_o[nt][3]*inv1, lo1);
        *(uint32_t*)&ahi[row0 * ND + col]       = hi0;
        *(uint32_t*)&alo[row0 * ND + col]       = lo0;
        *(uint32_t*)&ahi[(row0 + 8) * ND + col] = hi1;
        *(uint32_t*)&alo[(row0 + 8) * ND + col] = lo1;
    }
}

// ---------------------------------------------------------------------------
extern "C" void kernel_launch(void* const* d_in, const int* in_sizes, int n_in,
                              void* d_out, int out_size)
{
    const float* x    = (const float*)d_in[0];
    const float* Wqkv = (const float*)d_in[1];
    const float* bqkv = (const float*)d_in[2];
    const float* Wout = (const float*)d_in[3];
    const float* bout = (const float*)d_in[4];
    float* out = (float*)d_out;

    __nv_bfloat16 *xhi, *xlo, *ahi, *alo, *wqh, *wql, *woh, *wol;
    __nv_bfloat16 *qh, *ql, *kh, *kl, *vh, *vl;
    cudaGetSymbolAddress((void**)&xhi,  g_xhi);
    cudaGetSymbolAddress((void**)&xlo,  g_xlo);
    cudaGetSymbolAddress((void**)&ahi,  g_ahi);
    cudaGetSymbolAddress((void**)&alo,  g_alo);
    cudaGetSymbolAddress((void**)&wqh,  g_wqT_hi);
    cudaGetSymbolAddress((void**)&wql,  g_wqT_lo);
    cudaGetSymbolAddress((void**)&woh,  g_woT_hi);
    cudaGetSymbolAddress((void**)&wol,  g_woT_lo);
    cudaGetSymbolAddress((void**)&qh,   g_qh);
    cudaGetSymbolAddress((void**)&ql,   g_ql);
    cudaGetSymbolAddress((void**)&kh,   g_kh);
    cudaGetSymbolAddress((void**)&kl,   g_kl);
    cudaGetSymbolAddress((void**)&vh,   g_vh);
    cudaGetSymbolAddress((void**)&vl,   g_vl);

    cudaFuncSetAttribute(gemm_mma<0>,
                         cudaFuncAttributeMaxDynamicSharedMemorySize, GEMM_SMEM);
    cudaFuncSetAttribute(gemm_mma<1>,
                         cudaFuncAttributeMaxDynamicSharedMemorySize, GEMM_SMEM);
    cudaFuncSetAttribute(flash_mma,
                         cudaFuncAttributeMaxDynamicSharedMemorySize, FLASH_SMEM);

    // operand conversions
    cvt_split<<<(ROWS*(size_t)ND/4 + 255)/256, 256>>>(
        (const float4*)x, (uint2*)xhi, (uint2*)xlo);
    cvt_split_T<<<dim3(QKV_COLS/32, ND/32), dim3(32, 8)>>>(Wqkv, wqh, wql, ND, QKV_COLS);
    cvt_split_T<<<dim3(ND/32, ND/32), dim3(32, 8)>>>(Wout, woh, wol, ND, ND);

    // qkv = x @ Wqkv + b_qkv, written directly as split per-head q/k/v
    gemm_mma<1><<<dim3(QKV_COLS/128, ROWS/128), 256, GEMM_SMEM>>>(
        xhi, xlo, wqh, wql, bqkv, nullptr,
        qh, ql, kh, kl, vh, vl, ROWS, QKV_COLS, ND);

    // attention -> writes proj A-operand (hi/lo) directly
    flash_mma<<<dim3(NS/128, NH, NB), 256, FLASH_SMEM>>>(
        qh, ql, kh, kl, vh, vl, ahi, alo);

    // out = attn @ Wout + b_out
    gemm_mma<0><<<dim3(ND/128, ROWS/128), 256, GEMM_SMEM>>>(
        ahi, alo, woh, wol, bout, out,
        nullptr, nullptr, nullptr, nullptr, nullptr, nullptr, ROWS, ND, ND);
}

// round 9
// speedup vs baseline: 3.4280x; 1.0102x over previous
#include <cuda_runtime.h>
#include <cuda_bf16.h>
#include <cstdint>
#include <math.h>

#define NB 4
#define NS 2048
#define ND 2048
#define NH 16
#define NHD 128
#define ROWS (NB*NS)        /* 8192 */
#define QKV_COLS (3*ND)     /* 6144 */

// ---------------- scratch (device globals: allocation-free rule) ----------
__device__ __nv_bfloat16 g_xhi[(size_t)ROWS * ND];
__device__ __nv_bfloat16 g_xlo[(size_t)ROWS * ND];
__device__ __nv_bfloat16 g_ahi[(size_t)ROWS * ND];         // attn out hi
__device__ __nv_bfloat16 g_alo[(size_t)ROWS * ND];         // attn out lo
__device__ __nv_bfloat16 g_wqT_hi[(size_t)QKV_COLS * ND];  // Wqkv^T [6144][2048]
__device__ __nv_bfloat16 g_wqT_lo[(size_t)QKV_COLS * ND];
__device__ __nv_bfloat16 g_woT_hi[(size_t)ND * ND];        // Wout^T [2048][2048]
__device__ __nv_bfloat16 g_woT_lo[(size_t)ND * ND];
// per-head split QKV: [B*H][S][HD]
__device__ __nv_bfloat16 g_qh[(size_t)ROWS * ND];
__device__ __nv_bfloat16 g_ql[(size_t)ROWS * ND];
__device__ __nv_bfloat16 g_kh[(size_t)ROWS * ND];
__device__ __nv_bfloat16 g_kl[(size_t)ROWS * ND];
__device__ __nv_bfloat16 g_vh[(size_t)ROWS * ND];
__device__ __nv_bfloat16 g_vl[(size_t)ROWS * ND];

// ---------------- PTX helpers (baseline features only: sm_80+) ------------
__device__ __forceinline__ uint32_t smem_u32(const void* p) {
    uint32_t a;
    asm("{ .reg .u64 t; cvta.to.shared.u64 t, %1; cvt.u32.u64 %0, t; }"
        : "=r"(a) : "l"(p));
    return a;
}

__device__ __forceinline__ void cpa16(uint32_t s, const void* g) {
    asm volatile("cp.async.cg.shared.global [%0], [%1], 16;" :: "r"(s), "l"(g));
}
#define CP_COMMIT() asm volatile("cp.async.commit_group;" ::: "memory")
#define CP_WAIT(n)  asm volatile("cp.async.wait_group %0;" :: "n"(n) : "memory")

__device__ __forceinline__ void ldsm4(uint32_t* r, uint32_t addr) {
    asm volatile("ldmatrix.sync.aligned.m8n8.x4.shared.b16 {%0,%1,%2,%3}, [%4];"
                 : "=r"(r[0]), "=r"(r[1]), "=r"(r[2]), "=r"(r[3]) : "r"(addr));
}
__device__ __forceinline__ void ldsm4t(uint32_t* r, uint32_t addr) {
    asm volatile("ldmatrix.sync.aligned.m8n8.x4.trans.shared.b16 {%0,%1,%2,%3}, [%4];"
                 : "=r"(r[0]), "=r"(r[1]), "=r"(r[2]), "=r"(r[3]) : "r"(addr));
}

__device__ __forceinline__ void mma16816(float* d, const uint32_t* a,
                                         const uint32_t* b) {
    asm volatile(
        "mma.sync.aligned.m16n8k16.row.col.f32.bf16.bf16.f32 "
        "{%0,%1,%2,%3}, {%4,%5,%6,%7}, {%8,%9}, {%0,%1,%2,%3};"
        : "+f"(d[0]), "+f"(d[1]), "+f"(d[2]), "+f"(d[3])
        : "r"(a[0]), "r"(a[1]), "r"(a[2]), "r"(a[3]), "r"(b[0]), "r"(b[1]));
}

__device__ __forceinline__ float ex2f(float x) {
    float y;
    asm("ex2.approx.f32 %0, %1;" : "=f"(y) : "f"(x));
    return y;
}

#define PACK2(lo16, hi16) (((uint32_t)(hi16) << 16) | (uint32_t)(lo16))
#define BFU(x) __bfloat16_as_ushort(x)

__device__ __forceinline__ uint32_t split_pair(float a, float b, uint32_t& lo) {
    __nv_bfloat16 h0 = __float2bfloat16(a), h1 = __float2bfloat16(b);
    __nv_bfloat16 e0 = __float2bfloat16(a - __bfloat162float(h0));
    __nv_bfloat16 e1 = __float2bfloat16(b - __bfloat162float(h1));
    lo = PACK2(BFU(e0), BFU(e1));
    return PACK2(BFU(h0), BFU(h1));
}

// ---------------------------------------------------------------------------
// conversion kernels
// ---------------------------------------------------------------------------
__global__ void cvt_split(const float4* __restrict__ in, uint2* __restrict__ hi,
                          uint2* __restrict__ lo)
{
    int i = blockIdx.x * blockDim.x + threadIdx.x;
    float4 v = in[i];
    uint2 uh, ul;
    uh.x = split_pair(v.x, v.y, ul.x);
    uh.y = split_pair(v.z, v.w, ul.y);
    hi[i] = uh;
    lo[i] = ul;
}

// W [K][N] fp32  ->  T [N][K] bf16 hi/lo
__global__ void cvt_split_T(const float* __restrict__ W,
                            __nv_bfloat16* __restrict__ Thi,
                            __nv_bfloat16* __restrict__ Tlo, int K, int N)
{
    __shared__ float tile[32][33];
    int n0 = blockIdx.x * 32, k0 = blockIdx.y * 32;
    int tx = threadIdx.x, ty = threadIdx.y;  // 32 x 8
    #pragma unroll
    for (int r = 0; r < 4; r++)
        tile[ty + r*8][tx] = W[(size_t)(k0 + ty + r*8) * N + n0 + tx];
    __syncthreads();
    #pragma unroll
    for (int r = 0; r < 4; r++) {
        float v = tile[tx][ty + r*8];
        __nv_bfloat16 h = __float2bfloat16(v);
        __nv_bfloat16 l = __float2bfloat16(v - __bfloat162float(h));
        size_t o = (size_t)(n0 + ty + r*8) * K + k0 + tx;
        Thi[o] = h;
        Tlo[o] = l;
    }
}

// ---------------------------------------------------------------------------
// bf16x3 GEMM via mma.sync. EPI=0: fp32 C + bias. EPI=1: split per-head QKV.
// CTA 128x128, BK=32, 8 warps (2m x 4n), warp tile 64x32, 3-stage cp.async,
// 96KB smem -> 2 CTAs/SM. Register-stage software pipeline: B frags resident
// per ks-half, A frags double-buffered across the fm loop.
// ---------------------------------------------------------------------------
#define STAGES 3
#define STAGE_BYTES 32768      /* Ahi 8K | Alo 8K | Bhi 8K | Blo 8K */
#define GEMM_SMEM (STAGES * STAGE_BYTES)   /* 96 KB */
#define SWZ(row, kb) ((kb) ^ ((((row) >> 1) & 3) << 4))

__device__ __forceinline__ void issue_stage(
    uint32_t sb_stage, const __nv_bfloat16* __restrict__ Ahi,
    const __nv_bfloat16* __restrict__ Alo,
    const __nv_bfloat16* __restrict__ Bhi,
    const __nv_bfloat16* __restrict__ Blo,
    int rowBase, int colBase, int k0, int K, int t)
{
    #pragma unroll
    for (int u = 0; u < 2; u++) {
        int idx = t + 256*u;
        int row = idx >> 2, chunk = idx & 3;
        uint32_t soff = (uint32_t)(row*64 + SWZ(row, chunk*16));
        size_t geA = (size_t)(rowBase + row) * K + k0 + chunk*8;
        size_t geB = (size_t)(colBase + row) * K + k0 + chunk*8;
        cpa16(sb_stage +         soff, Ahi + geA);
        cpa16(sb_stage +  8192 + soff, Alo + geA);
        cpa16(sb_stage + 16384 + soff, Bhi + geB);
        cpa16(sb_stage + 24576 + soff, Blo + geB);
    }
    CP_COMMIT();
}

template<int EPI>
__global__ __launch_bounds__(256, 2)
void gemm_mma(const __nv_bfloat16* __restrict__ Ahi,
              const __nv_bfloat16* __restrict__ Alo,
              const __nv_bfloat16* __restrict__ Bhi,
              const __nv_bfloat16* __restrict__ Blo,
              const float* __restrict__ bias, float* __restrict__ C,
              __nv_bfloat16* __restrict__ q_h, __nv_bfloat16* __restrict__ q_l,
              __nv_bfloat16* __restrict__ k_h, __nv_bfloat16* __restrict__ k_l,
              __nv_bfloat16* __restrict__ v_h, __nv_bfloat16* __restrict__ v_l,
              int M, int N, int K)
{
    extern __shared__ char sm[];
    const uint32_t sb = smem_u32(sm);

    const int t = threadIdx.x, lane = t & 31, w = t >> 5;
    const int warp_m = w & 1, warp_n = w >> 1;   // 2 x 4
    const int rowBase = blockIdx.y * 128;
    const int colBase = blockIdx.x * 128;
    const int ksteps  = K >> 5;
    const int mat = lane >> 3, r8 = lane & 7;

    float acc[4][4][4];
    #pragma unroll
    for (int i = 0; i < 4; i++)
        #pragma unroll
        for (int j = 0; j < 4; j++)
            #pragma unroll
            for (int q = 0; q < 4; q++) acc[i][j][q] = 0.f;

    issue_stage(sb,               Ahi, Alo, Bhi, Blo, rowBase, colBase, 0,  K, t);
    issue_stage(sb + STAGE_BYTES, Ahi, Alo, Bhi, Blo, rowBase, colBase, 32, K, t);

    int rowA[4], rowB[2];
    #pragma unroll
    for (int fm = 0; fm < 4; fm++)
        rowA[fm] = warp_m*64 + fm*16 + (mat & 1)*8 + r8;
    #pragma unroll
    for (int fb = 0; fb < 2; fb++)
        rowB[fb] = warp_n*32 + fb*16 + (mat >> 1)*8 + r8;

    for (int i = 0; i < ksteps; i++) {
        CP_WAIT(1);
        __syncthreads();
        const uint32_t st = sb + (uint32_t)(i % 3) * STAGE_BYTES;

        #pragma unroll
        for (int ks = 0; ks < 2; ks++) {
            const int kbA = ks*32 + (mat >> 1)*16;
            const int kbB = ks*32 + (mat & 1)*16;

            // B fragments for both fb resident for the whole ks-half
            uint32_t rh[2][4], rl[2][4];
            #pragma unroll
            for (int fb = 0; fb < 2; fb++) {
                uint32_t off = (uint32_t)(rowB[fb]*64 + SWZ(rowB[fb], kbB));
                ldsm4(rh[fb], st + 16384 + off);
                ldsm4(rl[fb], st + 24576 + off);
            }
            // A fragments double-buffered across fm
            uint32_t ahc[2][4], alc[2][4];
            {
                uint32_t off = (uint32_t)(rowA[0]*64 + SWZ(rowA[0], kbA));
                ldsm4(ahc[0], st +        off);
                ldsm4(alc[0], st + 8192 + off);
            }
            // refill next stage once per k-step, overlapped with ldsm latency;
            // slot (i+2)%3 == (i-1)%3 was fully read before this iter's barrier
            if (ks == 0) {
                if (i + 2 < ksteps)
                    issue_stage(sb + (uint32_t)((i + 2) % 3) * STAGE_BYTES,
                                Ahi, Alo, Bhi, Blo, rowBase, colBase,
                                (i + 2)*32, K, t);
                else
                    CP_COMMIT();   // keep group accounting uniform
            }

            #pragma unroll
            for (int fm = 0; fm < 4; fm++) {
                const int cur = fm & 1;
                if (fm < 3) {
                    uint32_t off = (uint32_t)(rowA[fm+1]*64 +
                                              SWZ(rowA[fm+1], kbA));
                    ldsm4(ahc[cur^1], st +        off);
                    ldsm4(alc[cur^1], st + 8192 + off);
                }
                #pragma unroll
                for (int fb = 0; fb < 2; fb++) {
                    mma16816(acc[fm][2*fb+0], ahc[cur], rh[fb]);
                    mma16816(acc[fm][2*fb+0], ahc[cur], rl[fb]);
                    mma16816(acc[fm][2*fb+0], alc[cur], rh[fb]);
                    mma16816(acc[fm][2*fb+1], ahc[cur], rh[fb]+2);
                    mma16816(acc[fm][2*fb+1], ahc[cur], rl[fb]+2);
                    mma16816(acc[fm][2*fb+1], alc[cur], rh[fb]+2);
                }
            }
        }
    }

    const int qrow = lane >> 2, qcol = (lane & 3) * 2;
    #pragma unroll
    for (int fn = 0; fn < 4; fn++) {
        const int col = colBase + warp_n*32 + fn*8 + qcol;
        const float b0 = bias[col], b1 = bias[col + 1];
        if (EPI == 0) {
            #pragma unroll
            for (int fm = 0; fm < 4; fm++) {
                const int row0 = rowBase + warp_m*64 + fm*16 + qrow;
                float2 v0 = make_float2(acc[fm][fn][0] + b0, acc[fm][fn][1] + b1);
                float2 v1 = make_float2(acc[fm][fn][2] + b0, acc[fm][fn][3] + b1);
                *(float2*)&C[(size_t)row0 * N + col]       = v0;
                *(float2*)&C[(size_t)(row0 + 8) * N + col] = v1;
            }
        } else {
            const int sel = col >> 11, hh = (col >> 7) & 15, hd = col & 127;
            __nv_bfloat16* dh = (sel == 0) ? q_h : (sel == 1) ? k_h : v_h;
            __nv_bfloat16* dl = (sel == 0) ? q_l : (sel == 1) ? k_l : v_l;
            #pragma unroll
            for (int fm = 0; fm < 4; fm++) {
                const int r0 = rowBase + warp_m*64 + fm*16 + qrow;
                #pragma unroll
                for (int rr = 0; rr < 2; rr++) {
                    const int r = r0 + rr*8;
                    float va = acc[fm][fn][rr*2+0] + b0;
                    float vb = acc[fm][fn][rr*2+1] + b1;
                    uint32_t lo, hi = split_pair(va, vb, lo);
                    size_t o = (((size_t)((r >> 11)*NH + hh) * NS +
                                 (r & 2047)) * NHD + hd);
                    *(uint32_t*)&dh[o] = hi;
                    *(uint32_t*)&dl[o] = lo;
                }
            }
        }
    }
}

// ---------------------------------------------------------------------------
// Flash attention via mma.sync, bf16x3 emulation, ALiBi + causal.
// Static-max softmax (R7). Heavy tiles first. Register-stage pipelining of
// K/V fragments (prefetch next ng during current ng's mma).
// ---------------------------------------------------------------------------
#define FLASH_SMEM (3*65536)   /* 196608 */
#define SWZF(row, chunk) (((chunk) ^ ((row) & 7)) << 4)

__device__ __forceinline__ void flash_load_kv(
    uint32_t st, const __nv_bfloat16* __restrict__ kh,
    const __nv_bfloat16* __restrict__ kl,
    const __nv_bfloat16* __restrict__ vh,
    const __nv_bfloat16* __restrict__ vl,
    size_t hb, int kt, int t)
{
    #pragma unroll
    for (int u = 0; u < 4; u++) {
        int idx = t + 256*u;                 // 0..1023
        int row = idx >> 4, chunk = idx & 15;
        uint32_t soff = (uint32_t)(row*256 + SWZF(row, chunk));
        size_t g = hb + (size_t)(kt*64 + row)*NHD + chunk*8;
        cpa16(st +         soff, kh + g);
        cpa16(st + 16384 + soff, kl + g);
        cpa16(st + 32768 + soff, vh + g);
        cpa16(st + 49152 + soff, vl + g);
    }
    CP_COMMIT();
}

__global__ __launch_bounds__(256, 1)
void flash_mma(const __nv_bfloat16* __restrict__ qh,
               const __nv_bfloat16* __restrict__ ql,
               const __nv_bfloat16* __restrict__ kh,
               const __nv_bfloat16* __restrict__ kl,
               const __nv_bfloat16* __restrict__ vh,
               const __nv_bfloat16* __restrict__ vl,
               __nv_bfloat16* __restrict__ ahi,
               __nv_bfloat16* __restrict__ alo)
{
    extern __shared__ char sm[];
    const uint32_t sb = smem_u32(sm);
    const uint32_t qst = sb + 2*65536;       // Q staging = slot 2

    const int qt = (NS/128 - 1) - blockIdx.x;   // heavy tiles first
    const int h = blockIdx.y, b = blockIdx.z;
    const int t = threadIdx.x, lane = t & 31, w = t >> 5;
    const size_t hb = (size_t)(b*NH + h) * NS * NHD;

    const float L2E   = 1.4426950408889634f;
    const float scale = 0.08838834764831845f;          // 1/sqrt(128)
    const float slope = exp2f(-0.5f * (float)(h + 1)); // ALiBi, H=16
    const float c1  = scale * L2E;
    const float sl2 = slope * L2E;
    const float mc8 = -8.0f * L2E;
    const int r8 = lane & 7, m01 = (lane >> 3) & 1, m2 = lane >> 4;
    const int qr = lane >> 2, qc = (lane & 3) * 2;
    const int rg0 = qt*128 + w*16 + qr;                // global q row (c0/c1)

    // stage Q into slot 2
    #pragma unroll
    for (int u = 0; u < 8; u++) {
        int idx = t + 256*u;                 // 0..2047
        int row = idx >> 4, chunk = idx & 15;
        uint32_t soff = (uint32_t)(row*256 + SWZF(row, chunk));
        size_t g = hb + (size_t)(qt*128 + row)*NHD + chunk*8;
        cpa16(qst +         soff, qh + g);
        cpa16(qst + 32768 + soff, ql + g);
    }
    CP_COMMIT();                             // group: Q
    flash_load_kv(sb,         kh, kl, vh, vl, hb, 0, t);   // group: KV0
    flash_load_kv(sb + 65536, kh, kl, vh, vl, hb, 1, t);   // group: KV1

    CP_WAIT(2);                              // Q complete
    __syncthreads();

    // Q fragments -> registers (per warp: its own 16 rows, all 128 hd)
    uint32_t fqh[8][4], fql[8][4];
    {
        const int qrow = w*16 + m01*8 + r8;
        #pragma unroll
        for (int kc = 0; kc < 8; kc++) {
            uint32_t qa = qst + (uint32_t)(qrow*256 + SWZF(qrow, kc*2 + m2));
            ldsm4(fqh[kc], qa);
            ldsm4(fql[kc], qa + 32768);
        }
    }

    float l0 = 0.f, l1 = 0.f;
    float acc_o[16][4];
    #pragma unroll
    for (int i = 0; i < 16; i++)
        #pragma unroll
        for (int j = 0; j < 4; j++) acc_o[i][j] = 0.f;

    const int nkt = 2*qt + 2;
    for (int kt = 0; kt < nkt; kt++) {
        CP_WAIT(1);
        __syncthreads();
        const uint32_t st = sb + (uint32_t)(kt % 3)*65536;

        // ---- S = Q K^T (3-term), K frags double-buffered over ng ----
        float s_[8][4];
        #pragma unroll
        for (int i = 0; i < 8; i++)
            #pragma unroll
            for (int j = 0; j < 4; j++) s_[i][j] = 0.f;

        #pragma unroll
        for (int kc = 0; kc < 8; kc++) {
            const int kchk = kc*2 + m01;
            uint32_t rh[2][4], rl[2][4];
            {
                int krow = m2*8 + r8;                // ng = 0
                uint32_t ka = st + (uint32_t)(krow*256 + SWZF(krow, kchk));
                ldsm4(rh[0], ka);
                ldsm4(rl[0], ka + 16384);
            }
            if (kc == 0) {
                // refill: slot (kt+2)%3 was fully read in iter kt-1 (or was
                // Q staging, read before the first barrier) — safe now.
                if (kt + 2 < nkt)
                    flash_load_kv(sb + (uint32_t)((kt + 2) % 3)*65536,
                                  kh, kl, vh, vl, hb, kt + 2, t);
                else
                    CP_COMMIT();
            }
            #pragma unroll
            for (int ng = 0; ng < 4; ng++) {
                const int cur = ng & 1;
                if (ng < 3) {
                    int krow = (ng+1)*16 + m2*8 + r8;
                    uint32_t ka = st + (uint32_t)(krow*256 + SWZF(krow, kchk));
                    ldsm4(rh[cur^1], ka);
                    ldsm4(rl[cur^1], ka + 16384);
                }
                mma16816(s_[ng*2+0], fqh[kc], rh[cur]);
                mma16816(s_[ng*2+0], fqh[kc], rl[cur]);
                mma16816(s_[ng*2+0], fql[kc], rh[cur]);
                mma16816(s_[ng*2+1], fqh[kc], rh[cur]+2);
                mma16816(s_[ng*2+1], fqh[kc], rl[cur]+2);
                mma16816(s_[ng*2+1], fql[kc], rh[cur]+2);
            }
        }

        // ---- static-max softmax: p = ex2(s*c1 + sl2*(col - r) - 8*L2E) ----
        const bool diag = (kt >= 2*qt);
        const float baseA = fmaf((float)(kt*64 + qc - rg0), sl2, mc8);
        const float baseB = baseA - 8.0f*sl2;   // rows rg0+8
        if (diag) {
            #pragma unroll
            for (int nt = 0; nt < 8; nt++) {
                #pragma unroll
                for (int jj = 0; jj < 2; jj++) {
                    const float cf = (float)(nt*8 + jj);
                    float a0 = fmaf(s_[nt][jj],     c1, fmaf(cf, sl2, baseA));
                    float a1 = fmaf(s_[nt][2 + jj], c1, fmaf(cf, sl2, baseB));
                    int col = kt*64 + nt*8 + qc + jj;
                    if (col > rg0)     a0 = -10000.f;
                    if (col > rg0 + 8) a1 = -10000.f;
                    float p0 = ex2f(a0), p1 = ex2f(a1);
                    l0 += p0; l1 += p1;
                    s_[nt][jj] = p0; s_[nt][2 + jj] = p1;
                }
            }
        } else {
            #pragma unroll
            for (int nt = 0; nt < 8; nt++) {
                #pragma unroll
                for (int jj = 0; jj < 2; jj++) {
                    const float cf = (float)(nt*8 + jj);
                    float a0 = fmaf(s_[nt][jj],     c1, fmaf(cf, sl2, baseA));
                    float a1 = fmaf(s_[nt][2 + jj], c1, fmaf(cf, sl2, baseB));
                    float p0 = ex2f(a0), p1 = ex2f(a1);
                    l0 += p0; l1 += p1;
                    s_[nt][jj] = p0; s_[nt][2 + jj] = p1;
                }
            }
        }

        // ---- O += P V (3-term), V frags double-buffered over ng ----
        #pragma unroll
        for (int kc = 0; kc < 4; kc++) {
            uint32_t ph[4], pl[4];
            {
                const float* pa = s_[2*kc];
                const float* pb = s_[2*kc + 1];
                ph[0] = split_pair(pa[0], pa[1], pl[0]);
                ph[1] = split_pair(pa[2], pa[3], pl[1]);
                ph[2] = split_pair(pb[0], pb[1], pl[2]);
                ph[3] = split_pair(pb[2], pb[3], pl[3]);
            }
            const int vrow = kc*16 + m01*8 + r8;
            const uint32_t vbase = st + 32768 + (uint32_t)(vrow*256);
            uint32_t wh[2][4], wl[2][4];
            {
                uint32_t va = vbase + (uint32_t)SWZF(vrow, m2);   // ng = 0
                ldsm4t(wh[0], va);
                ldsm4t(wl[0], va + 16384);
            }
            #pragma unroll
            for (int ng = 0; ng < 8; ng++) {
                const int cur = ng & 1;
                if (ng < 7) {
                    uint32_t va = vbase + (uint32_t)SWZF(vrow, (ng+1)*2 + m2);
                    ldsm4t(wh[cur^1], va);
                    ldsm4t(wl[cur^1], va + 16384);
                }
                mma16816(acc_o[ng*2+0], ph, wh[cur]);
                mma16816(acc_o[ng*2+0], ph, wl[cur]);
                mma16816(acc_o[ng*2+0], pl, wh[cur]);
                mma16816(acc_o[ng*2+1], ph, wh[cur]+2);
                mma16816(acc_o[ng*2+1], ph, wl[cur]+2);
                mma16816(acc_o[ng*2+1], pl, wh[cur]+2);
            }
        }
    }

    // ---- finalize ----
    l0 += __shfl_xor_sync(0xffffffffu, l0, 1);
    l0 += __shfl_xor_sync(0xffffffffu, l0, 2);
    l1 += __shfl_xor_sync(0xffffffffu, l1, 1);
    l1 += __shfl_xor_sync(0xffffffffu, l1, 2);
    const float inv0 = 1.f / l0, inv1 = 1.f / l1;

    const size_t row0 = (size_t)(b*NS) + qt*128 + w*16 + qr;
    #pragma unroll
    for (int nt = 0; nt < 16; nt++) {
        int col = h*NHD + nt*8 + qc;
        uint32_t lo0, lo1;
        uint32_t hi0 = split_pair(acc_o[nt][0]*inv0, acc_o[nt][1]*inv0, lo0);
        uint32_t hi1 = split_pair(acc_o[nt][2]*inv1, acc_o[nt][3]*inv1, lo1);
        *(uint32_t*)&ahi[row0 * ND + col]       = hi0;
        *(uint32_t*)&alo[row0 * ND + col]       = lo0;
        *(uint32_t*)&ahi[(row0 + 8) * ND + col] = hi1;
        *(uint32_t*)&alo[(row0 + 8) * ND + col] = lo1;
    }
}

// ---------------------------------------------------------------------------
extern "C" void kernel_launch(void* const* d_in, const int* in_sizes, int n_in,
                              void* d_out, int out_size)
{
    const float* x    = (const float*)d_in[0];
    const float* Wqkv = (const float*)d_in[1];
    const float* bqkv = (const float*)d_in[2];
    const float* Wout = (const float*)d_in[3];
    const float* bout = (const float*)d_in[4];
    float* out = (float*)d_out;

    __nv_bfloat16 *xhi, *xlo, *ahi, *alo, *wqh, *wql, *woh, *wol;
    __nv_bfloat16 *qh, *ql, *kh, *kl, *vh, *vl;
    cudaGetSymbolAddress((void**)&xhi,  g_xhi);
    cudaGetSymbolAddress((void**)&xlo,  g_xlo);
    cudaGetSymbolAddress((void**)&ahi,  g_ahi);
    cudaGetSymbolAddress((void**)&alo,  g_alo);
    cudaGetSymbolAddress((void**)&wqh,  g_wqT_hi);
    cudaGetSymbolAddress((void**)&wql,  g_wqT_lo);
    cudaGetSymbolAddress((void**)&woh,  g_woT_hi);
    cudaGetSymbolAddress((void**)&wol,  g_woT_lo);
    cudaGetSymbolAddress((void**)&qh,   g_qh);
    cudaGetSymbolAddress((void**)&ql,   g_ql);
    cudaGetSymbolAddress((void**)&kh,   g_kh);
    cudaGetSymbolAddress((void**)&kl,   g_kl);
    cudaGetSymbolAddress((void**)&vh,   g_vh);
    cudaGetSymbolAddress((void**)&vl,   g_vl);

    cudaFuncSetAttribute(gemm_mma<0>,
                         cudaFuncAttributeMaxDynamicSharedMemorySize, GEMM_SMEM);
    cudaFuncSetAttribute(gemm_mma<1>,
                         cudaFuncAttributeMaxDynamicSharedMemorySize, GEMM_SMEM);
    cudaFuncSetAttribute(flash_mma,
                         cudaFuncAttributeMaxDynamicSharedMemorySize, FLASH_SMEM);

    // operand conversions
    cvt_split<<<(ROWS*(size_t)ND/4 + 255)/256, 256>>>(
        (const float4*)x, (uint2*)xhi, (uint2*)xlo);
    cvt_split_T<<<dim3(QKV_COLS/32, ND/32), dim3(32, 8)>>>(Wqkv, wqh, wql, ND, QKV_COLS);
    cvt_split_T<<<dim3(ND/32, ND/32), dim3(32, 8)>>>(Wout, woh, wol, ND, ND);

    // qkv = x @ Wqkv + b_qkv, written directly as split per-head q/k/v
    gemm_mma<1><<<dim3(QKV_COLS/128, ROWS/128), 256, GEMM_SMEM>>>(
        xhi, xlo, wqh, wql, bqkv, nullptr,
        qh, ql, kh, kl, vh, vl, ROWS, QKV_COLS, ND);

    // attention -> writes proj A-operand (hi/lo) directly
    flash_mma<<<dim3(NS/128, NH, NB), 256, FLASH_SMEM>>>(
        qh, ql, kh, kl, vh, vl, ahi, alo);

    // out = attn @ Wout + b_out
    gemm_mma<0><<<dim3(ND/128, ROWS/128), 256, GEMM_SMEM>>>(
        ahi, alo, woh, wol, bout, out,
        nullptr, nullptr, nullptr, nullptr, nullptr, nullptr, ROWS, ND, ND);
}

// round 10
// speedup vs baseline: 4.3481x; 1.2684x over previous
#include <cuda_runtime.h>
#include <cuda_bf16.h>
#include <cuda_fp16.h>
#include <cstdint>
#include <math.h>

#define NB 4
#define NS 2048
#define ND 2048
#define NH 16
#define NHD 128
#define ROWS (NB*NS)        /* 8192 */
#define QKV_COLS (3*ND)     /* 6144 */

// ---------------- scratch (device globals: allocation-free rule) ----------
__device__ __half g_xhi[(size_t)ROWS * ND];
__device__ __half g_xlo[(size_t)ROWS * ND];
__device__ __half g_ahi[(size_t)ROWS * ND];                // attn out hi
__device__ __half g_alo[(size_t)ROWS * ND];                // attn out lo
__device__ __half g_wqT[(size_t)QKV_COLS * ND];            // Wqkv^T [6144][2048]
__device__ __half g_woT[(size_t)ND * ND];                  // Wout^T [2048][2048]
// per-head split QKV (bf16 x3 path for attention): [B*H][S][HD]
__device__ __nv_bfloat16 g_qh[(size_t)ROWS * ND];
__device__ __nv_bfloat16 g_ql[(size_t)ROWS * ND];
__device__ __nv_bfloat16 g_kh[(size_t)ROWS * ND];
__device__ __nv_bfloat16 g_kl[(size_t)ROWS * ND];
__device__ __nv_bfloat16 g_vh[(size_t)ROWS * ND];
__device__ __nv_bfloat16 g_vl[(size_t)ROWS * ND];

// ---------------- PTX helpers (baseline features only: sm_80+) ------------
__device__ __forceinline__ uint32_t smem_u32(const void* p) {
    uint32_t a;
    asm("{ .reg .u64 t; cvta.to.shared.u64 t, %1; cvt.u32.u64 %0, t; }"
        : "=r"(a) : "l"(p));
    return a;
}

__device__ __forceinline__ void cpa16(uint32_t s, const void* g) {
    asm volatile("cp.async.cg.shared.global [%0], [%1], 16;" :: "r"(s), "l"(g));
}
#define CP_COMMIT() asm volatile("cp.async.commit_group;" ::: "memory")
#define CP_WAIT(n)  asm volatile("cp.async.wait_group %0;" :: "n"(n) : "memory")

__device__ __forceinline__ void ldsm4(uint32_t* r, uint32_t addr) {
    asm volatile("ldmatrix.sync.aligned.m8n8.x4.shared.b16 {%0,%1,%2,%3}, [%4];"
                 : "=r"(r[0]), "=r"(r[1]), "=r"(r[2]), "=r"(r[3]) : "r"(addr));
}
__device__ __forceinline__ void ldsm4t(uint32_t* r, uint32_t addr) {
    asm volatile("ldmatrix.sync.aligned.m8n8.x4.trans.shared.b16 {%0,%1,%2,%3}, [%4];"
                 : "=r"(r[0]), "=r"(r[1]), "=r"(r[2]), "=r"(r[3]) : "r"(addr));
}

// bf16 mma (attention path)
__device__ __forceinline__ void mma16816(float* d, const uint32_t* a,
                                         const uint32_t* b) {
    asm volatile(
        "mma.sync.aligned.m16n8k16.row.col.f32.bf16.bf16.f32 "
        "{%0,%1,%2,%3}, {%4,%5,%6,%7}, {%8,%9}, {%0,%1,%2,%3};"
        : "+f"(d[0]), "+f"(d[1]), "+f"(d[2]), "+f"(d[3])
        : "r"(a[0]), "r"(a[1]), "r"(a[2]), "r"(a[3]), "r"(b[0]), "r"(b[1]));
}
// fp16 mma (GEMM path)
__device__ __forceinline__ void mma16816h(float* d, const uint32_t* a,
                                          const uint32_t* b) {
    asm volatile(
        "mma.sync.aligned.m16n8k16.row.col.f32.f16.f16.f32 "
        "{%0,%1,%2,%3}, {%4,%5,%6,%7}, {%8,%9}, {%0,%1,%2,%3};"
        : "+f"(d[0]), "+f"(d[1]), "+f"(d[2]), "+f"(d[3])
        : "r"(a[0]), "r"(a[1]), "r"(a[2]), "r"(a[3]), "r"(b[0]), "r"(b[1]));
}

__device__ __forceinline__ float ex2f(float x) {
    float y;
    asm("ex2.approx.f32 %0, %1;" : "=f"(y) : "f"(x));
    return y;
}

#define PACK2(lo16, hi16) (((uint32_t)(hi16) << 16) | (uint32_t)(lo16))
#define BFU(x) __bfloat16_as_ushort(x)
#define HFU(x) __half_as_ushort(x)

// bf16 split (attention)
__device__ __forceinline__ uint32_t split_pair(float a, float b, uint32_t& lo) {
    __nv_bfloat16 h0 = __float2bfloat16(a), h1 = __float2bfloat16(b);
    __nv_bfloat16 e0 = __float2bfloat16(a - __bfloat162float(h0));
    __nv_bfloat16 e1 = __float2bfloat16(b - __bfloat162float(h1));
    lo = PACK2(BFU(e0), BFU(e1));
    return PACK2(BFU(h0), BFU(h1));
}
// fp16 split (GEMM A-operand)
__device__ __forceinline__ uint32_t split_pair_h(float a, float b, uint32_t& lo) {
    __half h0 = __float2half_rn(a), h1 = __float2half_rn(b);
    __half e0 = __float2half_rn(a - __half2float(h0));
    __half e1 = __float2half_rn(b - __half2float(h1));
    lo = PACK2(HFU(e0), HFU(e1));
    return PACK2(HFU(h0), HFU(h1));
}

// ---------------------------------------------------------------------------
// conversion kernels
// ---------------------------------------------------------------------------
__global__ void cvt_split_h(const float4* __restrict__ in, uint2* __restrict__ hi,
                            uint2* __restrict__ lo)
{
    int i = blockIdx.x * blockDim.x + threadIdx.x;
    float4 v = in[i];
    uint2 uh, ul;
    uh.x = split_pair_h(v.x, v.y, ul.x);
    uh.y = split_pair_h(v.z, v.w, ul.y);
    hi[i] = uh;
    lo[i] = ul;
}

// W [K][N] fp32  ->  T [N][K] single fp16
__global__ void cvt_T_h(const float* __restrict__ W, __half* __restrict__ Th,
                        int K, int N)
{
    __shared__ float tile[32][33];
    int n0 = blockIdx.x * 32, k0 = blockIdx.y * 32;
    int tx = threadIdx.x, ty = threadIdx.y;  // 32 x 8
    #pragma unroll
    for (int r = 0; r < 4; r++)
        tile[ty + r*8][tx] = W[(size_t)(k0 + ty + r*8) * N + n0 + tx];
    __syncthreads();
    #pragma unroll
    for (int r = 0; r < 4; r++) {
        float v = tile[tx][ty + r*8];
        Th[(size_t)(n0 + ty + r*8) * K + k0 + tx] = __float2half_rn(v);
    }
}

// ---------------------------------------------------------------------------
// fp16 2-term GEMM via mma.sync: C = A @ B^T + bias; A = ah+al fp16, B single.
// CTA 128x128, BK=32, 8 warps (4m x 2n), warp tile 32x64, 3-stage cp.async,
// 72KB smem -> 2 CTAs/SM. EPI=0: fp32 C + bias. EPI=1: bf16-split per-head QKV.
// ---------------------------------------------------------------------------
#define STAGES 3
#define STAGE_BYTES 24576      /* Ahi 8K | Alo 8K | B 8K */
#define GEMM_SMEM (STAGES * STAGE_BYTES)   /* 72 KB */
#define SWZ(row, kb) ((kb) ^ ((((row) >> 1) & 3) << 4))

__device__ __forceinline__ void issue_stage(
    uint32_t sb_stage, const __half* __restrict__ Ahi,
    const __half* __restrict__ Alo, const __half* __restrict__ B,
    int rowBase, int colBase, int k0, int K, int t)
{
    #pragma unroll
    for (int u = 0; u < 2; u++) {
        int idx = t + 256*u;
        int row = idx >> 2, chunk = idx & 3;
        uint32_t soff = (uint32_t)(row*64 + SWZ(row, chunk*16));
        size_t geA = (size_t)(rowBase + row) * K + k0 + chunk*8;
        size_t geB = (size_t)(colBase + row) * K + k0 + chunk*8;
        cpa16(sb_stage +         soff, Ahi + geA);
        cpa16(sb_stage +  8192 + soff, Alo + geA);
        cpa16(sb_stage + 16384 + soff, B   + geB);
    }
    CP_COMMIT();
}

template<int EPI>
__global__ __launch_bounds__(256, 2)
void gemm_mma(const __half* __restrict__ Ahi, const __half* __restrict__ Alo,
              const __half* __restrict__ B,
              const float* __restrict__ bias, float* __restrict__ C,
              __nv_bfloat16* __restrict__ q_h, __nv_bfloat16* __restrict__ q_l,
              __nv_bfloat16* __restrict__ k_h, __nv_bfloat16* __restrict__ k_l,
              __nv_bfloat16* __restrict__ v_h, __nv_bfloat16* __restrict__ v_l,
              int M, int N, int K)
{
    extern __shared__ char sm[];
    const uint32_t sb = smem_u32(sm);

    const int t = threadIdx.x, lane = t & 31, w = t >> 5;
    const int warp_m = w & 3, warp_n = w >> 2;   // 4 x 2
    const int rowBase = blockIdx.y * 128;
    const int colBase = blockIdx.x * 128;
    const int ksteps  = K >> 5;
    const int mat = lane >> 3, r8 = lane & 7;

    float acc[2][8][4];
    #pragma unroll
    for (int i = 0; i < 2; i++)
        #pragma unroll
        for (int j = 0; j < 8; j++)
            #pragma unroll
            for (int q = 0; q < 4; q++) acc[i][j][q] = 0.f;

    issue_stage(sb,               Ahi, Alo, B, rowBase, colBase, 0,  K, t);
    issue_stage(sb + STAGE_BYTES, Ahi, Alo, B, rowBase, colBase, 32, K, t);

    int rowA[2], rowB[4];
    #pragma unroll
    for (int fm = 0; fm < 2; fm++)
        rowA[fm] = warp_m*32 + fm*16 + (mat & 1)*8 + r8;
    #pragma unroll
    for (int fb = 0; fb < 4; fb++)
        rowB[fb] = warp_n*64 + fb*16 + (mat >> 1)*8 + r8;

    for (int i = 0; i < ksteps; i++) {
        CP_WAIT(1);
        __syncthreads();
        const uint32_t st = sb + (uint32_t)(i % 3) * STAGE_BYTES;

        #pragma unroll
        for (int ks = 0; ks < 2; ks++) {
            const int kbA = ks*32 + (mat >> 1)*16;
            const int kbB = ks*32 + (mat & 1)*16;

            // B fragments (single fp16) resident for the ks-half
            uint32_t rh[4][4];
            #pragma unroll
            for (int fb = 0; fb < 4; fb++) {
                uint32_t off = (uint32_t)(rowB[fb]*64 + SWZ(rowB[fb], kbB));
                ldsm4(rh[fb], st + 16384 + off);
            }
            // A fragments double-buffered across fm
            uint32_t ahc[2][4], alc[2][4];
            {
                uint32_t off = (uint32_t)(rowA[0]*64 + SWZ(rowA[0], kbA));
                ldsm4(ahc[0], st +        off);
                ldsm4(alc[0], st + 8192 + off);
            }
            // refill next stage once per k-step (slot (i+2)%3 == (i-1)%3)
            if (ks == 0) {
                if (i + 2 < ksteps)
                    issue_stage(sb + (uint32_t)((i + 2) % 3) * STAGE_BYTES,
                                Ahi, Alo, B, rowBase, colBase, (i + 2)*32, K, t);
                else
                    CP_COMMIT();   // keep group accounting uniform
            }

            #pragma unroll
            for (int fm = 0; fm < 2; fm++) {
                const int cur = fm & 1;
                if (fm < 1) {
                    uint32_t off = (uint32_t)(rowA[1]*64 + SWZ(rowA[1], kbA));
                    ldsm4(ahc[1], st +        off);
                    ldsm4(alc[1], st + 8192 + off);
                }
                #pragma unroll
                for (int fb = 0; fb < 4; fb++) {
                    mma16816h(acc[fm][2*fb+0], ahc[cur], rh[fb]);
                    mma16816h(acc[fm][2*fb+0], alc[cur], rh[fb]);
                    mma16816h(acc[fm][2*fb+1], ahc[cur], rh[fb]+2);
                    mma16816h(acc[fm][2*fb+1], alc[cur], rh[fb]+2);
                }
            }
        }
    }

    const int qrow = lane >> 2, qcol = (lane & 3) * 2;
    #pragma unroll
    for (int fn = 0; fn < 8; fn++) {
        const int col = colBase + warp_n*64 + fn*8 + qcol;
        const float b0 = bias[col], b1 = bias[col + 1];
        if (EPI == 0) {
            #pragma unroll
            for (int fm = 0; fm < 2; fm++) {
                const int row0 = rowBase + warp_m*32 + fm*16 + qrow;
                float2 v0 = make_float2(acc[fm][fn][0] + b0, acc[fm][fn][1] + b1);
                float2 v1 = make_float2(acc[fm][fn][2] + b0, acc[fm][fn][3] + b1);
                *(float2*)&C[(size_t)row0 * N + col]       = v0;
                *(float2*)&C[(size_t)(row0 + 8) * N + col] = v1;
            }
        } else {
            const int sel = col >> 11, hh = (col >> 7) & 15, hd = col & 127;
            __nv_bfloat16* dh = (sel == 0) ? q_h : (sel == 1) ? k_h : v_h;
            __nv_bfloat16* dl = (sel == 0) ? q_l : (sel == 1) ? k_l : v_l;
            #pragma unroll
            for (int fm = 0; fm < 2; fm++) {
                const int r0 = rowBase + warp_m*32 + fm*16 + qrow;
                #pragma unroll
                for (int rr = 0; rr < 2; rr++) {
                    const int r = r0 + rr*8;
                    float va = acc[fm][fn][rr*2+0] + b0;
                    float vb = acc[fm][fn][rr*2+1] + b1;
                    uint32_t lo, hi = split_pair(va, vb, lo);
                    size_t o = (((size_t)((r >> 11)*NH + hh) * NS +
                                 (r & 2047)) * NHD + hd);
                    *(uint32_t*)&dh[o] = hi;
                    *(uint32_t*)&dl[o] = lo;
                }
            }
        }
    }
}

// ---------------------------------------------------------------------------
// Flash attention via mma.sync, bf16x3 emulation, ALiBi + causal.
// Static-max softmax; heavy tiles first; register-stage pipelining.
// Epilogue writes fp16 hi/lo A-operand for the projection GEMM.
// ---------------------------------------------------------------------------
#define FLASH_SMEM (3*65536)   /* 196608 */
#define SWZF(row, chunk) (((chunk) ^ ((row) & 7)) << 4)

__device__ __forceinline__ void flash_load_kv(
    uint32_t st, const __nv_bfloat16* __restrict__ kh,
    const __nv_bfloat16* __restrict__ kl,
    const __nv_bfloat16* __restrict__ vh,
    const __nv_bfloat16* __restrict__ vl,
    size_t hb, int kt, int t)
{
    #pragma unroll
    for (int u = 0; u < 4; u++) {
        int idx = t + 256*u;                 // 0..1023
        int row = idx >> 4, chunk = idx & 15;
        uint32_t soff = (uint32_t)(row*256 + SWZF(row, chunk));
        size_t g = hb + (size_t)(kt*64 + row)*NHD + chunk*8;
        cpa16(st +         soff, kh + g);
        cpa16(st + 16384 + soff, kl + g);
        cpa16(st + 32768 + soff, vh + g);
        cpa16(st + 49152 + soff, vl + g);
    }
    CP_COMMIT();
}

__global__ __launch_bounds__(256, 1)
void flash_mma(const __nv_bfloat16* __restrict__ qh,
               const __nv_bfloat16* __restrict__ ql,
               const __nv_bfloat16* __restrict__ kh,
               const __nv_bfloat16* __restrict__ kl,
               const __nv_bfloat16* __restrict__ vh,
               const __nv_bfloat16* __restrict__ vl,
               __half* __restrict__ ahi, __half* __restrict__ alo)
{
    extern __shared__ char sm[];
    const uint32_t sb = smem_u32(sm);
    const uint32_t qst = sb + 2*65536;       // Q staging = slot 2

    const int qt = (NS/128 - 1) - blockIdx.x;   // heavy tiles first
    const int h = blockIdx.y, b = blockIdx.z;
    const int t = threadIdx.x, lane = t & 31, w = t >> 5;
    const size_t hb = (size_t)(b*NH + h) * NS * NHD;

    const float L2E   = 1.4426950408889634f;
    const float scale = 0.08838834764831845f;          // 1/sqrt(128)
    const float slope = exp2f(-0.5f * (float)(h + 1)); // ALiBi, H=16
    const float c1  = scale * L2E;
    const float sl2 = slope * L2E;
    const float mc8 = -8.0f * L2E;
    const int r8 = lane & 7, m01 = (lane >> 3) & 1, m2 = lane >> 4;
    const int qr = lane >> 2, qc = (lane & 3) * 2;
    const int rg0 = qt*128 + w*16 + qr;                // global q row (c0/c1)

    // stage Q into slot 2
    #pragma unroll
    for (int u = 0; u < 8; u++) {
        int idx = t + 256*u;                 // 0..2047
        int row = idx >> 4, chunk = idx & 15;
        uint32_t soff = (uint32_t)(row*256 + SWZF(row, chunk));
        size_t g = hb + (size_t)(qt*128 + row)*NHD + chunk*8;
        cpa16(qst +         soff, qh + g);
        cpa16(qst + 32768 + soff, ql + g);
    }
    CP_COMMIT();                             // group: Q
    flash_load_kv(sb,         kh, kl, vh, vl, hb, 0, t);   // group: KV0
    flash_load_kv(sb + 65536, kh, kl, vh, vl, hb, 1, t);   // group: KV1

    CP_WAIT(2);                              // Q complete
    __syncthreads();

    // Q fragments -> registers
    uint32_t fqh[8][4], fql[8][4];
    {
        const int qrow = w*16 + m01*8 + r8;
        #pragma unroll
        for (int kc = 0; kc < 8; kc++) {
            uint32_t qa = qst + (uint32_t)(qrow*256 + SWZF(qrow, kc*2 + m2));
            ldsm4(fqh[kc], qa);
            ldsm4(fql[kc], qa + 32768);
        }
    }

    float l0 = 0.f, l1 = 0.f;
    float acc_o[16][4];
    #pragma unroll
    for (int i = 0; i < 16; i++)
        #pragma unroll
        for (int j = 0; j < 4; j++) acc_o[i][j] = 0.f;

    const int nkt = 2*qt + 2;
    for (int kt = 0; kt < nkt; kt++) {
        CP_WAIT(1);
        __syncthreads();
        const uint32_t st = sb + (uint32_t)(kt % 3)*65536;

        // ---- S = Q K^T (3-term), K frags double-buffered over ng ----
        float s_[8][4];
        #pragma unroll
        for (int i = 0; i < 8; i++)
            #pragma unroll
            for (int j = 0; j < 4; j++) s_[i][j] = 0.f;

        #pragma unroll
        for (int kc = 0; kc < 8; kc++) {
            const int kchk = kc*2 + m01;
            uint32_t rh[2][4], rl[2][4];
            {
                int krow = m2*8 + r8;                // ng = 0
                uint32_t ka = st + (uint32_t)(krow*256 + SWZF(krow, kchk));
                ldsm4(rh[0], ka);
                ldsm4(rl[0], ka + 16384);
            }
            if (kc == 0) {
                if (kt + 2 < nkt)
                    flash_load_kv(sb + (uint32_t)((kt + 2) % 3)*65536,
                                  kh, kl, vh, vl, hb, kt + 2, t);
                else
                    CP_COMMIT();
            }
            #pragma unroll
            for (int ng = 0; ng < 4; ng++) {
                const int cur = ng & 1;
                if (ng < 3) {
                    int krow = (ng+1)*16 + m2*8 + r8;
                    uint32_t ka = st + (uint32_t)(krow*256 + SWZF(krow, kchk));
                    ldsm4(rh[cur^1], ka);
                    ldsm4(rl[cur^1], ka + 16384);
                }
                mma16816(s_[ng*2+0], fqh[kc], rh[cur]);
                mma16816(s_[ng*2+0], fqh[kc], rl[cur]);
                mma16816(s_[ng*2+0], fql[kc], rh[cur]);
                mma16816(s_[ng*2+1], fqh[kc], rh[cur]+2);
                mma16816(s_[ng*2+1], fqh[kc], rl[cur]+2);
                mma16816(s_[ng*2+1], fql[kc], rh[cur]+2);
            }
        }

        // ---- static-max softmax ----
        const bool diag = (kt >= 2*qt);
        const float baseA = fmaf((float)(kt*64 + qc - rg0), sl2, mc8);
        const float baseB = baseA - 8.0f*sl2;   // rows rg0+8
        if (diag) {
            #pragma unroll
            for (int nt = 0; nt < 8; nt++) {
                #pragma unroll
                for (int jj = 0; jj < 2; jj++) {
                    const float cf = (float)(nt*8 + jj);
                    float a0 = fmaf(s_[nt][jj],     c1, fmaf(cf, sl2, baseA));
                    float a1 = fmaf(s_[nt][2 + jj], c1, fmaf(cf, sl2, baseB));
                    int col = kt*64 + nt*8 + qc + jj;
                    if (col > rg0)     a0 = -10000.f;
                    if (col > rg0 + 8) a1 = -10000.f;
                    float p0 = ex2f(a0), p1 = ex2f(a1);
                    l0 += p0; l1 += p1;
                    s_[nt][jj] = p0; s_[nt][2 + jj] = p1;
                }
            }
        } else {
            #pragma unroll
            for (int nt = 0; nt < 8; nt++) {
                #pragma unroll
                for (int jj = 0; jj < 2; jj++) {
                    const float cf = (float)(nt*8 + jj);
                    float a0 = fmaf(s_[nt][jj],     c1, fmaf(cf, sl2, baseA));
                    float a1 = fmaf(s_[nt][2 + jj], c1, fmaf(cf, sl2, baseB));
                    float p0 = ex2f(a0), p1 = ex2f(a1);
                    l0 += p0; l1 += p1;
                    s_[nt][jj] = p0; s_[nt][2 + jj] = p1;
                }
            }
        }

        // ---- O += P V (3-term), V frags double-buffered over ng ----
        #pragma unroll
        for (int kc = 0; kc < 4; kc++) {
            uint32_t ph[4], pl[4];
            {
                const float* pa = s_[2*kc];
                const float* pb = s_[2*kc + 1];
                ph[0] = split_pair(pa[0], pa[1], pl[0]);
                ph[1] = split_pair(pa[2], pa[3], pl[1]);
                ph[2] = split_pair(pb[0], pb[1], pl[2]);
                ph[3] = split_pair(pb[2], pb[3], pl[3]);
            }
            const int vrow = kc*16 + m01*8 + r8;
            const uint32_t vbase = st + 32768 + (uint32_t)(vrow*256);
            uint32_t wh[2][4], wl[2][4];
            {
                uint32_t va = vbase + (uint32_t)SWZF(vrow, m2);   // ng = 0
                ldsm4t(wh[0], va);
                ldsm4t(wl[0], va + 16384);
            }
            #pragma unroll
            for (int ng = 0; ng < 8; ng++) {
                const int cur = ng & 1;
                if (ng < 7) {
                    uint32_t va = vbase + (uint32_t)SWZF(vrow, (ng+1)*2 + m2);
                    ldsm4t(wh[cur^1], va);
                    ldsm4t(wl[cur^1], va + 16384);
                }
                mma16816(acc_o[ng*2+0], ph, wh[cur]);
                mma16816(acc_o[ng*2+0], ph, wl[cur]);
                mma16816(acc_o[ng*2+0], pl, wh[cur]);
                mma16816(acc_o[ng*2+1], ph, wh[cur]+2);
                mma16816(acc_o[ng*2+1], ph, wl[cur]+2);
                mma16816(acc_o[ng*2+1], pl, wh[cur]+2);
            }
        }
    }

    // ---- finalize ----
    l0 += __shfl_xor_sync(0xffffffffu, l0, 1);
    l0 += __shfl_xor_sync(0xffffffffu, l0, 2);
    l1 += __shfl_xor_sync(0xffffffffu, l1, 1);
    l1 += __shfl_xor_sync(0xffffffffu, l1, 2);
    const float inv0 = 1.f / l0, inv1 = 1.f / l1;

    const size_t row0 = (size_t)(b*NS) + qt*128 + w*16 + qr;
    #pragma unroll
    for (int nt = 0; nt < 16; nt++) {
        int col = h*NHD + nt*8 + qc;
        uint32_t lo0, lo1;
        uint32_t hi0 = split_pair_h(acc_o[nt][0]*inv0, acc_o[nt][1]*inv0, lo0);
        uint32_t hi1 = split_pair_h(acc_o[nt][2]*inv1, acc_o[nt][3]*inv1, lo1);
        *(uint32_t*)&ahi[row0 * ND + col]       = hi0;
        *(uint32_t*)&alo[row0 * ND + col]       = lo0;
        *(uint32_t*)&ahi[(row0 + 8) * ND + col] = hi1;
        *(uint32_t*)&alo[(row0 + 8) * ND + col] = lo1;
    }
}

// ---------------------------------------------------------------------------
extern "C" void kernel_launch(void* const* d_in, const int* in_sizes, int n_in,
                              void* d_out, int out_size)
{
    const float* x    = (const float*)d_in[0];
    const float* Wqkv = (const float*)d_in[1];
    const float* bqkv = (const float*)d_in[2];
    const float* Wout = (const float*)d_in[3];
    const float* bout = (const float*)d_in[4];
    float* out = (float*)d_out;

    __half *xhi, *xlo, *ahi, *alo, *wqT, *woT;
    __nv_bfloat16 *qh, *ql, *kh, *kl, *vh, *vl;
    cudaGetSymbolAddress((void**)&xhi,  g_xhi);
    cudaGetSymbolAddress((void**)&xlo,  g_xlo);
    cudaGetSymbolAddress((void**)&ahi,  g_ahi);
    cudaGetSymbolAddress((void**)&alo,  g_alo);
    cudaGetSymbolAddress((void**)&wqT,  g_wqT);
    cudaGetSymbolAddress((void**)&woT,  g_woT);
    cudaGetSymbolAddress((void**)&qh,   g_qh);
    cudaGetSymbolAddress((void**)&ql,   g_ql);
    cudaGetSymbolAddress((void**)&kh,   g_kh);
    cudaGetSymbolAddress((void**)&kl,   g_kl);
    cudaGetSymbolAddress((void**)&vh,   g_vh);
    cudaGetSymbolAddress((void**)&vl,   g_vl);

    cudaFuncSetAttribute(gemm_mma<0>,
                         cudaFuncAttributeMaxDynamicSharedMemorySize, GEMM_SMEM);
    cudaFuncSetAttribute(gemm_mma<1>,
                         cudaFuncAttributeMaxDynamicSharedMemorySize, GEMM_SMEM);
    cudaFuncSetAttribute(flash_mma,
                         cudaFuncAttributeMaxDynamicSharedMemorySize, FLASH_SMEM);

    // operand conversions
    cvt_split_h<<<(ROWS*(size_t)ND/4 + 255)/256, 256>>>(
        (const float4*)x, (uint2*)xhi, (uint2*)xlo);
    cvt_T_h<<<dim3(QKV_COLS/32, ND/32), dim3(32, 8)>>>(Wqkv, wqT, ND, QKV_COLS);
    cvt_T_h<<<dim3(ND/32, ND/32), dim3(32, 8)>>>(Wout, woT, ND, ND);

    // qkv = x @ Wqkv + b_qkv, written directly as bf16-split per-head q/k/v
    gemm_mma<1><<<dim3(QKV_COLS/128, ROWS/128), 256, GEMM_SMEM>>>(
        xhi, xlo, wqT, bqkv, nullptr,
        qh, ql, kh, kl, vh, vl, ROWS, QKV_COLS, ND);

    // attention -> writes proj A-operand (fp16 hi/lo) directly
    flash_mma<<<dim3(NS/128, NH, NB), 256, FLASH_SMEM>>>(
        qh, ql, kh, kl, vh, vl, ahi, alo);

    // out = attn @ Wout + b_out
    gemm_mma<0><<<dim3(ND/128, ROWS/128), 256, GEMM_SMEM>>>(
        ahi, alo, woT, bout, out,
        nullptr, nullptr, nullptr, nullptr, nullptr, nullptr, ROWS, ND, ND);
}

// round 11
// speedup vs baseline: 4.8548x; 1.1165x over previous
#include <cuda_runtime.h>
#include <cuda_bf16.h>
#include <cuda_fp16.h>
#include <cstdint>
#include <math.h>

#define NB 4
#define NS 2048
#define ND 2048
#define NH 16
#define NHD 128
#define ROWS (NB*NS)        /* 8192 */
#define QKV_COLS (3*ND)     /* 6144 */

// ---------------- scratch (device globals: allocation-free rule) ----------
__device__ __half g_xhi[(size_t)ROWS * ND];
__device__ __half g_xlo[(size_t)ROWS * ND];
__device__ __half g_ahi[(size_t)ROWS * ND];                // attn out hi
__device__ __half g_alo[(size_t)ROWS * ND];                // attn out lo
__device__ __half g_wqT[(size_t)QKV_COLS * ND];            // Wqkv^T [6144][2048]
__device__ __half g_woT[(size_t)ND * ND];                  // Wout^T [2048][2048]
// per-head QKV: [B*H][S][HD]; Q split hi/lo, K and V single fp16
__device__ __half g_qhh[(size_t)ROWS * ND];
__device__ __half g_qll[(size_t)ROWS * ND];
__device__ __half g_kk[(size_t)ROWS * ND];
__device__ __half g_vv[(size_t)ROWS * ND];

// ---------------- PTX helpers (baseline features only: sm_80+) ------------
__device__ __forceinline__ uint32_t smem_u32(const void* p) {
    uint32_t a;
    asm("{ .reg .u64 t; cvta.to.shared.u64 t, %1; cvt.u32.u64 %0, t; }"
        : "=r"(a) : "l"(p));
    return a;
}

__device__ __forceinline__ void cpa16(uint32_t s, const void* g) {
    asm volatile("cp.async.cg.shared.global [%0], [%1], 16;" :: "r"(s), "l"(g));
}
#define CP_COMMIT() asm volatile("cp.async.commit_group;" ::: "memory")
#define CP_WAIT(n)  asm volatile("cp.async.wait_group %0;" :: "n"(n) : "memory")

__device__ __forceinline__ void ldsm4(uint32_t* r, uint32_t addr) {
    asm volatile("ldmatrix.sync.aligned.m8n8.x4.shared.b16 {%0,%1,%2,%3}, [%4];"
                 : "=r"(r[0]), "=r"(r[1]), "=r"(r[2]), "=r"(r[3]) : "r"(addr));
}
__device__ __forceinline__ void ldsm4t(uint32_t* r, uint32_t addr) {
    asm volatile("ldmatrix.sync.aligned.m8n8.x4.trans.shared.b16 {%0,%1,%2,%3}, [%4];"
                 : "=r"(r[0]), "=r"(r[1]), "=r"(r[2]), "=r"(r[3]) : "r"(addr));
}

// fp16 mma
__device__ __forceinline__ void mma16816h(float* d, const uint32_t* a,
                                          const uint32_t* b) {
    asm volatile(
        "mma.sync.aligned.m16n8k16.row.col.f32.f16.f16.f32 "
        "{%0,%1,%2,%3}, {%4,%5,%6,%7}, {%8,%9}, {%0,%1,%2,%3};"
        : "+f"(d[0]), "+f"(d[1]), "+f"(d[2]), "+f"(d[3])
        : "r"(a[0]), "r"(a[1]), "r"(a[2]), "r"(a[3]), "r"(b[0]), "r"(b[1]));
}

__device__ __forceinline__ float ex2f(float x) {
    float y;
    asm("ex2.approx.f32 %0, %1;" : "=f"(y) : "f"(x));
    return y;
}

#define PACK2(lo16, hi16) (((uint32_t)(hi16) << 16) | (uint32_t)(lo16))
#define HFU(x) __half_as_ushort(x)

__device__ __forceinline__ uint32_t split_pair_h(float a, float b, uint32_t& lo) {
    __half h0 = __float2half_rn(a), h1 = __float2half_rn(b);
    __half e0 = __float2half_rn(a - __half2float(h0));
    __half e1 = __float2half_rn(b - __half2float(h1));
    lo = PACK2(HFU(e0), HFU(e1));
    return PACK2(HFU(h0), HFU(h1));
}
__device__ __forceinline__ uint32_t pack_h(float a, float b) {
    return PACK2(HFU(__float2half_rn(a)), HFU(__float2half_rn(b)));
}

// ---------------------------------------------------------------------------
// conversion kernels
// ---------------------------------------------------------------------------
__global__ void cvt_split_h(const float4* __restrict__ in, uint2* __restrict__ hi,
                            uint2* __restrict__ lo)
{
    int i = blockIdx.x * blockDim.x + threadIdx.x;
    float4 v = in[i];
    uint2 uh, ul;
    uh.x = split_pair_h(v.x, v.y, ul.x);
    uh.y = split_pair_h(v.z, v.w, ul.y);
    hi[i] = uh;
    lo[i] = ul;
}

// W [K][N] fp32  ->  T [N][K] single fp16
__global__ void cvt_T_h(const float* __restrict__ W, __half* __restrict__ Th,
                        int K, int N)
{
    __shared__ float tile[32][33];
    int n0 = blockIdx.x * 32, k0 = blockIdx.y * 32;
    int tx = threadIdx.x, ty = threadIdx.y;  // 32 x 8
    #pragma unroll
    for (int r = 0; r < 4; r++)
        tile[ty + r*8][tx] = W[(size_t)(k0 + ty + r*8) * N + n0 + tx];
    __syncthreads();
    #pragma unroll
    for (int r = 0; r < 4; r++) {
        float v = tile[tx][ty + r*8];
        Th[(size_t)(n0 + ty + r*8) * K + k0 + tx] = __float2half_rn(v);
    }
}

// ---------------------------------------------------------------------------
// fp16 2-term GEMM via mma.sync: C = A @ B^T + bias; A = ah+al fp16, B single.
// CTA 128x128, BK=32, 8 warps (4m x 2n), warp tile 32x64, 3-stage cp.async,
// 72KB smem -> 2 CTAs/SM. EPI=0: fp32 C + bias. EPI=1: per-head QKV
// (Q split hi/lo, K and V single fp16).
// ---------------------------------------------------------------------------
#define STAGES 3
#define STAGE_BYTES 24576      /* Ahi 8K | Alo 8K | B 8K */
#define GEMM_SMEM (STAGES * STAGE_BYTES)   /* 72 KB */
#define SWZ(row, kb) ((kb) ^ ((((row) >> 1) & 3) << 4))

__device__ __forceinline__ void issue_stage(
    uint32_t sb_stage, const __half* __restrict__ Ahi,
    const __half* __restrict__ Alo, const __half* __restrict__ B,
    int rowBase, int colBase, int k0, int K, int t)
{
    #pragma unroll
    for (int u = 0; u < 2; u++) {
        int idx = t + 256*u;
        int row = idx >> 2, chunk = idx & 3;
        uint32_t soff = (uint32_t)(row*64 + SWZ(row, chunk*16));
        size_t geA = (size_t)(rowBase + row) * K + k0 + chunk*8;
        size_t geB = (size_t)(colBase + row) * K + k0 + chunk*8;
        cpa16(sb_stage +         soff, Ahi + geA);
        cpa16(sb_stage +  8192 + soff, Alo + geA);
        cpa16(sb_stage + 16384 + soff, B   + geB);
    }
    CP_COMMIT();
}

template<int EPI>
__global__ __launch_bounds__(256, 2)
void gemm_mma(const __half* __restrict__ Ahi, const __half* __restrict__ Alo,
              const __half* __restrict__ B,
              const float* __restrict__ bias, float* __restrict__ C,
              __half* __restrict__ q_h, __half* __restrict__ q_l,
              __half* __restrict__ k_s, __half* __restrict__ v_s,
              int M, int N, int K)
{
    extern __shared__ char sm[];
    const uint32_t sb = smem_u32(sm);

    const int t = threadIdx.x, lane = t & 31, w = t >> 5;
    const int warp_m = w & 3, warp_n = w >> 2;   // 4 x 2
    const int rowBase = blockIdx.y * 128;
    const int colBase = blockIdx.x * 128;
    const int ksteps  = K >> 5;
    const int mat = lane >> 3, r8 = lane & 7;

    float acc[2][8][4];
    #pragma unroll
    for (int i = 0; i < 2; i++)
        #pragma unroll
        for (int j = 0; j < 8; j++)
            #pragma unroll
            for (int q = 0; q < 4; q++) acc[i][j][q] = 0.f;

    issue_stage(sb,               Ahi, Alo, B, rowBase, colBase, 0,  K, t);
    issue_stage(sb + STAGE_BYTES, Ahi, Alo, B, rowBase, colBase, 32, K, t);

    int rowA[2], rowB[4];
    #pragma unroll
    for (int fm = 0; fm < 2; fm++)
        rowA[fm] = warp_m*32 + fm*16 + (mat & 1)*8 + r8;
    #pragma unroll
    for (int fb = 0; fb < 4; fb++)
        rowB[fb] = warp_n*64 + fb*16 + (mat >> 1)*8 + r8;

    for (int i = 0; i < ksteps; i++) {
        CP_WAIT(1);
        __syncthreads();
        const uint32_t st = sb + (uint32_t)(i % 3) * STAGE_BYTES;

        #pragma unroll
        for (int ks = 0; ks < 2; ks++) {
            const int kbA = ks*32 + (mat >> 1)*16;
            const int kbB = ks*32 + (mat & 1)*16;

            uint32_t rh[4][4];
            #pragma unroll
            for (int fb = 0; fb < 4; fb++) {
                uint32_t off = (uint32_t)(rowB[fb]*64 + SWZ(rowB[fb], kbB));
                ldsm4(rh[fb], st + 16384 + off);
            }
            uint32_t ahc[2][4], alc[2][4];
            {
                uint32_t off = (uint32_t)(rowA[0]*64 + SWZ(rowA[0], kbA));
                ldsm4(ahc[0], st +        off);
                ldsm4(alc[0], st + 8192 + off);
            }
            if (ks == 0) {
                if (i + 2 < ksteps)
                    issue_stage(sb + (uint32_t)((i + 2) % 3) * STAGE_BYTES,
                                Ahi, Alo, B, rowBase, colBase, (i + 2)*32, K, t);
                else
                    CP_COMMIT();   // keep group accounting uniform
            }

            #pragma unroll
            for (int fm = 0; fm < 2; fm++) {
                const int cur = fm & 1;
                if (fm < 1) {
                    uint32_t off = (uint32_t)(rowA[1]*64 + SWZ(rowA[1], kbA));
                    ldsm4(ahc[1], st +        off);
                    ldsm4(alc[1], st + 8192 + off);
                }
                #pragma unroll
                for (int fb = 0; fb < 4; fb++) {
                    mma16816h(acc[fm][2*fb+0], ahc[cur], rh[fb]);
                    mma16816h(acc[fm][2*fb+0], alc[cur], rh[fb]);
                    mma16816h(acc[fm][2*fb+1], ahc[cur], rh[fb]+2);
                    mma16816h(acc[fm][2*fb+1], alc[cur], rh[fb]+2);
                }
            }
        }
    }

    const int qrow = lane >> 2, qcol = (lane & 3) * 2;
    #pragma unroll
    for (int fn = 0; fn < 8; fn++) {
        const int col = colBase + warp_n*64 + fn*8 + qcol;
        const float b0 = bias[col], b1 = bias[col + 1];
        if (EPI == 0) {
            #pragma unroll
            for (int fm = 0; fm < 2; fm++) {
                const int row0 = rowBase + warp_m*32 + fm*16 + qrow;
                float2 v0 = make_float2(acc[fm][fn][0] + b0, acc[fm][fn][1] + b1);
                float2 v1 = make_float2(acc[fm][fn][2] + b0, acc[fm][fn][3] + b1);
                *(float2*)&C[(size_t)row0 * N + col]       = v0;
                *(float2*)&C[(size_t)(row0 + 8) * N + col] = v1;
            }
        } else {
            const int sel = col >> 11, hh = (col >> 7) & 15, hd = col & 127;
            #pragma unroll
            for (int fm = 0; fm < 2; fm++) {
                const int r0 = rowBase + warp_m*32 + fm*16 + qrow;
                #pragma unroll
                for (int rr = 0; rr < 2; rr++) {
                    const int r = r0 + rr*8;
                    float va = acc[fm][fn][rr*2+0] + b0;
                    float vb = acc[fm][fn][rr*2+1] + b1;
                    size_t o = (((size_t)((r >> 11)*NH + hh) * NS +
                                 (r & 2047)) * NHD + hd);
                    if (sel == 0) {
                        uint32_t lo, hi = split_pair_h(va, vb, lo);
                        *(uint32_t*)&q_h[o] = hi;
                        *(uint32_t*)&q_l[o] = lo;
                    } else {
                        __half* d = (sel == 1) ? k_s : v_s;
                        *(uint32_t*)&d[o] = pack_h(va, vb);
                    }
                }
            }
        }
    }
}

// ---------------------------------------------------------------------------
// Flash attention via fp16 mma, 2-term emulation (Q,P split; K,V single).
// Static-max softmax; heavy tiles first; register-stage pipelining.
// smem: 3 KV stages of 32KB (K 16K | V 16K) + persistent Q 64KB (hi|lo).
// ---------------------------------------------------------------------------
#define KV_STAGE 32768
#define FLASH_SMEM (3*KV_STAGE + 65536)   /* 163840 */
#define SWZF(row, chunk) (((chunk) ^ ((row) & 7)) << 4)

__device__ __forceinline__ void flash_load_kv(
    uint32_t st, const __half* __restrict__ k_s,
    const __half* __restrict__ v_s, size_t hb, int kt, int t)
{
    #pragma unroll
    for (int u = 0; u < 4; u++) {
        int idx = t + 256*u;                 // 0..1023
        int row = idx >> 4, chunk = idx & 15;
        uint32_t soff = (uint32_t)(row*256 + SWZF(row, chunk));
        size_t g = hb + (size_t)(kt*64 + row)*NHD + chunk*8;
        cpa16(st +         soff, k_s + g);
        cpa16(st + 16384 + soff, v_s + g);
    }
    CP_COMMIT();
}

__global__ __launch_bounds__(256, 1)
void flash_mma(const __half* __restrict__ qh, const __half* __restrict__ ql,
               const __half* __restrict__ k_s, const __half* __restrict__ v_s,
               __half* __restrict__ ahi, __half* __restrict__ alo)
{
    extern __shared__ char sm[];
    const uint32_t sb = smem_u32(sm);
    const uint32_t qst = sb + 3*KV_STAGE;    // persistent Q region

    const int qt = (NS/128 - 1) - blockIdx.x;   // heavy tiles first
    const int h = blockIdx.y, b = blockIdx.z;
    const int t = threadIdx.x, lane = t & 31, w = t >> 5;
    const size_t hb = (size_t)(b*NH + h) * NS * NHD;

    const float L2E   = 1.4426950408889634f;
    const float scale = 0.08838834764831845f;          // 1/sqrt(128)
    const float slope = exp2f(-0.5f * (float)(h + 1)); // ALiBi, H=16
    const float c1  = scale * L2E;
    const float sl2 = slope * L2E;
    const float mc8 = -8.0f * L2E;
    const int r8 = lane & 7, m01 = (lane >> 3) & 1, m2 = lane >> 4;
    const int qr = lane >> 2, qc = (lane & 3) * 2;
    const int rg0 = qt*128 + w*16 + qr;                // global q row (c0/c1)

    // stage Q (hi|lo) into the persistent region
    #pragma unroll
    for (int u = 0; u < 8; u++) {
        int idx = t + 256*u;                 // 0..2047
        int row = idx >> 4, chunk = idx & 15;
        uint32_t soff = (uint32_t)(row*256 + SWZF(row, chunk));
        size_t g = hb + (size_t)(qt*128 + row)*NHD + chunk*8;
        cpa16(qst +         soff, qh + g);
        cpa16(qst + 32768 + soff, ql + g);
    }
    CP_COMMIT();                             // group: Q
    flash_load_kv(sb,            k_s, v_s, hb, 0, t);   // group: KV0
    flash_load_kv(sb + KV_STAGE, k_s, v_s, hb, 1, t);   // group: KV1

    CP_WAIT(2);                              // Q complete
    __syncthreads();

    // Q fragments -> registers
    uint32_t fqh[8][4], fql[8][4];
    {
        const int qrow = w*16 + m01*8 + r8;
        #pragma unroll
        for (int kc = 0; kc < 8; kc++) {
            uint32_t qa = qst + (uint32_t)(qrow*256 + SWZF(qrow, kc*2 + m2));
            ldsm4(fqh[kc], qa);
            ldsm4(fql[kc], qa + 32768);
        }
    }

    float l0 = 0.f, l1 = 0.f;
    float acc_o[16][4];
    #pragma unroll
    for (int i = 0; i < 16; i++)
        #pragma unroll
        for (int j = 0; j < 4; j++) acc_o[i][j] = 0.f;

    const int nkt = 2*qt + 2;
    for (int kt = 0; kt < nkt; kt++) {
        CP_WAIT(1);
        __syncthreads();
        const uint32_t st = sb + (uint32_t)(kt % 3)*KV_STAGE;

        // ---- S = Q K^T (2-term), K frags double-buffered over ng ----
        float s_[8][4];
        #pragma unroll
        for (int i = 0; i < 8; i++)
            #pragma unroll
            for (int j = 0; j < 4; j++) s_[i][j] = 0.f;

        #pragma unroll
        for (int kc = 0; kc < 8; kc++) {
            const int kchk = kc*2 + m01;
            uint32_t rh[2][4];
            {
                int krow = m2*8 + r8;                // ng = 0
                ldsm4(rh[0], st + (uint32_t)(krow*256 + SWZF(krow, kchk)));
            }
            if (kc == 0) {
                // refill: slot (kt+2)%3 fully read in iter kt-1
                if (kt + 2 < nkt)
                    flash_load_kv(sb + (uint32_t)((kt + 2) % 3)*KV_STAGE,
                                  k_s, v_s, hb, kt + 2, t);
                else
                    CP_COMMIT();
            }
            #pragma unroll
            for (int ng = 0; ng < 4; ng++) {
                const int cur = ng & 1;
                if (ng < 3) {
                    int krow = (ng+1)*16 + m2*8 + r8;
                    ldsm4(rh[cur^1],
                          st + (uint32_t)(krow*256 + SWZF(krow, kchk)));
                }
                mma16816h(s_[ng*2+0], fqh[kc], rh[cur]);
                mma16816h(s_[ng*2+0], fql[kc], rh[cur]);
                mma16816h(s_[ng*2+1], fqh[kc], rh[cur]+2);
                mma16816h(s_[ng*2+1], fql[kc], rh[cur]+2);
            }
        }

        // ---- static-max softmax ----
        const bool diag = (kt >= 2*qt);
        const float baseA = fmaf((float)(kt*64 + qc - rg0), sl2, mc8);
        const float baseB = baseA - 8.0f*sl2;   // rows rg0+8
        if (diag) {
            #pragma unroll
            for (int nt = 0; nt < 8; nt++) {
                #pragma unroll
                for (int jj = 0; jj < 2; jj++) {
                    const float cf = (float)(nt*8 + jj);
                    float a0 = fmaf(s_[nt][jj],     c1, fmaf(cf, sl2, baseA));
                    float a1 = fmaf(s_[nt][2 + jj], c1, fmaf(cf, sl2, baseB));
                    int col = kt*64 + nt*8 + qc + jj;
                    if (col > rg0)     a0 = -10000.f;
                    if (col > rg0 + 8) a1 = -10000.f;
                    float p0 = ex2f(a0), p1 = ex2f(a1);
                    l0 += p0; l1 += p1;
                    s_[nt][jj] = p0; s_[nt][2 + jj] = p1;
                }
            }
        } else {
            #pragma unroll
            for (int nt = 0; nt < 8; nt++) {
                #pragma unroll
                for (int jj = 0; jj < 2; jj++) {
                    const float cf = (float)(nt*8 + jj);
                    float a0 = fmaf(s_[nt][jj],     c1, fmaf(cf, sl2, baseA));
                    float a1 = fmaf(s_[nt][2 + jj], c1, fmaf(cf, sl2, baseB));
                    float p0 = ex2f(a0), p1 = ex2f(a1);
                    l0 += p0; l1 += p1;
                    s_[nt][jj] = p0; s_[nt][2 + jj] = p1;
                }
            }
        }

        // ---- O += P V (2-term), V frags double-buffered over ng ----
        #pragma unroll
        for (int kc = 0; kc < 4; kc++) {
            uint32_t ph[4], pl[4];
            {
                const float* pa = s_[2*kc];
                const float* pb = s_[2*kc + 1];
                ph[0] = split_pair_h(pa[0], pa[1], pl[0]);
                ph[1] = split_pair_h(pa[2], pa[3], pl[1]);
                ph[2] = split_pair_h(pb[0], pb[1], pl[2]);
                ph[3] = split_pair_h(pb[2], pb[3], pl[3]);
            }
            const int vrow = kc*16 + m01*8 + r8;
            const uint32_t vbase = st + 16384 + (uint32_t)(vrow*256);
            uint32_t wh[2][4];
            ldsm4t(wh[0], vbase + (uint32_t)SWZF(vrow, m2));   // ng = 0
            #pragma unroll
            for (int ng = 0; ng < 8; ng++) {
                const int cur = ng & 1;
                if (ng < 7)
                    ldsm4t(wh[cur^1],
                           vbase + (uint32_t)SWZF(vrow, (ng+1)*2 + m2));
                mma16816h(acc_o[ng*2+0], ph, wh[cur]);
                mma16816h(acc_o[ng*2+0], pl, wh[cur]);
                mma16816h(acc_o[ng*2+1], ph, wh[cur]+2);
                mma16816h(acc_o[ng*2+1], pl, wh[cur]+2);
            }
        }
    }

    // ---- finalize ----
    l0 += __shfl_xor_sync(0xffffffffu, l0, 1);
    l0 += __shfl_xor_sync(0xffffffffu, l0, 2);
    l1 += __shfl_xor_sync(0xffffffffu, l1, 1);
    l1 += __shfl_xor_sync(0xffffffffu, l1, 2);
    const float inv0 = 1.f / l0, inv1 = 1.f / l1;

    const size_t row0 = (size_t)(b*NS) + qt*128 + w*16 + qr;
    #pragma unroll
    for (int nt = 0; nt < 16; nt++) {
        int col = h*NHD + nt*8 + qc;
        uint32_t lo0, lo1;
        uint32_t hi0 = split_pair_h(acc_o[nt][0]*inv0, acc_o[nt][1]*inv0, lo0);
        uint32_t hi1 = split_pair_h(acc_o[nt][2]*inv1, acc_o[nt][3]*inv1, lo1);
        *(uint32_t*)&ahi[row0 * ND + col]       = hi0;
        *(uint32_t*)&alo[row0 * ND + col]       = lo0;
        *(uint32_t*)&ahi[(row0 + 8) * ND + col] = hi1;
        *(uint32_t*)&alo[(row0 + 8) * ND + col] = lo1;
    }
}

// ---------------------------------------------------------------------------
extern "C" void kernel_launch(void* const* d_in, const int* in_sizes, int n_in,
                              void* d_out, int out_size)
{
    const float* x    = (const float*)d_in[0];
    const float* Wqkv = (const float*)d_in[1];
    const float* bqkv = (const float*)d_in[2];
    const float* Wout = (const float*)d_in[3];
    const float* bout = (const float*)d_in[4];
    float* out = (float*)d_out;

    __half *xhi, *xlo, *ahi, *alo, *wqT, *woT, *qh, *ql, *ks, *vs;
    cudaGetSymbolAddress((void**)&xhi,  g_xhi);
    cudaGetSymbolAddress((void**)&xlo,  g_xlo);
    cudaGetSymbolAddress((void**)&ahi,  g_ahi);
    cudaGetSymbolAddress((void**)&alo,  g_alo);
    cudaGetSymbolAddress((void**)&wqT,  g_wqT);
    cudaGetSymbolAddress((void**)&woT,  g_woT);
    cudaGetSymbolAddress((void**)&qh,   g_qhh);
    cudaGetSymbolAddress((void**)&ql,   g_qll);
    cudaGetSymbolAddress((void**)&ks,   g_kk);
    cudaGetSymbolAddress((void**)&vs,   g_vv);

    cudaFuncSetAttribute(gemm_mma<0>,
                         cudaFuncAttributeMaxDynamicSharedMemorySize, GEMM_SMEM);
    cudaFuncSetAttribute(gemm_mma<1>,
                         cudaFuncAttributeMaxDynamicSharedMemorySize, GEMM_SMEM);
    cudaFuncSetAttribute(flash_mma,
                         cudaFuncAttributeMaxDynamicSharedMemorySize, FLASH_SMEM);

    // operand conversions
    cvt_split_h<<<(ROWS*(size_t)ND/4 + 255)/256, 256>>>(
        (const float4*)x, (uint2*)xhi, (uint2*)xlo);
    cvt_T_h<<<dim3(QKV_COLS/32, ND/32), dim3(32, 8)>>>(Wqkv, wqT, ND, QKV_COLS);
    cvt_T_h<<<dim3(ND/32, ND/32), dim3(32, 8)>>>(Wout, woT, ND, ND);

    // qkv = x @ Wqkv + b_qkv, written directly as per-head q(hi/lo), k, v
    gemm_mma<1><<<dim3(QKV_COLS/128, ROWS/128), 256, GEMM_SMEM>>>(
        xhi, xlo, wqT, bqkv, nullptr,
        qh, ql, ks, vs, ROWS, QKV_COLS, ND);

    // attention -> writes proj A-operand (fp16 hi/lo) directly
    flash_mma<<<dim3(NS/128, NH, NB), 256, FLASH_SMEM>>>(
        qh, ql, ks, vs, ahi, alo);

    // out = attn @ Wout + b_out
    gemm_mma<0><<<dim3(ND/128, ROWS/128), 256, GEMM_SMEM>>>(
        ahi, alo, woT, bout, out,
        nullptr, nullptr, nullptr, nullptr, ROWS, ND, ND);
}

// round 12
// speedup vs baseline: 6.2411x; 1.2856x over previous
#include <cuda_runtime.h>
#include <cuda_bf16.h>
#include <cuda_fp16.h>
#include <cstdint>
#include <math.h>

#define NB 4
#define NS 2048
#define ND 2048
#define NH 16
#define NHD 128
#define ROWS (NB*NS)        /* 8192 */
#define QKV_COLS (3*ND)     /* 6144 */

// ---------------- scratch (device globals: allocation-free rule) ----------
__device__ __half g_xh[(size_t)ROWS * ND];                 // x single fp16
__device__ __half g_ahi[(size_t)ROWS * ND];                // attn out hi
__device__ __half g_alo[(size_t)ROWS * ND];                // attn out lo
__device__ __half g_wqT[(size_t)QKV_COLS * ND];            // Wqkv^T [6144][2048]
__device__ __half g_woT[(size_t)ND * ND];                  // Wout^T [2048][2048]
// per-head QKV: [B*H][S][HD]; Q split hi/lo, K and V single fp16
__device__ __half g_qhh[(size_t)ROWS * ND];
__device__ __half g_qll[(size_t)ROWS * ND];
__device__ __half g_kk[(size_t)ROWS * ND];
__device__ __half g_vv[(size_t)ROWS * ND];

// ---------------- PTX helpers (baseline features only: sm_80+) ------------
__device__ __forceinline__ uint32_t smem_u32(const void* p) {
    uint32_t a;
    asm("{ .reg .u64 t; cvta.to.shared.u64 t, %1; cvt.u32.u64 %0, t; }"
        : "=r"(a) : "l"(p));
    return a;
}

__device__ __forceinline__ void cpa16(uint32_t s, const void* g) {
    asm volatile("cp.async.cg.shared.global [%0], [%1], 16;" :: "r"(s), "l"(g));
}
#define CP_COMMIT() asm volatile("cp.async.commit_group;" ::: "memory")
#define CP_WAIT(n)  asm volatile("cp.async.wait_group %0;" :: "n"(n) : "memory")

__device__ __forceinline__ void ldsm4(uint32_t* r, uint32_t addr) {
    asm volatile("ldmatrix.sync.aligned.m8n8.x4.shared.b16 {%0,%1,%2,%3}, [%4];"
                 : "=r"(r[0]), "=r"(r[1]), "=r"(r[2]), "=r"(r[3]) : "r"(addr));
}
__device__ __forceinline__ void ldsm4t(uint32_t* r, uint32_t addr) {
    asm volatile("ldmatrix.sync.aligned.m8n8.x4.trans.shared.b16 {%0,%1,%2,%3}, [%4];"
                 : "=r"(r[0]), "=r"(r[1]), "=r"(r[2]), "=r"(r[3]) : "r"(addr));
}

// fp16 mma
__device__ __forceinline__ void mma16816h(float* d, const uint32_t* a,
                                          const uint32_t* b) {
    asm volatile(
        "mma.sync.aligned.m16n8k16.row.col.f32.f16.f16.f32 "
        "{%0,%1,%2,%3}, {%4,%5,%6,%7}, {%8,%9}, {%0,%1,%2,%3};"
        : "+f"(d[0]), "+f"(d[1]), "+f"(d[2]), "+f"(d[3])
        : "r"(a[0]), "r"(a[1]), "r"(a[2]), "r"(a[3]), "r"(b[0]), "r"(b[1]));
}

__device__ __forceinline__ float ex2f(float x) {
    float y;
    asm("ex2.approx.f32 %0, %1;" : "=f"(y) : "f"(x));
    return y;
}

#define PACK2(lo16, hi16) (((uint32_t)(hi16) << 16) | (uint32_t)(lo16))
#define HFU(x) __half_as_ushort(x)

__device__ __forceinline__ uint32_t split_pair_h(float a, float b, uint32_t& lo) {
    __half h0 = __float2half_rn(a), h1 = __float2half_rn(b);
    __half e0 = __float2half_rn(a - __half2float(h0));
    __half e1 = __float2half_rn(b - __half2float(h1));
    lo = PACK2(HFU(e0), HFU(e1));
    return PACK2(HFU(h0), HFU(h1));
}
__device__ __forceinline__ uint32_t pack_h(float a, float b) {
    return PACK2(HFU(__float2half_rn(a)), HFU(__float2half_rn(b)));
}

// ---------------------------------------------------------------------------
// conversion kernels
// ---------------------------------------------------------------------------
__global__ void cvt_h(const float4* __restrict__ in, uint2* __restrict__ hi)
{
    int i = blockIdx.x * blockDim.x + threadIdx.x;
    float4 v = in[i];
    uint2 uh;
    uh.x = pack_h(v.x, v.y);
    uh.y = pack_h(v.z, v.w);
    hi[i] = uh;
}

// W [K][N] fp32  ->  T [N][K] single fp16
__global__ void cvt_T_h(const float* __restrict__ W, __half* __restrict__ Th,
                        int K, int N)
{
    __shared__ float tile[32][33];
    int n0 = blockIdx.x * 32, k0 = blockIdx.y * 32;
    int tx = threadIdx.x, ty = threadIdx.y;  // 32 x 8
    #pragma unroll
    for (int r = 0; r < 4; r++)
        tile[ty + r*8][tx] = W[(size_t)(k0 + ty + r*8) * N + n0 + tx];
    __syncthreads();
    #pragma unroll
    for (int r = 0; r < 4; r++) {
        float v = tile[tx][ty + r*8];
        Th[(size_t)(n0 + ty + r*8) * K + k0 + tx] = __float2half_rn(v);
    }
}

// ---------------------------------------------------------------------------
// fp16 GEMM via mma.sync: C = A @ B^T + bias.
// TERMS=2: A = ah+al (hi/lo split). TERMS=1: A = ah only.
// CTA 128x128, BK=32, 8 warps (4m x 2n), warp tile 32x64, 3-stage cp.async,
// 72KB smem -> 2 CTAs/SM. EPI=0: fp32 C + bias. EPI=1: per-head QKV
// (Q split hi/lo, K and V single fp16).
// ---------------------------------------------------------------------------
#define STAGES 3
#define STAGE_BYTES 24576      /* Ahi 8K | Alo 8K | B 8K */
#define GEMM_SMEM (STAGES * STAGE_BYTES)   /* 72 KB */
#define SWZ(row, kb) ((kb) ^ ((((row) >> 1) & 3) << 4))

template<int TERMS>
__device__ __forceinline__ void issue_stage(
    uint32_t sb_stage, const __half* __restrict__ Ahi,
    const __half* __restrict__ Alo, const __half* __restrict__ B,
    int rowBase, int colBase, int k0, int K, int t)
{
    #pragma unroll
    for (int u = 0; u < 2; u++) {
        int idx = t + 256*u;
        int row = idx >> 2, chunk = idx & 3;
        uint32_t soff = (uint32_t)(row*64 + SWZ(row, chunk*16));
        size_t geA = (size_t)(rowBase + row) * K + k0 + chunk*8;
        size_t geB = (size_t)(colBase + row) * K + k0 + chunk*8;
        cpa16(sb_stage +         soff, Ahi + geA);
        if (TERMS == 2)
            cpa16(sb_stage + 8192 + soff, Alo + geA);
        cpa16(sb_stage + 16384 + soff, B   + geB);
    }
    CP_COMMIT();
}

template<int EPI, int TERMS>
__global__ __launch_bounds__(256, 2)
void gemm_mma(const __half* __restrict__ Ahi, const __half* __restrict__ Alo,
              const __half* __restrict__ B,
              const float* __restrict__ bias, float* __restrict__ C,
              __half* __restrict__ q_h, __half* __restrict__ q_l,
              __half* __restrict__ k_s, __half* __restrict__ v_s,
              int M, int N, int K)
{
    extern __shared__ char sm[];
    const uint32_t sb = smem_u32(sm);

    const int t = threadIdx.x, lane = t & 31, w = t >> 5;
    const int warp_m = w & 3, warp_n = w >> 2;   // 4 x 2
    const int rowBase = blockIdx.y * 128;
    const int colBase = blockIdx.x * 128;
    const int ksteps  = K >> 5;
    const int mat = lane >> 3, r8 = lane & 7;

    float acc[2][8][4];
    #pragma unroll
    for (int i = 0; i < 2; i++)
        #pragma unroll
        for (int j = 0; j < 8; j++)
            #pragma unroll
            for (int q = 0; q < 4; q++) acc[i][j][q] = 0.f;

    issue_stage<TERMS>(sb,               Ahi, Alo, B, rowBase, colBase, 0,  K, t);
    issue_stage<TERMS>(sb + STAGE_BYTES, Ahi, Alo, B, rowBase, colBase, 32, K, t);

    int rowA[2], rowB[4];
    #pragma unroll
    for (int fm = 0; fm < 2; fm++)
        rowA[fm] = warp_m*32 + fm*16 + (mat & 1)*8 + r8;
    #pragma unroll
    for (int fb = 0; fb < 4; fb++)
        rowB[fb] = warp_n*64 + fb*16 + (mat >> 1)*8 + r8;

    for (int i = 0; i < ksteps; i++) {
        CP_WAIT(1);
        __syncthreads();
        const uint32_t st = sb + (uint32_t)(i % 3) * STAGE_BYTES;

        #pragma unroll
        for (int ks = 0; ks < 2; ks++) {
            const int kbA = ks*32 + (mat >> 1)*16;
            const int kbB = ks*32 + (mat & 1)*16;

            uint32_t rh[4][4];
            #pragma unroll
            for (int fb = 0; fb < 4; fb++) {
                uint32_t off = (uint32_t)(rowB[fb]*64 + SWZ(rowB[fb], kbB));
                ldsm4(rh[fb], st + 16384 + off);
            }
            uint32_t ahc[2][4], alc[2][4];
            {
                uint32_t off = (uint32_t)(rowA[0]*64 + SWZ(rowA[0], kbA));
                ldsm4(ahc[0], st + off);
                if (TERMS == 2) ldsm4(alc[0], st + 8192 + off);
            }
            if (ks == 0) {
                if (i + 2 < ksteps)
                    issue_stage<TERMS>(sb + (uint32_t)((i + 2) % 3) * STAGE_BYTES,
                                       Ahi, Alo, B, rowBase, colBase,
                                       (i + 2)*32, K, t);
                else
                    CP_COMMIT();   // keep group accounting uniform
            }

            #pragma unroll
            for (int fm = 0; fm < 2; fm++) {
                const int cur = fm & 1;
                if (fm < 1) {
                    uint32_t off = (uint32_t)(rowA[1]*64 + SWZ(rowA[1], kbA));
                    ldsm4(ahc[1], st + off);
                    if (TERMS == 2) ldsm4(alc[1], st + 8192 + off);
                }
                #pragma unroll
                for (int fb = 0; fb < 4; fb++) {
                    mma16816h(acc[fm][2*fb+0], ahc[cur], rh[fb]);
                    if (TERMS == 2)
                        mma16816h(acc[fm][2*fb+0], alc[cur], rh[fb]);
                    mma16816h(acc[fm][2*fb+1], ahc[cur], rh[fb]+2);
                    if (TERMS == 2)
                        mma16816h(acc[fm][2*fb+1], alc[cur], rh[fb]+2);
                }
            }
        }
    }

    const int qrow = lane >> 2, qcol = (lane & 3) * 2;
    #pragma unroll
    for (int fn = 0; fn < 8; fn++) {
        const int col = colBase + warp_n*64 + fn*8 + qcol;
        const float b0 = bias[col], b1 = bias[col + 1];
        if (EPI == 0) {
            #pragma unroll
            for (int fm = 0; fm < 2; fm++) {
                const int row0 = rowBase + warp_m*32 + fm*16 + qrow;
                float2 v0 = make_float2(acc[fm][fn][0] + b0, acc[fm][fn][1] + b1);
                float2 v1 = make_float2(acc[fm][fn][2] + b0, acc[fm][fn][3] + b1);
                *(float2*)&C[(size_t)row0 * N + col]       = v0;
                *(float2*)&C[(size_t)(row0 + 8) * N + col] = v1;
            }
        } else {
            const int sel = col >> 11, hh = (col >> 7) & 15, hd = col & 127;
            #pragma unroll
            for (int fm = 0; fm < 2; fm++) {
                const int r0 = rowBase + warp_m*32 + fm*16 + qrow;
                #pragma unroll
                for (int rr = 0; rr < 2; rr++) {
                    const int r = r0 + rr*8;
                    float va = acc[fm][fn][rr*2+0] + b0;
                    float vb = acc[fm][fn][rr*2+1] + b1;
                    size_t o = (((size_t)((r >> 11)*NH + hh) * NS +
                                 (r & 2047)) * NHD + hd);
                    if (sel == 0) {
                        uint32_t lo, hi = split_pair_h(va, vb, lo);
                        *(uint32_t*)&q_h[o] = hi;
                        *(uint32_t*)&q_l[o] = lo;
                    } else {
                        __half* d = (sel == 1) ? k_s : v_s;
                        *(uint32_t*)&d[o] = pack_h(va, vb);
                    }
                }
            }
        }
    }
}

// ---------------------------------------------------------------------------
// Flash attention via fp16 mma, 2-term emulation (Q,P split; K,V single).
// Static-max softmax; heavy tiles first; register-stage pipelining.
// smem: 3 KV stages of 32KB (K 16K | V 16K) + persistent Q 64KB (hi|lo).
// ---------------------------------------------------------------------------
#define KV_STAGE 32768
#define FLASH_SMEM (3*KV_STAGE + 65536)   /* 163840 */
#define SWZF(row, chunk) (((chunk) ^ ((row) & 7)) << 4)

__device__ __forceinline__ void flash_load_kv(
    uint32_t st, const __half* __restrict__ k_s,
    const __half* __restrict__ v_s, size_t hb, int kt, int t)
{
    #pragma unroll
    for (int u = 0; u < 4; u++) {
        int idx = t + 256*u;                 // 0..1023
        int row = idx >> 4, chunk = idx & 15;
        uint32_t soff = (uint32_t)(row*256 + SWZF(row, chunk));
        size_t g = hb + (size_t)(kt*64 + row)*NHD + chunk*8;
        cpa16(st +         soff, k_s + g);
        cpa16(st + 16384 + soff, v_s + g);
    }
    CP_COMMIT();
}

__global__ __launch_bounds__(256, 1)
void flash_mma(const __half* __restrict__ qh, const __half* __restrict__ ql,
               const __half* __restrict__ k_s, const __half* __restrict__ v_s,
               __half* __restrict__ ahi, __half* __restrict__ alo)
{
    extern __shared__ char sm[];
    const uint32_t sb = smem_u32(sm);
    const uint32_t qst = sb + 3*KV_STAGE;    // persistent Q region

    const int qt = (NS/128 - 1) - blockIdx.x;   // heavy tiles first
    const int h = blockIdx.y, b = blockIdx.z;
    const int t = threadIdx.x, lane = t & 31, w = t >> 5;
    const size_t hb = (size_t)(b*NH + h) * NS * NHD;

    const float L2E   = 1.4426950408889634f;
    const float scale = 0.08838834764831845f;          // 1/sqrt(128)
    const float slope = exp2f(-0.5f * (float)(h + 1)); // ALiBi, H=16
    const float c1  = scale * L2E;
    const float sl2 = slope * L2E;
    const float mc8 = -8.0f * L2E;
    const int r8 = lane & 7, m01 = (lane >> 3) & 1, m2 = lane >> 4;
    const int qr = lane >> 2, qc = (lane & 3) * 2;
    const int rg0 = qt*128 + w*16 + qr;                // global q row (c0/c1)

    // stage Q (hi|lo) into the persistent region
    #pragma unroll
    for (int u = 0; u < 8; u++) {
        int idx = t + 256*u;                 // 0..2047
        int row = idx >> 4, chunk = idx & 15;
        uint32_t soff = (uint32_t)(row*256 + SWZF(row, chunk));
        size_t g = hb + (size_t)(qt*128 + row)*NHD + chunk*8;
        cpa16(qst +         soff, qh + g);
        cpa16(qst + 32768 + soff, ql + g);
    }
    CP_COMMIT();                             // group: Q
    flash_load_kv(sb,            k_s, v_s, hb, 0, t);   // group: KV0
    flash_load_kv(sb + KV_STAGE, k_s, v_s, hb, 1, t);   // group: KV1

    CP_WAIT(2);                              // Q complete
    __syncthreads();

    // Q fragments -> registers
    uint32_t fqh[8][4], fql[8][4];
    {
        const int qrow = w*16 + m01*8 + r8;
        #pragma unroll
        for (int kc = 0; kc < 8; kc++) {
            uint32_t qa = qst + (uint32_t)(qrow*256 + SWZF(qrow, kc*2 + m2));
            ldsm4(fqh[kc], qa);
            ldsm4(fql[kc], qa + 32768);
        }
    }

    float l0 = 0.f, l1 = 0.f;
    float acc_o[16][4];
    #pragma unroll
    for (int i = 0; i < 16; i++)
        #pragma unroll
        for (int j = 0; j < 4; j++) acc_o[i][j] = 0.f;

    const int nkt = 2*qt + 2;
    for (int kt = 0; kt < nkt; kt++) {
        CP_WAIT(1);
        __syncthreads();
        const uint32_t st = sb + (uint32_t)(kt % 3)*KV_STAGE;

        // ---- S = Q K^T (2-term), K frags double-buffered over ng ----
        float s_[8][4];
        #pragma unroll
        for (int i = 0; i < 8; i++)
            #pragma unroll
            for (int j = 0; j < 4; j++) s_[i][j] = 0.f;

        #pragma unroll
        for (int kc = 0; kc < 8; kc++) {
            const int kchk = kc*2 + m01;
            uint32_t rh[2][4];
            {
                int krow = m2*8 + r8;                // ng = 0
                ldsm4(rh[0], st + (uint32_t)(krow*256 + SWZF(krow, kchk)));
            }
            if (kc == 0) {
                if (kt + 2 < nkt)
                    flash_load_kv(sb + (uint32_t)((kt + 2) % 3)*KV_STAGE,
                                  k_s, v_s, hb, kt + 2, t);
                else
                    CP_COMMIT();
            }
            #pragma unroll
            for (int ng = 0; ng < 4; ng++) {
                const int cur = ng & 1;
                if (ng < 3) {
                    int krow = (ng+1)*16 + m2*8 + r8;
                    ldsm4(rh[cur^1],
                          st + (uint32_t)(krow*256 + SWZF(krow, kchk)));
                }
                mma16816h(s_[ng*2+0], fqh[kc], rh[cur]);
                mma16816h(s_[ng*2+0], fql[kc], rh[cur]);
                mma16816h(s_[ng*2+1], fqh[kc], rh[cur]+2);
                mma16816h(s_[ng*2+1], fql[kc], rh[cur]+2);
            }
        }

        // ---- static-max softmax ----
        const bool diag = (kt >= 2*qt);
        const float baseA = fmaf((float)(kt*64 + qc - rg0), sl2, mc8);
        const float baseB = baseA - 8.0f*sl2;   // rows rg0+8
        if (diag) {
            #pragma unroll
            for (int nt = 0; nt < 8; nt++) {
                #pragma unroll
                for (int jj = 0; jj < 2; jj++) {
                    const float cf = (float)(nt*8 + jj);
                    float a0 = fmaf(s_[nt][jj],     c1, fmaf(cf, sl2, baseA));
                    float a1 = fmaf(s_[nt][2 + jj], c1, fmaf(cf, sl2, baseB));
                    int col = kt*64 + nt*8 + qc + jj;
                    if (col > rg0)     a0 = -10000.f;
                    if (col > rg0 + 8) a1 = -10000.f;
                    float p0 = ex2f(a0), p1 = ex2f(a1);
                    l0 += p0; l1 += p1;
                    s_[nt][jj] = p0; s_[nt][2 + jj] = p1;
                }
            }
        } else {
            #pragma unroll
            for (int nt = 0; nt < 8; nt++) {
                #pragma unroll
                for (int jj = 0; jj < 2; jj++) {
                    const float cf = (float)(nt*8 + jj);
                    float a0 = fmaf(s_[nt][jj],     c1, fmaf(cf, sl2, baseA));
                    float a1 = fmaf(s_[nt][2 + jj], c1, fmaf(cf, sl2, baseB));
                    float p0 = ex2f(a0), p1 = ex2f(a1);
                    l0 += p0; l1 += p1;
                    s_[nt][jj] = p0; s_[nt][2 + jj] = p1;
                }
            }
        }

        // ---- O += P V (2-term), V frags double-buffered over ng ----
        #pragma unroll
        for (int kc = 0; kc < 4; kc++) {
            uint32_t ph[4], pl[4];
            {
                const float* pa = s_[2*kc];
                const float* pb = s_[2*kc + 1];
                ph[0] = split_pair_h(pa[0], pa[1], pl[0]);
                ph[1] = split_pair_h(pa[2], pa[3], pl[1]);
                ph[2] = split_pair_h(pb[0], pb[1], pl[2]);
                ph[3] = split_pair_h(pb[2], pb[3], pl[3]);
            }
            const int vrow = kc*16 + m01*8 + r8;
            const uint32_t vbase = st + 16384 + (uint32_t)(vrow*256);
            uint32_t wh[2][4];
            ldsm4t(wh[0], vbase + (uint32_t)SWZF(vrow, m2));   // ng = 0
            #pragma unroll
            for (int ng = 0; ng < 8; ng++) {
                const int cur = ng & 1;
                if (ng < 7)
                    ldsm4t(wh[cur^1],
                           vbase + (uint32_t)SWZF(vrow, (ng+1)*2 + m2));
                mma16816h(acc_o[ng*2+0], ph, wh[cur]);
                mma16816h(acc_o[ng*2+0], pl, wh[cur]);
                mma16816h(acc_o[ng*2+1], ph, wh[cur]+2);
                mma16816h(acc_o[ng*2+1], pl, wh[cur]+2);
            }
        }
    }

    // ---- finalize ----
    l0 += __shfl_xor_sync(0xffffffffu, l0, 1);
    l0 += __shfl_xor_sync(0xffffffffu, l0, 2);
    l1 += __shfl_xor_sync(0xffffffffu, l1, 1);
    l1 += __shfl_xor_sync(0xffffffffu, l1, 2);
    const float inv0 = 1.f / l0, inv1 = 1.f / l1;

    const size_t row0 = (size_t)(b*NS) + qt*128 + w*16 + qr;
    #pragma unroll
    for (int nt = 0; nt < 16; nt++) {
        int col = h*NHD + nt*8 + qc;
        uint32_t lo0, lo1;
        uint32_t hi0 = split_pair_h(acc_o[nt][0]*inv0, acc_o[nt][1]*inv0, lo0);
        uint32_t hi1 = split_pair_h(acc_o[nt][2]*inv1, acc_o[nt][3]*inv1, lo1);
        *(uint32_t*)&ahi[row0 * ND + col]       = hi0;
        *(uint32_t*)&alo[row0 * ND + col]       = lo0;
        *(uint32_t*)&ahi[(row0 + 8) * ND + col] = hi1;
        *(uint32_t*)&alo[(row0 + 8) * ND + col] = lo1;
    }
}

// ---------------------------------------------------------------------------
extern "C" void kernel_launch(void* const* d_in, const int* in_sizes, int n_in,
                              void* d_out, int out_size)
{
    const float* x    = (const float*)d_in[0];
    const float* Wqkv = (const float*)d_in[1];
    const float* bqkv = (const float*)d_in[2];
    const float* Wout = (const float*)d_in[3];
    const float* bout = (const float*)d_in[4];
    float* out = (float*)d_out;

    __half *xh, *ahi, *alo, *wqT, *woT, *qh, *ql, *ks, *vs;
    cudaGetSymbolAddress((void**)&xh,   g_xh);
    cudaGetSymbolAddress((void**)&ahi,  g_ahi);
    cudaGetSymbolAddress((void**)&alo,  g_alo);
    cudaGetSymbolAddress((void**)&wqT,  g_wqT);
    cudaGetSymbolAddress((void**)&woT,  g_woT);
    cudaGetSymbolAddress((void**)&qh,   g_qhh);
    cudaGetSymbolAddress((void**)&ql,   g_qll);
    cudaGetSymbolAddress((void**)&ks,   g_kk);
    cudaGetSymbolAddress((void**)&vs,   g_vv);

    cudaFuncSetAttribute((const void*)gemm_mma<0,2>,
                         cudaFuncAttributeMaxDynamicSharedMemorySize, GEMM_SMEM);
    cudaFuncSetAttribute((const void*)gemm_mma<1,1>,
                         cudaFuncAttributeMaxDynamicSharedMemorySize, GEMM_SMEM);
    cudaFuncSetAttribute(flash_mma,
                         cudaFuncAttributeMaxDynamicSharedMemorySize, FLASH_SMEM);

    // operand conversions
    cvt_h<<<(ROWS*(size_t)ND/4 + 255)/256, 256>>>((const float4*)x, (uint2*)xh);
    cvt_T_h<<<dim3(QKV_COLS/32, ND/32), dim3(32, 8)>>>(Wqkv, wqT, ND, QKV_COLS);
    cvt_T_h<<<dim3(ND/32, ND/32), dim3(32, 8)>>>(Wout, woT, ND, ND);

    // qkv = x @ Wqkv + b_qkv (1-term A), written as per-head q(hi/lo), k, v
    gemm_mma<1,1><<<dim3(QKV_COLS/128, ROWS/128), 256, GEMM_SMEM>>>(
        xh, nullptr, wqT, bqkv, nullptr,
        qh, ql, ks, vs, ROWS, QKV_COLS, ND);

    // attention -> writes proj A-operand (fp16 hi/lo) directly
    flash_mma<<<dim3(NS/128, NH, NB), 256, FLASH_SMEM>>>(
        qh, ql, ks, vs, ahi, alo);

    // out = attn @ Wout + b_out (2-term A)
    gemm_mma<0,2><<<dim3(ND/128, ROWS/128), 256, GEMM_SMEM>>>(
        ahi, alo, woT, bout, out,
        nullptr, nullptr, nullptr, nullptr, ROWS, ND, ND);
}

// round 13
// speedup vs baseline: 7.5112x; 1.2035x over previous
#include <cuda_runtime.h>
#include <cuda_bf16.h>
#include <cuda_fp16.h>
#include <cstdint>
#include <math.h>

#define NB 4
#define NS 2048
#define ND 2048
#define NH 16
#define NHD 128
#define ROWS (NB*NS)        /* 8192 */
#define QKV_COLS (3*ND)     /* 6144 */

// ---------------- scratch (device globals: allocation-free rule) ----------
__device__ __half g_xh[(size_t)ROWS * ND];                 // x single fp16
__device__ __half g_ao[(size_t)ROWS * ND];                 // attn out (single)
__device__ __half g_wqT[(size_t)QKV_COLS * ND];            // Wqkv^T [6144][2048]
__device__ __half g_woT[(size_t)ND * ND];                  // Wout^T [2048][2048]
// per-head QKV: [B*H][S][HD]; Q split hi/lo, K and V single fp16
__device__ __half g_qhh[(size_t)ROWS * ND];
__device__ __half g_qll[(size_t)ROWS * ND];
__device__ __half g_kk[(size_t)ROWS * ND];
__device__ __half g_vv[(size_t)ROWS * ND];

// ---------------- PTX helpers (baseline features only: sm_80+) ------------
__device__ __forceinline__ uint32_t smem_u32(const void* p) {
    uint32_t a;
    asm("{ .reg .u64 t; cvta.to.shared.u64 t, %1; cvt.u32.u64 %0, t; }"
        : "=r"(a) : "l"(p));
    return a;
}

__device__ __forceinline__ void cpa16(uint32_t s, const void* g) {
    asm volatile("cp.async.cg.shared.global [%0], [%1], 16;" :: "r"(s), "l"(g));
}
#define CP_COMMIT() asm volatile("cp.async.commit_group;" ::: "memory")
#define CP_WAIT(n)  asm volatile("cp.async.wait_group %0;" :: "n"(n) : "memory")

__device__ __forceinline__ void ldsm4(uint32_t* r, uint32_t addr) {
    asm volatile("ldmatrix.sync.aligned.m8n8.x4.shared.b16 {%0,%1,%2,%3}, [%4];"
                 : "=r"(r[0]), "=r"(r[1]), "=r"(r[2]), "=r"(r[3]) : "r"(addr));
}
__device__ __forceinline__ void ldsm4t(uint32_t* r, uint32_t addr) {
    asm volatile("ldmatrix.sync.aligned.m8n8.x4.trans.shared.b16 {%0,%1,%2,%3}, [%4];"
                 : "=r"(r[0]), "=r"(r[1]), "=r"(r[2]), "=r"(r[3]) : "r"(addr));
}

// fp16 mma
__device__ __forceinline__ void mma16816h(float* d, const uint32_t* a,
                                          const uint32_t* b) {
    asm volatile(
        "mma.sync.aligned.m16n8k16.row.col.f32.f16.f16.f32 "
        "{%0,%1,%2,%3}, {%4,%5,%6,%7}, {%8,%9}, {%0,%1,%2,%3};"
        : "+f"(d[0]), "+f"(d[1]), "+f"(d[2]), "+f"(d[3])
        : "r"(a[0]), "r"(a[1]), "r"(a[2]), "r"(a[3]), "r"(b[0]), "r"(b[1]));
}

__device__ __forceinline__ float ex2f(float x) {
    float y;
    asm("ex2.approx.f32 %0, %1;" : "=f"(y) : "f"(x));
    return y;
}

#define PACK2(lo16, hi16) (((uint32_t)(hi16) << 16) | (uint32_t)(lo16))
#define HFU(x) __half_as_ushort(x)

__device__ __forceinline__ uint32_t split_pair_h(float a, float b, uint32_t& lo) {
    __half h0 = __float2half_rn(a), h1 = __float2half_rn(b);
    __half e0 = __float2half_rn(a - __half2float(h0));
    __half e1 = __float2half_rn(b - __half2float(h1));
    lo = PACK2(HFU(e0), HFU(e1));
    return PACK2(HFU(h0), HFU(h1));
}
__device__ __forceinline__ uint32_t pack_h(float a, float b) {
    return PACK2(HFU(__float2half_rn(a)), HFU(__float2half_rn(b)));
}

// ---------------------------------------------------------------------------
// conversion kernels
// ---------------------------------------------------------------------------
__global__ void cvt_h(const float4* __restrict__ in, uint2* __restrict__ hi)
{
    int i = blockIdx.x * blockDim.x + threadIdx.x;
    float4 v = in[i];
    uint2 uh;
    uh.x = pack_h(v.x, v.y);
    uh.y = pack_h(v.z, v.w);
    hi[i] = uh;
}

// W [K][N] fp32  ->  T [N][K] single fp16
__global__ void cvt_T_h(const float* __restrict__ W, __half* __restrict__ Th,
                        int K, int N)
{
    __shared__ float tile[32][33];
    int n0 = blockIdx.x * 32, k0 = blockIdx.y * 32;
    int tx = threadIdx.x, ty = threadIdx.y;  // 32 x 8
    #pragma unroll
    for (int r = 0; r < 4; r++)
        tile[ty + r*8][tx] = W[(size_t)(k0 + ty + r*8) * N + n0 + tx];
    __syncthreads();
    #pragma unroll
    for (int r = 0; r < 4; r++) {
        float v = tile[tx][ty + r*8];
        Th[(size_t)(n0 + ty + r*8) * K + k0 + tx] = __float2half_rn(v);
    }
}

// ---------------------------------------------------------------------------
// fp16 GEMM via mma.sync: C = A @ B^T + bias.
// TERMS=2: A = ah+al (hi/lo split). TERMS=1: A = ah only.
// CTA 128x128, BK=32, 8 warps (4m x 2n), warp tile 32x64, 3-stage cp.async,
// 72KB smem -> 2 CTAs/SM. EPI=0: fp32 C + bias. EPI=1: per-head QKV
// (Q split hi/lo, K and V single fp16).
// ---------------------------------------------------------------------------
#define STAGES 3
#define STAGE_BYTES 24576      /* Ahi 8K | Alo 8K | B 8K */
#define GEMM_SMEM (STAGES * STAGE_BYTES)   /* 72 KB */
#define SWZ(row, kb) ((kb) ^ ((((row) >> 1) & 3) << 4))

template<int TERMS>
__device__ __forceinline__ void issue_stage(
    uint32_t sb_stage, const __half* __restrict__ Ahi,
    const __half* __restrict__ Alo, const __half* __restrict__ B,
    int rowBase, int colBase, int k0, int K, int t)
{
    #pragma unroll
    for (int u = 0; u < 2; u++) {
        int idx = t + 256*u;
        int row = idx >> 2, chunk = idx & 3;
        uint32_t soff = (uint32_t)(row*64 + SWZ(row, chunk*16));
        size_t geA = (size_t)(rowBase + row) * K + k0 + chunk*8;
        size_t geB = (size_t)(colBase + row) * K + k0 + chunk*8;
        cpa16(sb_stage +         soff, Ahi + geA);
        if (TERMS == 2)
            cpa16(sb_stage + 8192 + soff, Alo + geA);
        cpa16(sb_stage + 16384 + soff, B   + geB);
    }
    CP_COMMIT();
}

template<int EPI, int TERMS>
__global__ __launch_bounds__(256, 2)
void gemm_mma(const __half* __restrict__ Ahi, const __half* __restrict__ Alo,
              const __half* __restrict__ B,
              const float* __restrict__ bias, float* __restrict__ C,
              __half* __restrict__ q_h, __half* __restrict__ q_l,
              __half* __restrict__ k_s, __half* __restrict__ v_s,
              int M, int N, int K)
{
    extern __shared__ char sm[];
    const uint32_t sb = smem_u32(sm);

    const int t = threadIdx.x, lane = t & 31, w = t >> 5;
    const int warp_m = w & 3, warp_n = w >> 2;   // 4 x 2
    const int rowBase = blockIdx.y * 128;
    const int colBase = blockIdx.x * 128;
    const int ksteps  = K >> 5;
    const int mat = lane >> 3, r8 = lane & 7;

    float acc[2][8][4];
    #pragma unroll
    for (int i = 0; i < 2; i++)
        #pragma unroll
        for (int j = 0; j < 8; j++)
            #pragma unroll
            for (int q = 0; q < 4; q++) acc[i][j][q] = 0.f;

    issue_stage<TERMS>(sb,               Ahi, Alo, B, rowBase, colBase, 0,  K, t);
    issue_stage<TERMS>(sb + STAGE_BYTES, Ahi, Alo, B, rowBase, colBase, 32, K, t);

    int rowA[2], rowB[4];
    #pragma unroll
    for (int fm = 0; fm < 2; fm++)
        rowA[fm] = warp_m*32 + fm*16 + (mat & 1)*8 + r8;
    #pragma unroll
    for (int fb = 0; fb < 4; fb++)
        rowB[fb] = warp_n*64 + fb*16 + (mat >> 1)*8 + r8;

    for (int i = 0; i < ksteps; i++) {
        CP_WAIT(1);
        __syncthreads();
        const uint32_t st = sb + (uint32_t)(i % 3) * STAGE_BYTES;

        #pragma unroll
        for (int ks = 0; ks < 2; ks++) {
            const int kbA = ks*32 + (mat >> 1)*16;
            const int kbB = ks*32 + (mat & 1)*16;

            uint32_t rh[4][4];
            #pragma unroll
            for (int fb = 0; fb < 4; fb++) {
                uint32_t off = (uint32_t)(rowB[fb]*64 + SWZ(rowB[fb], kbB));
                ldsm4(rh[fb], st + 16384 + off);
            }
            uint32_t ahc[2][4], alc[2][4];
            {
                uint32_t off = (uint32_t)(rowA[0]*64 + SWZ(rowA[0], kbA));
                ldsm4(ahc[0], st + off);
                if (TERMS == 2) ldsm4(alc[0], st + 8192 + off);
            }
            if (ks == 0) {
                if (i + 2 < ksteps)
                    issue_stage<TERMS>(sb + (uint32_t)((i + 2) % 3) * STAGE_BYTES,
                                       Ahi, Alo, B, rowBase, colBase,
                                       (i + 2)*32, K, t);
                else
                    CP_COMMIT();   // keep group accounting uniform
            }

            #pragma unroll
            for (int fm = 0; fm < 2; fm++) {
                const int cur = fm & 1;
                if (fm < 1) {
                    uint32_t off = (uint32_t)(rowA[1]*64 + SWZ(rowA[1], kbA));
                    ldsm4(ahc[1], st + off);
                    if (TERMS == 2) ldsm4(alc[1], st + 8192 + off);
                }
                #pragma unroll
                for (int fb = 0; fb < 4; fb++) {
                    mma16816h(acc[fm][2*fb+0], ahc[cur], rh[fb]);
                    if (TERMS == 2)
                        mma16816h(acc[fm][2*fb+0], alc[cur], rh[fb]);
                    mma16816h(acc[fm][2*fb+1], ahc[cur], rh[fb]+2);
                    if (TERMS == 2)
                        mma16816h(acc[fm][2*fb+1], alc[cur], rh[fb]+2);
                }
            }
        }
    }

    const int qrow = lane >> 2, qcol = (lane & 3) * 2;
    #pragma unroll
    for (int fn = 0; fn < 8; fn++) {
        const int col = colBase + warp_n*64 + fn*8 + qcol;
        const float b0 = bias[col], b1 = bias[col + 1];
        if (EPI == 0) {
            #pragma unroll
            for (int fm = 0; fm < 2; fm++) {
                const int row0 = rowBase + warp_m*32 + fm*16 + qrow;
                float2 v0 = make_float2(acc[fm][fn][0] + b0, acc[fm][fn][1] + b1);
                float2 v1 = make_float2(acc[fm][fn][2] + b0, acc[fm][fn][3] + b1);
                *(float2*)&C[(size_t)row0 * N + col]       = v0;
                *(float2*)&C[(size_t)(row0 + 8) * N + col] = v1;
            }
        } else {
            const int sel = col >> 11, hh = (col >> 7) & 15, hd = col & 127;
            #pragma unroll
            for (int fm = 0; fm < 2; fm++) {
                const int r0 = rowBase + warp_m*32 + fm*16 + qrow;
                #pragma unroll
                for (int rr = 0; rr < 2; rr++) {
                    const int r = r0 + rr*8;
                    float va = acc[fm][fn][rr*2+0] + b0;
                    float vb = acc[fm][fn][rr*2+1] + b1;
                    size_t o = (((size_t)((r >> 11)*NH + hh) * NS +
                                 (r & 2047)) * NHD + hd);
                    if (sel == 0) {
                        uint32_t lo, hi = split_pair_h(va, vb, lo);
                        *(uint32_t*)&q_h[o] = hi;
                        *(uint32_t*)&q_l[o] = lo;
                    } else {
                        __half* d = (sel == 1) ? k_s : v_s;
                        *(uint32_t*)&d[o] = pack_h(va, vb);
                    }
                }
            }
        }
    }
}

// ---------------------------------------------------------------------------
// Flash attention via fp16 mma. Q 2-term (hi/lo); K, V, P single fp16.
// Static-max softmax; heavy tiles first; register-stage pipelining.
// smem: 3 KV stages of 32KB (K 16K | V 16K) + persistent Q 64KB (hi|lo).
// Epilogue writes single-fp16 attention output (proj GEMM A-operand).
// ---------------------------------------------------------------------------
#define KV_STAGE 32768
#define FLASH_SMEM (3*KV_STAGE + 65536)   /* 163840 */
#define SWZF(row, chunk) (((chunk) ^ ((row) & 7)) << 4)

__device__ __forceinline__ void flash_load_kv(
    uint32_t st, const __half* __restrict__ k_s,
    const __half* __restrict__ v_s, size_t hb, int kt, int t)
{
    #pragma unroll
    for (int u = 0; u < 4; u++) {
        int idx = t + 256*u;                 // 0..1023
        int row = idx >> 4, chunk = idx & 15;
        uint32_t soff = (uint32_t)(row*256 + SWZF(row, chunk));
        size_t g = hb + (size_t)(kt*64 + row)*NHD + chunk*8;
        cpa16(st +         soff, k_s + g);
        cpa16(st + 16384 + soff, v_s + g);
    }
    CP_COMMIT();
}

__global__ __launch_bounds__(256, 1)
void flash_mma(const __half* __restrict__ qh, const __half* __restrict__ ql,
               const __half* __restrict__ k_s, const __half* __restrict__ v_s,
               __half* __restrict__ ao)
{
    extern __shared__ char sm[];
    const uint32_t sb = smem_u32(sm);
    const uint32_t qst = sb + 3*KV_STAGE;    // persistent Q region

    const int qt = (NS/128 - 1) - blockIdx.x;   // heavy tiles first
    const int h = blockIdx.y, b = blockIdx.z;
    const int t = threadIdx.x, lane = t & 31, w = t >> 5;
    const size_t hb = (size_t)(b*NH + h) * NS * NHD;

    const float L2E   = 1.4426950408889634f;
    const float scale = 0.08838834764831845f;          // 1/sqrt(128)
    const float slope = exp2f(-0.5f * (float)(h + 1)); // ALiBi, H=16
    const float c1  = scale * L2E;
    const float sl2 = slope * L2E;
    const float mc8 = -8.0f * L2E;
    const int r8 = lane & 7, m01 = (lane >> 3) & 1, m2 = lane >> 4;
    const int qr = lane >> 2, qc = (lane & 3) * 2;
    const int rg0 = qt*128 + w*16 + qr;                // global q row (c0/c1)

    // stage Q (hi|lo) into the persistent region
    #pragma unroll
    for (int u = 0; u < 8; u++) {
        int idx = t + 256*u;                 // 0..2047
        int row = idx >> 4, chunk = idx & 15;
        uint32_t soff = (uint32_t)(row*256 + SWZF(row, chunk));
        size_t g = hb + (size_t)(qt*128 + row)*NHD + chunk*8;
        cpa16(qst +         soff, qh + g);
        cpa16(qst + 32768 + soff, ql + g);
    }
    CP_COMMIT();                             // group: Q
    flash_load_kv(sb,            k_s, v_s, hb, 0, t);   // group: KV0
    flash_load_kv(sb + KV_STAGE, k_s, v_s, hb, 1, t);   // group: KV1

    CP_WAIT(2);                              // Q complete
    __syncthreads();

    // Q fragments -> registers
    uint32_t fqh[8][4], fql[8][4];
    {
        const int qrow = w*16 + m01*8 + r8;
        #pragma unroll
        for (int kc = 0; kc < 8; kc++) {
            uint32_t qa = qst + (uint32_t)(qrow*256 + SWZF(qrow, kc*2 + m2));
            ldsm4(fqh[kc], qa);
            ldsm4(fql[kc], qa + 32768);
        }
    }

    float l0 = 0.f, l1 = 0.f;
    float acc_o[16][4];
    #pragma unroll
    for (int i = 0; i < 16; i++)
        #pragma unroll
        for (int j = 0; j < 4; j++) acc_o[i][j] = 0.f;

    const int nkt = 2*qt + 2;
    for (int kt = 0; kt < nkt; kt++) {
        CP_WAIT(1);
        __syncthreads();
        const uint32_t st = sb + (uint32_t)(kt % 3)*KV_STAGE;

        // ---- S = Q K^T (2-term), K frags double-buffered over ng ----
        float s_[8][4];
        #pragma unroll
        for (int i = 0; i < 8; i++)
            #pragma unroll
            for (int j = 0; j < 4; j++) s_[i][j] = 0.f;

        #pragma unroll
        for (int kc = 0; kc < 8; kc++) {
            const int kchk = kc*2 + m01;
            uint32_t rh[2][4];
            {
                int krow = m2*8 + r8;                // ng = 0
                ldsm4(rh[0], st + (uint32_t)(krow*256 + SWZF(krow, kchk)));
            }
            if (kc == 0) {
                if (kt + 2 < nkt)
                    flash_load_kv(sb + (uint32_t)((kt + 2) % 3)*KV_STAGE,
                                  k_s, v_s, hb, kt + 2, t);
                else
                    CP_COMMIT();
            }
            #pragma unroll
            for (int ng = 0; ng < 4; ng++) {
                const int cur = ng & 1;
                if (ng < 3) {
                    int krow = (ng+1)*16 + m2*8 + r8;
                    ldsm4(rh[cur^1],
                          st + (uint32_t)(krow*256 + SWZF(krow, kchk)));
                }
                mma16816h(s_[ng*2+0], fqh[kc], rh[cur]);
                mma16816h(s_[ng*2+0], fql[kc], rh[cur]);
                mma16816h(s_[ng*2+1], fqh[kc], rh[cur]+2);
                mma16816h(s_[ng*2+1], fql[kc], rh[cur]+2);
            }
        }

        // ---- static-max softmax ----
        const bool diag = (kt >= 2*qt);
        const float baseA = fmaf((float)(kt*64 + qc - rg0), sl2, mc8);
        const float baseB = baseA - 8.0f*sl2;   // rows rg0+8
        if (diag) {
            #pragma unroll
            for (int nt = 0; nt < 8; nt++) {
                #pragma unroll
                for (int jj = 0; jj < 2; jj++) {
                    const float cf = (float)(nt*8 + jj);
                    float a0 = fmaf(s_[nt][jj],     c1, fmaf(cf, sl2, baseA));
                    float a1 = fmaf(s_[nt][2 + jj], c1, fmaf(cf, sl2, baseB));
                    int col = kt*64 + nt*8 + qc + jj;
                    if (col > rg0)     a0 = -10000.f;
                    if (col > rg0 + 8) a1 = -10000.f;
                    float p0 = ex2f(a0), p1 = ex2f(a1);
                    l0 += p0; l1 += p1;
                    s_[nt][jj] = p0; s_[nt][2 + jj] = p1;
                }
            }
        } else {
            #pragma unroll
            for (int nt = 0; nt < 8; nt++) {
                #pragma unroll
                for (int jj = 0; jj < 2; jj++) {
                    const float cf = (float)(nt*8 + jj);
                    float a0 = fmaf(s_[nt][jj],     c1, fmaf(cf, sl2, baseA));
                    float a1 = fmaf(s_[nt][2 + jj], c1, fmaf(cf, sl2, baseB));
                    float p0 = ex2f(a0), p1 = ex2f(a1);
                    l0 += p0; l1 += p1;
                    s_[nt][jj] = p0; s_[nt][2 + jj] = p1;
                }
            }
        }

        // ---- O += P V (P single fp16), V frags double-buffered over ng ----
        #pragma unroll
        for (int kc = 0; kc < 4; kc++) {
            uint32_t ph[4];
            {
                const float* pa = s_[2*kc];
                const float* pb = s_[2*kc + 1];
                ph[0] = pack_h(pa[0], pa[1]);
                ph[1] = pack_h(pa[2], pa[3]);
                ph[2] = pack_h(pb[0], pb[1]);
                ph[3] = pack_h(pb[2], pb[3]);
            }
            const int vrow = kc*16 + m01*8 + r8;
            const uint32_t vbase = st + 16384 + (uint32_t)(vrow*256);
            uint32_t wh[2][4];
            ldsm4t(wh[0], vbase + (uint32_t)SWZF(vrow, m2));   // ng = 0
            #pragma unroll
            for (int ng = 0; ng < 8; ng++) {
                const int cur = ng & 1;
                if (ng < 7)
                    ldsm4t(wh[cur^1],
                           vbase + (uint32_t)SWZF(vrow, (ng+1)*2 + m2));
                mma16816h(acc_o[ng*2+0], ph, wh[cur]);
                mma16816h(acc_o[ng*2+1], ph, wh[cur]+2);
            }
        }
    }

    // ---- finalize ----
    l0 += __shfl_xor_sync(0xffffffffu, l0, 1);
    l0 += __shfl_xor_sync(0xffffffffu, l0, 2);
    l1 += __shfl_xor_sync(0xffffffffu, l1, 1);
    l1 += __shfl_xor_sync(0xffffffffu, l1, 2);
    const float inv0 = 1.f / l0, inv1 = 1.f / l1;

    const size_t row0 = (size_t)(b*NS) + qt*128 + w*16 + qr;
    #pragma unroll
    for (int nt = 0; nt < 16; nt++) {
        int col = h*NHD + nt*8 + qc;
        *(uint32_t*)&ao[row0 * ND + col] =
            pack_h(acc_o[nt][0]*inv0, acc_o[nt][1]*inv0);
        *(uint32_t*)&ao[(row0 + 8) * ND + col] =
            pack_h(acc_o[nt][2]*inv1, acc_o[nt][3]*inv1);
    }
}

// ---------------------------------------------------------------------------
extern "C" void kernel_launch(void* const* d_in, const int* in_sizes, int n_in,
                              void* d_out, int out_size)
{
    const float* x    = (const float*)d_in[0];
    const float* Wqkv = (const float*)d_in[1];
    const float* bqkv = (const float*)d_in[2];
    const float* Wout = (const float*)d_in[3];
    const float* bout = (const float*)d_in[4];
    float* out = (float*)d_out;

    __half *xh, *ao, *wqT, *woT, *qh, *ql, *ks, *vs;
    cudaGetSymbolAddress((void**)&xh,   g_xh);
    cudaGetSymbolAddress((void**)&ao,   g_ao);
    cudaGetSymbolAddress((void**)&wqT,  g_wqT);
    cudaGetSymbolAddress((void**)&woT,  g_woT);
    cudaGetSymbolAddress((void**)&qh,   g_qhh);
    cudaGetSymbolAddress((void**)&ql,   g_qll);
    cudaGetSymbolAddress((void**)&ks,   g_kk);
    cudaGetSymbolAddress((void**)&vs,   g_vv);

    cudaFuncSetAttribute((const void*)gemm_mma<0,1>,
                         cudaFuncAttributeMaxDynamicSharedMemorySize, GEMM_SMEM);
    cudaFuncSetAttribute((const void*)gemm_mma<1,1>,
                         cudaFuncAttributeMaxDynamicSharedMemorySize, GEMM_SMEM);
    cudaFuncSetAttribute(flash_mma,
                         cudaFuncAttributeMaxDynamicSharedMemorySize, FLASH_SMEM);

    // operand conversions
    cvt_h<<<(ROWS*(size_t)ND/4 + 255)/256, 256>>>((const float4*)x, (uint2*)xh);
    cvt_T_h<<<dim3(QKV_COLS/32, ND/32), dim3(32, 8)>>>(Wqkv, wqT, ND, QKV_COLS);
    cvt_T_h<<<dim3(ND/32, ND/32), dim3(32, 8)>>>(Wout, woT, ND, ND);

    // qkv = x @ Wqkv + b_qkv (1-term A), written as per-head q(hi/lo), k, v
    gemm_mma<1,1><<<dim3(QKV_COLS/128, ROWS/128), 256, GEMM_SMEM>>>(
        xh, nullptr, wqT, bqkv, nullptr,
        qh, ql, ks, vs, ROWS, QKV_COLS, ND);

    // attention -> writes proj A-operand (single fp16) directly
    flash_mma<<<dim3(NS/128, NH, NB), 256, FLASH_SMEM>>>(
        qh, ql, ks, vs, ao);

    // out = attn @ Wout + b_out (1-term A)
    gemm_mma<0,1><<<dim3(ND/128, ROWS/128), 256, GEMM_SMEM>>>(
        ao, nullptr, woT, bout, out,
        nullptr, nullptr, nullptr, nullptr, ROWS, ND, ND);
}

// round 14
// speedup vs baseline: 8.3996x; 1.1183x over previous
#include <cuda_runtime.h>
#include <cuda_bf16.h>
#include <cuda_fp16.h>
#include <cstdint>
#include <math.h>

#define NB 4
#define NS 2048
#define ND 2048
#define NH 16
#define NHD 128
#define ROWS (NB*NS)        /* 8192 */
#define QKV_COLS (3*ND)     /* 6144 */

// ---------------- scratch (device globals: allocation-free rule) ----------
__device__ __half g_xh[(size_t)ROWS * ND];                 // x single fp16
__device__ __half g_ao[(size_t)ROWS * ND];                 // attn out (single)
__device__ __half g_wqT[(size_t)QKV_COLS * ND];            // Wqkv^T [6144][2048]
__device__ __half g_woT[(size_t)ND * ND];                  // Wout^T [2048][2048]
// per-head QKV: [B*H][S][HD]; Q split hi/lo, K and V single fp16
__device__ __half g_qhh[(size_t)ROWS * ND];
__device__ __half g_qll[(size_t)ROWS * ND];
__device__ __half g_kk[(size_t)ROWS * ND];
__device__ __half g_vv[(size_t)ROWS * ND];

// ---------------- PTX helpers (baseline features only: sm_80+) ------------
__device__ __forceinline__ uint32_t smem_u32(const void* p) {
    uint32_t a;
    asm("{ .reg .u64 t; cvta.to.shared.u64 t, %1; cvt.u32.u64 %0, t; }"
        : "=r"(a) : "l"(p));
    return a;
}

__device__ __forceinline__ void cpa16(uint32_t s, const void* g) {
    asm volatile("cp.async.cg.shared.global [%0], [%1], 16;" :: "r"(s), "l"(g));
}
#define CP_COMMIT() asm volatile("cp.async.commit_group;" ::: "memory")
#define CP_WAIT(n)  asm volatile("cp.async.wait_group %0;" :: "n"(n) : "memory")

__device__ __forceinline__ void ldsm4(uint32_t* r, uint32_t addr) {
    asm volatile("ldmatrix.sync.aligned.m8n8.x4.shared.b16 {%0,%1,%2,%3}, [%4];"
                 : "=r"(r[0]), "=r"(r[1]), "=r"(r[2]), "=r"(r[3]) : "r"(addr));
}
__device__ __forceinline__ void ldsm4t(uint32_t* r, uint32_t addr) {
    asm volatile("ldmatrix.sync.aligned.m8n8.x4.trans.shared.b16 {%0,%1,%2,%3}, [%4];"
                 : "=r"(r[0]), "=r"(r[1]), "=r"(r[2]), "=r"(r[3]) : "r"(addr));
}

// fp16 mma
__device__ __forceinline__ void mma16816h(float* d, const uint32_t* a,
                                          const uint32_t* b) {
    asm volatile(
        "mma.sync.aligned.m16n8k16.row.col.f32.f16.f16.f32 "
        "{%0,%1,%2,%3}, {%4,%5,%6,%7}, {%8,%9}, {%0,%1,%2,%3};"
        : "+f"(d[0]), "+f"(d[1]), "+f"(d[2]), "+f"(d[3])
        : "r"(a[0]), "r"(a[1]), "r"(a[2]), "r"(a[3]), "r"(b[0]), "r"(b[1]));
}

__device__ __forceinline__ float ex2f(float x) {
    float y;
    asm("ex2.approx.f32 %0, %1;" : "=f"(y) : "f"(x));
    return y;
}

#define PACK2(lo16, hi16) (((uint32_t)(hi16) << 16) | (uint32_t)(lo16))
#define HFU(x) __half_as_ushort(x)

__device__ __forceinline__ uint32_t split_pair_h(float a, float b, uint32_t& lo) {
    __half h0 = __float2half_rn(a), h1 = __float2half_rn(b);
    __half e0 = __float2half_rn(a - __half2float(h0));
    __half e1 = __float2half_rn(b - __half2float(h1));
    lo = PACK2(HFU(e0), HFU(e1));
    return PACK2(HFU(h0), HFU(h1));
}
__device__ __forceinline__ uint32_t pack_h(float a, float b) {
    return PACK2(HFU(__float2half_rn(a)), HFU(__float2half_rn(b)));
}

// ---------------------------------------------------------------------------
// conversion kernels
// ---------------------------------------------------------------------------
__global__ void cvt_h(const float4* __restrict__ in, uint2* __restrict__ hi)
{
    int i = blockIdx.x * blockDim.x + threadIdx.x;
    float4 v = in[i];
    uint2 uh;
    uh.x = pack_h(v.x, v.y);
    uh.y = pack_h(v.z, v.w);
    hi[i] = uh;
}

// W [K][N] fp32  ->  T [N][K] single fp16
__global__ void cvt_T_h(const float* __restrict__ W, __half* __restrict__ Th,
                        int K, int N)
{
    __shared__ float tile[32][33];
    int n0 = blockIdx.x * 32, k0 = blockIdx.y * 32;
    int tx = threadIdx.x, ty = threadIdx.y;  // 32 x 8
    #pragma unroll
    for (int r = 0; r < 4; r++)
        tile[ty + r*8][tx] = W[(size_t)(k0 + ty + r*8) * N + n0 + tx];
    __syncthreads();
    #pragma unroll
    for (int r = 0; r < 4; r++) {
        float v = tile[tx][ty + r*8];
        Th[(size_t)(n0 + ty + r*8) * K + k0 + tx] = __float2half_rn(v);
    }
}

// ---------------------------------------------------------------------------
// fp16 1-term GEMM via mma.sync: C = A @ B^T + bias.
// CTA 128x128, BK=64, 8 warps (4m x 2n), warp tile 32x64, 3-stage cp.async,
// 96KB smem -> 2 CTAs/SM. Rows are 128 B with 8-way swizzle; 4 straight-line
// k16 halves per barrier for a wide scheduling window.
// EPI=0: fp32 C + bias. EPI=1: per-head QKV (Q split hi/lo, K/V single).
// ---------------------------------------------------------------------------
#define STAGES 3
#define STAGE_BYTES 32768      /* A 16K | B 16K */
#define GEMM_SMEM (STAGES * STAGE_BYTES)   /* 96 KB */
#define SWZ8(row, chunk) ((((chunk) ^ ((row) & 7)) << 4))

__device__ __forceinline__ void issue_stage(
    uint32_t sb_stage, const __half* __restrict__ A,
    const __half* __restrict__ B,
    int rowBase, int colBase, int k0, int K, int t)
{
    #pragma unroll
    for (int u = 0; u < 4; u++) {
        int idx = t + 256*u;               // 0..1023
        int row = idx >> 3, chunk = idx & 7;
        uint32_t soff = (uint32_t)(row*128 + SWZ8(row, chunk));
        size_t ge = k0 + chunk*8;
        cpa16(sb_stage +         soff, A + (size_t)(rowBase + row) * K + ge);
        cpa16(sb_stage + 16384 + soff, B + (size_t)(colBase + row) * K + ge);
    }
    CP_COMMIT();
}

template<int EPI>
__global__ __launch_bounds__(256, 2)
void gemm_mma(const __half* __restrict__ A, const __half* __restrict__ B,
              const float* __restrict__ bias, float* __restrict__ C,
              __half* __restrict__ q_h, __half* __restrict__ q_l,
              __half* __restrict__ k_s, __half* __restrict__ v_s,
              int M, int N, int K)
{
    extern __shared__ char sm[];
    const uint32_t sb = smem_u32(sm);

    const int t = threadIdx.x, lane = t & 31, w = t >> 5;
    const int warp_m = w & 3, warp_n = w >> 2;   // 4 x 2
    const int rowBase = blockIdx.y * 128;
    const int colBase = blockIdx.x * 128;
    const int ksteps  = K >> 6;
    const int mat = lane >> 3, r8 = lane & 7;

    float acc[2][8][4];
    #pragma unroll
    for (int i = 0; i < 2; i++)
        #pragma unroll
        for (int j = 0; j < 8; j++)
            #pragma unroll
            for (int q = 0; q < 4; q++) acc[i][j][q] = 0.f;

    issue_stage(sb,               A, B, rowBase, colBase, 0,  K, t);
    issue_stage(sb + STAGE_BYTES, A, B, rowBase, colBase, 64, K, t);

    int rowA[2], rowB[4];
    #pragma unroll
    for (int fm = 0; fm < 2; fm++)
        rowA[fm] = warp_m*32 + fm*16 + (mat & 1)*8 + r8;
    #pragma unroll
    for (int fb = 0; fb < 4; fb++)
        rowB[fb] = warp_n*64 + fb*16 + (mat >> 1)*8 + r8;

    for (int i = 0; i < ksteps; i++) {
        CP_WAIT(1);
        __syncthreads();
        const uint32_t st = sb + (uint32_t)(i % 3) * STAGE_BYTES;

        // refill slot (i+2)%3 == (i-1)%3: its reads completed before the
        // barrier above (all warps finished iter i-1's compute).
        if (i + 2 < ksteps)
            issue_stage(sb + (uint32_t)((i + 2) % 3) * STAGE_BYTES,
                        A, B, rowBase, colBase, (i + 2)*64, K, t);
        else
            CP_COMMIT();   // keep group accounting uniform

        #pragma unroll
        for (int ks = 0; ks < 4; ks++) {
            const int ckA = ks*2 + (mat >> 1);   // 16B chunk index for A
            const int ckB = ks*2 + (mat & 1);    // 16B chunk index for B

            uint32_t rh[4][4];
            #pragma unroll
            for (int fb = 0; fb < 4; fb++) {
                uint32_t off = (uint32_t)(rowB[fb]*128 + SWZ8(rowB[fb], ckB));
                ldsm4(rh[fb], st + 16384 + off);
            }
            uint32_t ahc[2][4];
            #pragma unroll
            for (int fm = 0; fm < 2; fm++) {
                uint32_t off = (uint32_t)(rowA[fm]*128 + SWZ8(rowA[fm], ckA));
                ldsm4(ahc[fm], st + off);
            }

            #pragma unroll
            for (int fm = 0; fm < 2; fm++)
                #pragma unroll
                for (int fb = 0; fb < 4; fb++) {
                    mma16816h(acc[fm][2*fb+0], ahc[fm], rh[fb]);
                    mma16816h(acc[fm][2*fb+1], ahc[fm], rh[fb]+2);
                }
        }
    }

    const int qrow = lane >> 2, qcol = (lane & 3) * 2;
    #pragma unroll
    for (int fn = 0; fn < 8; fn++) {
        const int col = colBase + warp_n*64 + fn*8 + qcol;
        const float b0 = bias[col], b1 = bias[col + 1];
        if (EPI == 0) {
            #pragma unroll
            for (int fm = 0; fm < 2; fm++) {
                const int row0 = rowBase + warp_m*32 + fm*16 + qrow;
                float2 v0 = make_float2(acc[fm][fn][0] + b0, acc[fm][fn][1] + b1);
                float2 v1 = make_float2(acc[fm][fn][2] + b0, acc[fm][fn][3] + b1);
                *(float2*)&C[(size_t)row0 * N + col]       = v0;
                *(float2*)&C[(size_t)(row0 + 8) * N + col] = v1;
            }
        } else {
            const int sel = col >> 11, hh = (col >> 7) & 15, hd = col & 127;
            #pragma unroll
            for (int fm = 0; fm < 2; fm++) {
                const int r0 = rowBase + warp_m*32 + fm*16 + qrow;
                #pragma unroll
                for (int rr = 0; rr < 2; rr++) {
                    const int r = r0 + rr*8;
                    float va = acc[fm][fn][rr*2+0] + b0;
                    float vb = acc[fm][fn][rr*2+1] + b1;
                    size_t o = (((size_t)((r >> 11)*NH + hh) * NS +
                                 (r & 2047)) * NHD + hd);
                    if (sel == 0) {
                        uint32_t lo, hi = split_pair_h(va, vb, lo);
                        *(uint32_t*)&q_h[o] = hi;
                        *(uint32_t*)&q_l[o] = lo;
                    } else {
                        __half* d = (sel == 1) ? k_s : v_s;
                        *(uint32_t*)&d[o] = pack_h(va, vb);
                    }
                }
            }
        }
    }
}

// ---------------------------------------------------------------------------
// Flash attention via fp16 mma. Q 2-term (hi/lo); K, V, P single fp16.
// Static-max softmax; heavy tiles first; register-stage pipelining.
// smem: 3 KV stages of 32KB (K 16K | V 16K) + persistent Q 64KB (hi|lo).
// ---------------------------------------------------------------------------
#define KV_STAGE 32768
#define FLASH_SMEM (3*KV_STAGE + 65536)   /* 163840 */
#define SWZF(row, chunk) (((chunk) ^ ((row) & 7)) << 4)

__device__ __forceinline__ void flash_load_kv(
    uint32_t st, const __half* __restrict__ k_s,
    const __half* __restrict__ v_s, size_t hb, int kt, int t)
{
    #pragma unroll
    for (int u = 0; u < 4; u++) {
        int idx = t + 256*u;                 // 0..1023
        int row = idx >> 4, chunk = idx & 15;
        uint32_t soff = (uint32_t)(row*256 + SWZF(row, chunk));
        size_t g = hb + (size_t)(kt*64 + row)*NHD + chunk*8;
        cpa16(st +         soff, k_s + g);
        cpa16(st + 16384 + soff, v_s + g);
    }
    CP_COMMIT();
}

__global__ __launch_bounds__(256, 1)
void flash_mma(const __half* __restrict__ qh, const __half* __restrict__ ql,
               const __half* __restrict__ k_s, const __half* __restrict__ v_s,
               __half* __restrict__ ao)
{
    extern __shared__ char sm[];
    const uint32_t sb = smem_u32(sm);
    const uint32_t qst = sb + 3*KV_STAGE;    // persistent Q region

    const int qt = (NS/128 - 1) - blockIdx.x;   // heavy tiles first
    const int h = blockIdx.y, b = blockIdx.z;
    const int t = threadIdx.x, lane = t & 31, w = t >> 5;
    const size_t hb = (size_t)(b*NH + h) * NS * NHD;

    const float L2E   = 1.4426950408889634f;
    const float scale = 0.08838834764831845f;          // 1/sqrt(128)
    const float slope = exp2f(-0.5f * (float)(h + 1)); // ALiBi, H=16
    const float c1  = scale * L2E;
    const float sl2 = slope * L2E;
    const float mc8 = -8.0f * L2E;
    const int r8 = lane & 7, m01 = (lane >> 3) & 1, m2 = lane >> 4;
    const int qr = lane >> 2, qc = (lane & 3) * 2;
    const int rg0 = qt*128 + w*16 + qr;                // global q row (c0/c1)

    // stage Q (hi|lo) into the persistent region
    #pragma unroll
    for (int u = 0; u < 8; u++) {
        int idx = t + 256*u;                 // 0..2047
        int row = idx >> 4, chunk = idx & 15;
        uint32_t soff = (uint32_t)(row*256 + SWZF(row, chunk));
        size_t g = hb + (size_t)(qt*128 + row)*NHD + chunk*8;
        cpa16(qst +         soff, qh + g);
        cpa16(qst + 32768 + soff, ql + g);
    }
    CP_COMMIT();                             // group: Q
    flash_load_kv(sb,            k_s, v_s, hb, 0, t);   // group: KV0
    flash_load_kv(sb + KV_STAGE, k_s, v_s, hb, 1, t);   // group: KV1

    CP_WAIT(2);                              // Q complete
    __syncthreads();

    // Q fragments -> registers
    uint32_t fqh[8][4], fql[8][4];
    {
        const int qrow = w*16 + m01*8 + r8;
        #pragma unroll
        for (int kc = 0; kc < 8; kc++) {
            uint32_t qa = qst + (uint32_t)(qrow*256 + SWZF(qrow, kc*2 + m2));
            ldsm4(fqh[kc], qa);
            ldsm4(fql[kc], qa + 32768);
        }
    }

    float l0 = 0.f, l1 = 0.f;
    float acc_o[16][4];
    #pragma unroll
    for (int i = 0; i < 16; i++)
        #pragma unroll
        for (int j = 0; j < 4; j++) acc_o[i][j] = 0.f;

    const int nkt = 2*qt + 2;
    for (int kt = 0; kt < nkt; kt++) {
        CP_WAIT(1);
        __syncthreads();
        const uint32_t st = sb + (uint32_t)(kt % 3)*KV_STAGE;

        // ---- S = Q K^T (2-term), K frags double-buffered over ng ----
        float s_[8][4];
        #pragma unroll
        for (int i = 0; i < 8; i++)
            #pragma unroll
            for (int j = 0; j < 4; j++) s_[i][j] = 0.f;

        #pragma unroll
        for (int kc = 0; kc < 8; kc++) {
            const int kchk = kc*2 + m01;
            uint32_t rh[2][4];
            {
                int krow = m2*8 + r8;                // ng = 0
                ldsm4(rh[0], st + (uint32_t)(krow*256 + SWZF(krow, kchk)));
            }
            if (kc == 0) {
                if (kt + 2 < nkt)
                    flash_load_kv(sb + (uint32_t)((kt + 2) % 3)*KV_STAGE,
                                  k_s, v_s, hb, kt + 2, t);
                else
                    CP_COMMIT();
            }
            #pragma unroll
            for (int ng = 0; ng < 4; ng++) {
                const int cur = ng & 1;
                if (ng < 3) {
                    int krow = (ng+1)*16 + m2*8 + r8;
                    ldsm4(rh[cur^1],
                          st + (uint32_t)(krow*256 + SWZF(krow, kchk)));
                }
                mma16816h(s_[ng*2+0], fqh[kc], rh[cur]);
                mma16816h(s_[ng*2+0], fql[kc], rh[cur]);
                mma16816h(s_[ng*2+1], fqh[kc], rh[cur]+2);
                mma16816h(s_[ng*2+1], fql[kc], rh[cur]+2);
            }
        }

        // ---- static-max softmax ----
        const bool diag = (kt >= 2*qt);
        const float baseA = fmaf((float)(kt*64 + qc - rg0), sl2, mc8);
        const float baseB = baseA - 8.0f*sl2;   // rows rg0+8
        if (diag) {
            #pragma unroll
            for (int nt = 0; nt < 8; nt++) {
                #pragma unroll
                for (int jj = 0; jj < 2; jj++) {
                    const float cf = (float)(nt*8 + jj);
                    float a0 = fmaf(s_[nt][jj],     c1, fmaf(cf, sl2, baseA));
                    float a1 = fmaf(s_[nt][2 + jj], c1, fmaf(cf, sl2, baseB));
                    int col = kt*64 + nt*8 + qc + jj;
                    if (col > rg0)     a0 = -10000.f;
                    if (col > rg0 + 8) a1 = -10000.f;
                    float p0 = ex2f(a0), p1 = ex2f(a1);
                    l0 += p0; l1 += p1;
                    s_[nt][jj] = p0; s_[nt][2 + jj] = p1;
                }
            }
        } else {
            #pragma unroll
            for (int nt = 0; nt < 8; nt++) {
                #pragma unroll
                for (int jj = 0; jj < 2; jj++) {
                    const float cf = (float)(nt*8 + jj);
                    float a0 = fmaf(s_[nt][jj],     c1, fmaf(cf, sl2, baseA));
                    float a1 = fmaf(s_[nt][2 + jj], c1, fmaf(cf, sl2, baseB));
                    float p0 = ex2f(a0), p1 = ex2f(a1);
                    l0 += p0; l1 += p1;
                    s_[nt][jj] = p0; s_[nt][2 + jj] = p1;
                }
            }
        }

        // ---- O += P V (P single fp16), V frags double-buffered over ng ----
        #pragma unroll
        for (int kc = 0; kc < 4; kc++) {
            uint32_t ph[4];
            {
                const float* pa = s_[2*kc];
                const float* pb = s_[2*kc + 1];
                ph[0] = pack_h(pa[0], pa[1]);
                ph[1] = pack_h(pa[2], pa[3]);
                ph[2] = pack_h(pb[0], pb[1]);
                ph[3] = pack_h(pb[2], pb[3]);
            }
            const int vrow = kc*16 + m01*8 + r8;
            const uint32_t vbase = st + 16384 + (uint32_t)(vrow*256);
            uint32_t wh[2][4];
            ldsm4t(wh[0], vbase + (uint32_t)SWZF(vrow, m2));   // ng = 0
            #pragma unroll
            for (int ng = 0; ng < 8; ng++) {
                const int cur = ng & 1;
                if (ng < 7)
                    ldsm4t(wh[cur^1],
                           vbase + (uint32_t)SWZF(vrow, (ng+1)*2 + m2));
                mma16816h(acc_o[ng*2+0], ph, wh[cur]);
                mma16816h(acc_o[ng*2+1], ph, wh[cur]+2);
            }
        }
    }

    // ---- finalize ----
    l0 += __shfl_xor_sync(0xffffffffu, l0, 1);
    l0 += __shfl_xor_sync(0xffffffffu, l0, 2);
    l1 += __shfl_xor_sync(0xffffffffu, l1, 1);
    l1 += __shfl_xor_sync(0xffffffffu, l1, 2);
    const float inv0 = 1.f / l0, inv1 = 1.f / l1;

    const size_t row0 = (size_t)(b*NS) + qt*128 + w*16 + qr;
    #pragma unroll
    for (int nt = 0; nt < 16; nt++) {
        int col = h*NHD + nt*8 + qc;
        *(uint32_t*)&ao[row0 * ND + col] =
            pack_h(acc_o[nt][0]*inv0, acc_o[nt][1]*inv0);
        *(uint32_t*)&ao[(row0 + 8) * ND + col] =
            pack_h(acc_o[nt][2]*inv1, acc_o[nt][3]*inv1);
    }
}

// ---------------------------------------------------------------------------
extern "C" void kernel_launch(void* const* d_in, const int* in_sizes, int n_in,
                              void* d_out, int out_size)
{
    const float* x    = (const float*)d_in[0];
    const float* Wqkv = (const float*)d_in[1];
    const float* bqkv = (const float*)d_in[2];
    const float* Wout = (const float*)d_in[3];
    const float* bout = (const float*)d_in[4];
    float* out = (float*)d_out;

    __half *xh, *ao, *wqT, *woT, *qh, *ql, *ks, *vs;
    cudaGetSymbolAddress((void**)&xh,   g_xh);
    cudaGetSymbolAddress((void**)&ao,   g_ao);
    cudaGetSymbolAddress((void**)&wqT,  g_wqT);
    cudaGetSymbolAddress((void**)&woT,  g_woT);
    cudaGetSymbolAddress((void**)&qh,   g_qhh);
    cudaGetSymbolAddress((void**)&ql,   g_qll);
    cudaGetSymbolAddress((void**)&ks,   g_kk);
    cudaGetSymbolAddress((void**)&vs,   g_vv);

    cudaFuncSetAttribute((const void*)gemm_mma<0>,
                         cudaFuncAttributeMaxDynamicSharedMemorySize, GEMM_SMEM);
    cudaFuncSetAttribute((const void*)gemm_mma<1>,
                         cudaFuncAttributeMaxDynamicSharedMemorySize, GEMM_SMEM);
    cudaFuncSetAttribute(flash_mma,
                         cudaFuncAttributeMaxDynamicSharedMemorySize, FLASH_SMEM);

    // operand conversions
    cvt_h<<<(ROWS*(size_t)ND/4 + 255)/256, 256>>>((const float4*)x, (uint2*)xh);
    cvt_T_h<<<dim3(QKV_COLS/32, ND/32), dim3(32, 8)>>>(Wqkv, wqT, ND, QKV_COLS);
    cvt_T_h<<<dim3(ND/32, ND/32), dim3(32, 8)>>>(Wout, woT, ND, ND);

    // qkv = x @ Wqkv + b_qkv, written as per-head q(hi/lo), k, v
    gemm_mma<1><<<dim3(QKV_COLS/128, ROWS/128), 256, GEMM_SMEM>>>(
        xh, wqT, bqkv, nullptr,
        qh, ql, ks, vs, ROWS, QKV_COLS, ND);

    // attention -> writes proj A-operand (single fp16) directly
    flash_mma<<<dim3(NS/128, NH, NB), 256, FLASH_SMEM>>>(
        qh, ql, ks, vs, ao);

    // out = attn @ Wout + b_out
    gemm_mma<0><<<dim3(ND/128, ROWS/128), 256, GEMM_SMEM>>>(
        ao, woT, bout, out,
        nullptr, nullptr, nullptr, nullptr, ROWS, ND, ND);
}